// round 1
// baseline (speedup 1.0000x reference)
#include <cuda_runtime.h>

// ---------------------------------------------------------------------------
// NEZHA-style MHA, fp32 baseline with packed f32x2 FMA (sm_103a).
// B=4, S=1024, H=12, DK=DV=64, DM=768.
// ---------------------------------------------------------------------------

#define S 1024
#define Hh 12
#define BH 48           // B*H
#define DKc 64
#define DMc 768
#define NEGV (-1e12f)

typedef unsigned long long ull;

// Scratch (static device memory — allowed; no runtime allocation).
__device__ float g_qw[(size_t)BH * S * DKc];        // [bh][s][d]   12.6 MB
__device__ float g_kw[(size_t)BH * S * DKc];
__device__ float g_vw[(size_t)BH * S * DKc];
__device__ float g_attn[(size_t)4 * S * DMc];       // [b][s][h*64+d] 12.6 MB
__device__ float g_scores[(size_t)BH * S * S];      // [bh][j][k]   201 MB

// ---- packed fp32x2 helpers -------------------------------------------------
__device__ __forceinline__ void fma2(ull &acc, ull a, ull b) {
    asm("fma.rn.f32x2 %0, %1, %2, %0;" : "+l"(acc) : "l"(a), "l"(b));
}
__device__ __forceinline__ ull dup2(float x) {
    ull r;
    unsigned xi = __float_as_uint(x);
    asm("mov.b64 %0, {%1, %1};" : "=l"(r) : "r"(xi));
    return r;
}
union F4U { float4 f; ull u[2]; };
union UF2 { ull u; float2 f; };

// ---------------------------------------------------------------------------
// Generic 4096x768x768 GEMM + bias.  xmode: 0 = Xext, 1 = g_attn.
// ymode: 0 = Yext row-major [4096,768], 1/2/3 = scatter into g_qw/g_kw/g_vw
// with [bh][s][d] layout.
// Tiles: 128x128, BK=8, 256 threads, 8x8 micro-tile, f32x2 FMAs.
// ---------------------------------------------------------------------------
__global__ __launch_bounds__(256) void gemm768_kernel(
    const float* __restrict__ Xext, const float* __restrict__ W,
    const float* __restrict__ bias, float* __restrict__ Yext,
    int xmode, int ymode)
{
    __shared__ __align__(16) float As[8][128];
    __shared__ __align__(16) float Bs[8][128];
    const float* X = (xmode == 1) ? g_attn : Xext;

    const int bm = blockIdx.y * 128;
    const int bn = blockIdx.x * 128;
    const int tid = threadIdx.x;
    const int tx = tid & 15, ty = tid >> 4;
    const int ar = tid >> 1, ac = (tid & 1) * 4;
    const int br = tid >> 5, bc = (tid & 31) * 4;

    ull acc[8][4];
#pragma unroll
    for (int i = 0; i < 8; i++)
#pragma unroll
        for (int j = 0; j < 4; j++) acc[i][j] = 0ull;

    for (int k0 = 0; k0 < 768; k0 += 8) {
        float4 av = *(const float4*)&X[(size_t)(bm + ar) * 768 + k0 + ac];
        float4 bv = *(const float4*)&W[(size_t)(k0 + br) * 768 + bn + bc];
        __syncthreads();
        As[ac + 0][ar] = av.x; As[ac + 1][ar] = av.y;
        As[ac + 2][ar] = av.z; As[ac + 3][ar] = av.w;
        *(float4*)&Bs[br][bc] = bv;
        __syncthreads();
#pragma unroll
        for (int k = 0; k < 8; k++) {
            float4 a0 = *(const float4*)&As[k][ty * 8];
            float4 a1 = *(const float4*)&As[k][ty * 8 + 4];
            F4U b0, b1;
            b0.f = *(const float4*)&Bs[k][tx * 8];
            b1.f = *(const float4*)&Bs[k][tx * 8 + 4];
            float a[8] = {a0.x, a0.y, a0.z, a0.w, a1.x, a1.y, a1.z, a1.w};
#pragma unroll
            for (int i = 0; i < 8; i++) {
                ull ad = dup2(a[i]);
                fma2(acc[i][0], ad, b0.u[0]);
                fma2(acc[i][1], ad, b0.u[1]);
                fma2(acc[i][2], ad, b1.u[0]);
                fma2(acc[i][3], ad, b1.u[1]);
            }
        }
    }

    float* Yq = (ymode == 1) ? g_qw : (ymode == 2) ? g_kw : (ymode == 3) ? g_vw : Yext;
#pragma unroll
    for (int i = 0; i < 8; i++) {
        int row = bm + ty * 8 + i;
#pragma unroll
        for (int jp = 0; jp < 4; jp++) {
            UF2 v; v.u = acc[i][jp];
            int col = bn + tx * 8 + jp * 2;
            v.f.x += bias[col];
            v.f.y += bias[col + 1];
            if (ymode != 0) {
                int b = row >> 10, s = row & 1023;
                int h = col >> 6,  d = col & 63;
                float* p = &Yq[(((size_t)(b * Hh + h)) * S + s) * DKc + d];
                p[0] = v.f.x; p[1] = v.f.y;
            } else {
                Yq[(size_t)row * 768 + col]     = v.f.x;
                Yq[(size_t)row * 768 + col + 1] = v.f.y;
            }
        }
    }
}

// ---------------------------------------------------------------------------
// scores[bh][j][k] = sum_d qw[bh][j][d] * kw[bh][k][d]   (NT GEMM, K=64)
// grid (k_tiles=8, j_tiles=8, bh=48), 256 threads, 128x128 tile.
// ---------------------------------------------------------------------------
__global__ __launch_bounds__(256) void qk_kernel() {
    const int bh = blockIdx.z;
    const int bj = blockIdx.y * 128, bk = blockIdx.x * 128;
    const float* Q  = g_qw + (size_t)bh * S * DKc;
    const float* Kt = g_kw + (size_t)bh * S * DKc;
    __shared__ __align__(16) float As[8][128];
    __shared__ __align__(16) float Bs[8][128];
    const int tid = threadIdx.x;
    const int tx = tid & 15, ty = tid >> 4;
    const int ar = tid >> 1, ac = (tid & 1) * 4;

    ull acc[8][4];
#pragma unroll
    for (int i = 0; i < 8; i++)
#pragma unroll
        for (int j = 0; j < 4; j++) acc[i][j] = 0ull;

    for (int d0 = 0; d0 < 64; d0 += 8) {
        float4 av = *(const float4*)&Q [(size_t)(bj + ar) * 64 + d0 + ac];
        float4 bv = *(const float4*)&Kt[(size_t)(bk + ar) * 64 + d0 + ac];
        __syncthreads();
        As[ac + 0][ar] = av.x; As[ac + 1][ar] = av.y;
        As[ac + 2][ar] = av.z; As[ac + 3][ar] = av.w;
        Bs[ac + 0][ar] = bv.x; Bs[ac + 1][ar] = bv.y;
        Bs[ac + 2][ar] = bv.z; Bs[ac + 3][ar] = bv.w;
        __syncthreads();
#pragma unroll
        for (int k = 0; k < 8; k++) {
            float4 a0 = *(const float4*)&As[k][ty * 8];
            float4 a1 = *(const float4*)&As[k][ty * 8 + 4];
            F4U b0, b1;
            b0.f = *(const float4*)&Bs[k][tx * 8];
            b1.f = *(const float4*)&Bs[k][tx * 8 + 4];
            float a[8] = {a0.x, a0.y, a0.z, a0.w, a1.x, a1.y, a1.z, a1.w};
#pragma unroll
            for (int i = 0; i < 8; i++) {
                ull ad = dup2(a[i]);
                fma2(acc[i][0], ad, b0.u[0]);
                fma2(acc[i][1], ad, b0.u[1]);
                fma2(acc[i][2], ad, b1.u[0]);
                fma2(acc[i][3], ad, b1.u[1]);
            }
        }
    }
#pragma unroll
    for (int i = 0; i < 8; i++) {
        int row = bj + ty * 8 + i;
#pragma unroll
        for (int jp = 0; jp < 4; jp++) {
            UF2 v; v.u = acc[i][jp];
            int col = bk + tx * 8 + jp * 2;
            size_t idx = ((size_t)bh << 20) + ((size_t)row << 10) + col;
            g_scores[idx]     = v.f.x;
            g_scores[idx + 1] = v.f.y;
        }
    }
}

// ---------------------------------------------------------------------------
// scores[bh][j][k] += sum_d qw[bh][j][d] * pb[j][k][d]
// One block per (k_tile=128, j). pb tile is loaded ONCE and shared across all
// 48 (b,h). 192 threads: micro 8(bh) x 4(k).
// ---------------------------------------------------------------------------
__global__ __launch_bounds__(192) void pbq_kernel(const float* __restrict__ pb) {
    const int j  = blockIdx.y;
    const int k0 = blockIdx.x * 128;
    __shared__ __align__(16) float Qs[64][48];    // [d][bh]
    __shared__ __align__(16) float Ps[64][128];   // [d][k]
    const int tid = threadIdx.x;

    for (int i = tid; i < BH * 64; i += 192) {
        int bh = i >> 6, d = i & 63;
        Qs[d][bh] = g_qw[((size_t)bh * S + j) * 64 + d];
    }
    for (int i = tid; i < 2048; i += 192) {
        int kk = i >> 4, dq = (i & 15) * 4;
        float4 v = *(const float4*)&pb[((size_t)j * 1024 + k0 + kk) * 64 + dq];
        Ps[dq + 0][kk] = v.x; Ps[dq + 1][kk] = v.y;
        Ps[dq + 2][kk] = v.z; Ps[dq + 3][kk] = v.w;
    }
    __syncthreads();

    const int ty = tid >> 5, tx = tid & 31;   // rows ty*8..+7, cols tx*4..+3
    ull acc[8][2] = {};
#pragma unroll 8
    for (int d = 0; d < 64; d++) {
        float4 a0 = *(const float4*)&Qs[d][ty * 8];
        float4 a1 = *(const float4*)&Qs[d][ty * 8 + 4];
        F4U b; b.f = *(const float4*)&Ps[d][tx * 4];
        float a[8] = {a0.x, a0.y, a0.z, a0.w, a1.x, a1.y, a1.z, a1.w};
#pragma unroll
        for (int i = 0; i < 8; i++) {
            ull ad = dup2(a[i]);
            fma2(acc[i][0], ad, b.u[0]);
            fma2(acc[i][1], ad, b.u[1]);
        }
    }
#pragma unroll
    for (int i = 0; i < 8; i++) {
        int bh = ty * 8 + i;
        size_t base = ((size_t)bh << 20) + ((size_t)j << 10) + k0 + tx * 4;
        UF2 v0, v1; v0.u = acc[i][0]; v1.u = acc[i][1];
        g_scores[base + 0] += v0.f.x;
        g_scores[base + 1] += v0.f.y;
        g_scores[base + 2] += v1.f.x;
        g_scores[base + 3] += v1.f.y;
    }
}

// ---------------------------------------------------------------------------
// In-place row softmax with scale, attention_mask, and v_mask.
// One block per (j, bh) row of 1024.
// ---------------------------------------------------------------------------
__global__ __launch_bounds__(256) void softmax_kernel(
    const float* __restrict__ amask, const int* __restrict__ vmask)
{
    const int j = blockIdx.x, bh = blockIdx.y, b = bh / Hh;
    const size_t base = ((size_t)bh << 20) + ((size_t)j << 10);
    const int tid = threadIdx.x;
    float x[4];
#pragma unroll
    for (int i = 0; i < 4; i++) {
        int k = tid + i * 256;
        float vv = g_scores[base + k] * 0.125f + amask[j * 1024 + k];
        x[i] = vmask[b * 1024 + k] ? vv : NEGV;
    }
    float m = fmaxf(fmaxf(x[0], x[1]), fmaxf(x[2], x[3]));
#pragma unroll
    for (int o = 16; o > 0; o >>= 1) m = fmaxf(m, __shfl_xor_sync(0xffffffffu, m, o));
    __shared__ float redm[8], reds[8];
    const int lane = tid & 31, w = tid >> 5;
    if (lane == 0) redm[w] = m;
    __syncthreads();
    m = redm[0];
#pragma unroll
    for (int i = 1; i < 8; i++) m = fmaxf(m, redm[i]);
    float s = 0.f;
#pragma unroll
    for (int i = 0; i < 4; i++) { x[i] = __expf(x[i] - m); s += x[i]; }
#pragma unroll
    for (int o = 16; o > 0; o >>= 1) s += __shfl_xor_sync(0xffffffffu, s, o);
    if (lane == 0) reds[w] = s;
    __syncthreads();
    s = reds[0];
#pragma unroll
    for (int i = 1; i < 8; i++) s += reds[i];
    float inv = 1.0f / s;
#pragma unroll
    for (int i = 0; i < 4; i++) g_scores[base + tid + i * 256] = x[i] * inv;
}

// ---------------------------------------------------------------------------
// attn[b][j][h][:] = sum_k A[bh][j][k] * vw[bh][k][:]
// grid (j_tiles=8, bh=48), 256 threads, tile 128(j) x 64(d), BK=16.
// ---------------------------------------------------------------------------
__global__ __launch_bounds__(256) void av_kernel() {
    const int bh = blockIdx.y;
    const int bj = blockIdx.x * 128;
    const float* A = g_scores + ((size_t)bh << 20);
    const float* V = g_vw + (size_t)bh * S * 64;
    __shared__ __align__(16) float As[16][128];
    __shared__ __align__(16) float Vs[16][64];
    const int tid = threadIdx.x;
    const int tx = tid & 15, ty = tid >> 4;       // cols tx*4, rows ty*8
    const int r1 = tid >> 2, c1 = (tid & 3) * 4;
    const int vr = tid >> 4, vc = (tid & 15) * 4;

    ull acc[8][2] = {};
    for (int k0 = 0; k0 < 1024; k0 += 16) {
        float4 av0 = *(const float4*)&A[(size_t)(bj + r1)      * 1024 + k0 + c1];
        float4 av1 = *(const float4*)&A[(size_t)(bj + r1 + 64) * 1024 + k0 + c1];
        float4 vv  = *(const float4*)&V[(size_t)(k0 + vr) * 64 + vc];
        __syncthreads();
        As[c1 + 0][r1] = av0.x; As[c1 + 1][r1] = av0.y;
        As[c1 + 2][r1] = av0.z; As[c1 + 3][r1] = av0.w;
        As[c1 + 0][r1 + 64] = av1.x; As[c1 + 1][r1 + 64] = av1.y;
        As[c1 + 2][r1 + 64] = av1.z; As[c1 + 3][r1 + 64] = av1.w;
        *(float4*)&Vs[vr][vc] = vv;
        __syncthreads();
#pragma unroll
        for (int k = 0; k < 16; k++) {
            float4 a0 = *(const float4*)&As[k][ty * 8];
            float4 a1 = *(const float4*)&As[k][ty * 8 + 4];
            F4U b; b.f = *(const float4*)&Vs[k][tx * 4];
            float a[8] = {a0.x, a0.y, a0.z, a0.w, a1.x, a1.y, a1.z, a1.w};
#pragma unroll
            for (int i = 0; i < 8; i++) {
                ull ad = dup2(a[i]);
                fma2(acc[i][0], ad, b.u[0]);
                fma2(acc[i][1], ad, b.u[1]);
            }
        }
    }
    const int b = bh / Hh, h = bh % Hh;
#pragma unroll
    for (int i = 0; i < 8; i++) {
        int jrow = bj + ty * 8 + i;
        size_t idx = (((size_t)b * S + jrow) * Hh + h) * 64 + tx * 4;
        UF2 v0, v1; v0.u = acc[i][0]; v1.u = acc[i][1];
        g_attn[idx + 0] = v0.f.x;
        g_attn[idx + 1] = v0.f.y;
        g_attn[idx + 2] = v1.f.x;
        g_attn[idx + 3] = v1.f.y;
    }
}

// ---------------------------------------------------------------------------
// attn[b][j][h][d] += sum_k A[bh][j][k] * pb[j][k][d]
// One block per j; pb[j] chunk shared across all 48 (b,h). 192 threads,
// micro 8(bh) x 2(d), K chunked by 32.
// ---------------------------------------------------------------------------
__global__ __launch_bounds__(192) void apb_kernel(const float* __restrict__ pb) {
    const int j = blockIdx.x;
    __shared__ __align__(16) float As[32][48];    // [k][bh]
    __shared__ __align__(16) float Ps[32][64];    // [k][d]
    const int tid = threadIdx.x;
    const int ty = tid >> 5, tx = tid & 31;       // rows ty*8..+7, cols tx*2..+1

    ull acc[8] = {};
    for (int k0 = 0; k0 < 1024; k0 += 32) {
        __syncthreads();
        for (int i = tid; i < 48 * 32; i += 192) {
            int bh = i >> 5, kk = i & 31;
            As[kk][bh] = g_scores[((size_t)bh << 20) + ((size_t)j << 10) + k0 + kk];
        }
        for (int i = tid; i < 512; i += 192) {
            int kk = i >> 4, dq = (i & 15) * 4;
            *(float4*)&Ps[kk][dq] =
                *(const float4*)&pb[((size_t)j * 1024 + k0 + kk) * 64 + dq];
        }
        __syncthreads();
#pragma unroll 8
        for (int kk = 0; kk < 32; kk++) {
            float4 a0 = *(const float4*)&As[kk][ty * 8];
            float4 a1 = *(const float4*)&As[kk][ty * 8 + 4];
            UF2 bb; bb.f = *(const float2*)&Ps[kk][tx * 2];
            float a[8] = {a0.x, a0.y, a0.z, a0.w, a1.x, a1.y, a1.z, a1.w};
#pragma unroll
            for (int i = 0; i < 8; i++) fma2(acc[i], dup2(a[i]), bb.u);
        }
    }
#pragma unroll
    for (int i = 0; i < 8; i++) {
        int bh = ty * 8 + i;
        int b = bh / Hh, h = bh % Hh;
        size_t idx = (((size_t)b * S + j) * Hh + h) * 64 + tx * 2;
        UF2 v; v.u = acc[i];
        g_attn[idx + 0] += v.f.x;
        g_attn[idx + 1] += v.f.y;
    }
}

// ---------------------------------------------------------------------------
extern "C" void kernel_launch(void* const* d_in, const int* in_sizes, int n_in,
                              void* d_out, int out_size) {
    const float* q     = (const float*)d_in[0];
    const float* k     = (const float*)d_in[1];
    const float* v     = (const float*)d_in[2];
    const float* amask = (const float*)d_in[3];
    const float* pb    = (const float*)d_in[4];
    const int*   vmask = (const int*)  d_in[5];
    const float* Wq    = (const float*)d_in[6];
    const float* bq    = (const float*)d_in[7];
    const float* Wk    = (const float*)d_in[8];
    const float* bk    = (const float*)d_in[9];
    const float* Wv    = (const float*)d_in[10];
    const float* bv    = (const float*)d_in[11];
    const float* Wo    = (const float*)d_in[12];
    const float* bo    = (const float*)d_in[13];
    float* out = (float*)d_out;

    dim3 gproj(6, 32);
    gemm768_kernel<<<gproj, 256>>>(q, Wq, bq, nullptr, 0, 1);
    gemm768_kernel<<<gproj, 256>>>(k, Wk, bk, nullptr, 0, 2);
    gemm768_kernel<<<gproj, 256>>>(v, Wv, bv, nullptr, 0, 3);
    qk_kernel<<<dim3(8, 8, 48), 256>>>();
    pbq_kernel<<<dim3(8, 1024), 192>>>(pb);
    softmax_kernel<<<dim3(1024, 48), 256>>>(amask, vmask);
    av_kernel<<<dim3(8, 48), 256>>>();
    apb_kernel<<<1024, 192>>>(pb);
    gemm768_kernel<<<gproj, 256>>>(nullptr, Wo, bo, out, 1, 0);
}

// round 3
// speedup vs baseline: 1.4805x; 1.4805x over previous
#include <cuda_runtime.h>
#include <cuda_bf16.h>
#include <cstdint>

// ---------------------------------------------------------------------------
// NEZHA-style MHA. HMMA (mma.sync bf16, hi/lo 3-product) for 4 dense GEMMs +
// QK^T; fp32 f32x2 for pb-einsums / softmax / AV.
// B=4, S=1024, H=12, DK=DV=64, DM=768.  Target compiles as plain sm_103
// (no tcgen05 available in this harness), so tensor work goes via mma.sync.
// ---------------------------------------------------------------------------

#define S 1024
#define Hh 12
#define BH 48
#define NEGV (-1e12f)

typedef unsigned long long ull;

// ---------------- scratch (static device memory) ----------------------------
__device__ float g_qw  [(size_t)BH * S * 64];
__device__ float g_vw  [(size_t)BH * S * 64];
__device__ float g_attn[(size_t)4 * S * 768];
__device__ float g_scores[(size_t)BH * S * S];     // 201 MB

__device__ __align__(16) __nv_bfloat16 g_xhi[(size_t)3 * 4096 * 768];
__device__ __align__(16) __nv_bfloat16 g_xlo[(size_t)3 * 4096 * 768];
__device__ __align__(16) __nv_bfloat16 g_wthi[(size_t)4 * 768 * 768];
__device__ __align__(16) __nv_bfloat16 g_wtlo[(size_t)4 * 768 * 768];
__device__ __align__(16) __nv_bfloat16 g_qhi[(size_t)BH * S * 64];
__device__ __align__(16) __nv_bfloat16 g_qlo[(size_t)BH * S * 64];
__device__ __align__(16) __nv_bfloat16 g_khi[(size_t)BH * S * 64];
__device__ __align__(16) __nv_bfloat16 g_klo[(size_t)BH * S * 64];

// ---------------- helpers ----------------------------------------------------
__device__ __forceinline__ uint32_t smem_to_u32(const void* p) {
    uint32_t a;
    asm("{ .reg .u64 t; cvta.to.shared.u64 t, %1; cvt.u32.u64 %0, t; }"
        : "=r"(a) : "l"(p));
    return a;
}
#define SWZ(o) ((uint32_t)(o) ^ ((((uint32_t)(o)) >> 3) & 0x70))

__device__ __forceinline__ void ldmx4(uint32_t* r, uint32_t a) {
    asm volatile("ldmatrix.sync.aligned.m8n8.x4.shared.b16 {%0,%1,%2,%3}, [%4];"
                 : "=r"(r[0]), "=r"(r[1]), "=r"(r[2]), "=r"(r[3]) : "r"(a));
}
__device__ __forceinline__ void mma16816(float* c, const uint32_t* a,
                                         const uint32_t* b) {
    asm volatile(
        "mma.sync.aligned.m16n8k16.row.col.f32.bf16.bf16.f32 "
        "{%0,%1,%2,%3},{%4,%5,%6,%7},{%8,%9},{%0,%1,%2,%3};"
        : "+f"(c[0]), "+f"(c[1]), "+f"(c[2]), "+f"(c[3])
        : "r"(a[0]), "r"(a[1]), "r"(a[2]), "r"(a[3]), "r"(b[0]), "r"(b[1]));
}

__device__ __forceinline__ void fma2(ull &acc, ull a, ull b) {
    asm("fma.rn.f32x2 %0, %1, %2, %0;" : "+l"(acc) : "l"(a), "l"(b));
}
__device__ __forceinline__ ull dup2(float x) {
    ull r; unsigned xi = __float_as_uint(x);
    asm("mov.b64 %0, {%1, %1};" : "=l"(r) : "r"(xi));
    return r;
}
union F4U { float4 f; ull u[2]; };
union UF2 { ull u; float2 f; };

// ---------------- conversion kernels ----------------------------------------
__global__ void conv_split_kernel(const float* __restrict__ src, int slot, int n4) {
    int i = blockIdx.x * blockDim.x + threadIdx.x;
    if (i >= n4) return;
    const float* s = src ? src : g_attn;
    float4 v = ((const float4*)s)[i];
    __nv_bfloat16* hi = g_xhi + (size_t)slot * 4096 * 768;
    __nv_bfloat16* lo = g_xlo + (size_t)slot * 4096 * 768;
    float vv[4] = {v.x, v.y, v.z, v.w};
#pragma unroll
    for (int c = 0; c < 4; c++) {
        __nv_bfloat16 h = __float2bfloat16(vv[c]);
        hi[(size_t)i * 4 + c] = h;
        lo[(size_t)i * 4 + c] = __float2bfloat16(vv[c] - __bfloat162float(h));
    }
}

__global__ void transpose_conv_kernel(const float* __restrict__ W, int slot) {
    __shared__ float t[32][33];
    int tx = threadIdx.x, ty = threadIdx.y;
    int k = blockIdx.y * 32 + ty, n = blockIdx.x * 32 + tx;
    t[ty][tx] = W[(size_t)k * 768 + n];
    __syncthreads();
    int n2 = blockIdx.x * 32 + ty, k2 = blockIdx.y * 32 + tx;
    float v = t[tx][ty];
    __nv_bfloat16 h = __float2bfloat16(v);
    size_t off = (size_t)slot * 768 * 768 + (size_t)n2 * 768 + k2;
    g_wthi[off] = h;
    g_wtlo[off] = __float2bfloat16(v - __bfloat162float(h));
}

// ---------------- HMMA dense GEMM: [4096x768] @ WT^T -> [4096x768] ----------
// mode 0: QKV (blockIdx.z selects x/W slot + epilogue), mode 1: out projection.
// Tiles 128x128, BK=64, 8 warps (4M x 2N), hi/lo 3-product bf16.
__global__ __launch_bounds__(256) void gemm_mma_kernel(
    const float* __restrict__ b0, const float* __restrict__ b1,
    const float* __restrict__ b2, float* __restrict__ yout, int mode)
{
    extern __shared__ __align__(128) char smem[];
    const uint32_t AH = 0, AL = 16384, BHo = 32768, BL = 49152;
    const uint32_t sbase = smem_to_u32(smem);
    const int tid = threadIdx.x, wid = tid >> 5, lane = tid & 31;
    const int z = blockIdx.z;
    const int bm = blockIdx.y * 128, bn = blockIdx.x * 128;
    const int xsel = (mode == 0) ? z : 0;
    const int wsel = (mode == 0) ? z : 3;
    const __nv_bfloat16* xh = g_xhi + (size_t)xsel * 4096 * 768;
    const __nv_bfloat16* xl = g_xlo + (size_t)xsel * 4096 * 768;
    const __nv_bfloat16* wh = g_wthi + (size_t)wsel * 768 * 768;
    const __nv_bfloat16* wl = g_wtlo + (size_t)wsel * 768 * 768;
    const float* bias = (mode == 1) ? b0 : (z == 0 ? b0 : (z == 1 ? b1 : b2));

    const int wm = (wid >> 1) * 32, wn = (wid & 1) * 64;
    float acc[2][8][4];
#pragma unroll
    for (int a = 0; a < 2; a++)
#pragma unroll
        for (int b = 0; b < 8; b++)
#pragma unroll
            for (int c = 0; c < 4; c++) acc[a][b][c] = 0.f;

    for (int st = 0; st < 12; st++) {
        const int k0 = st * 64;
        __syncthreads();
#pragma unroll
        for (int i = 0; i < 4; i++) {
            int idx = tid + i * 256;
            int row = idx >> 3, q = idx & 7;
            uint32_t dst = SWZ(row * 128 + q * 16);
            size_t sa = (size_t)(bm + row) * 768 + k0 + q * 8;
            size_t sb = (size_t)(bn + row) * 768 + k0 + q * 8;
            *(uint4*)(smem + AH + dst)  = *(const uint4*)(xh + sa);
            *(uint4*)(smem + AL + dst)  = *(const uint4*)(xl + sa);
            *(uint4*)(smem + BHo + dst) = *(const uint4*)(wh + sb);
            *(uint4*)(smem + BL + dst)  = *(const uint4*)(wl + sb);
        }
        __syncthreads();
#pragma unroll
        for (int kk = 0; kk < 4; kk++) {
            uint32_t ah[2][4], al[2][4];
            uint32_t aoff = SWZ((wm + (lane & 15)) * 128 + (kk * 2 + (lane >> 4)) * 16);
            ldmx4(ah[0], sbase + AH + aoff);
            ldmx4(ah[1], sbase + AH + aoff + 2048);
            ldmx4(al[0], sbase + AL + aoff);
            ldmx4(al[1], sbase + AL + aoff + 2048);
            uint32_t boff = SWZ((wn + (lane >> 4) * 8 + (lane & 7)) * 128 +
                                (kk * 2 + ((lane >> 3) & 1)) * 16);
#pragma unroll
            for (int ntp = 0; ntp < 4; ntp++) {
                uint32_t bh4[4], bl4[4];
                ldmx4(bh4, sbase + BHo + boff + ntp * 2048);
                ldmx4(bl4, sbase + BL + boff + ntp * 2048);
#pragma unroll
                for (int mt = 0; mt < 2; mt++) {
                    mma16816(acc[mt][ntp * 2 + 0], ah[mt], bh4);
                    mma16816(acc[mt][ntp * 2 + 0], ah[mt], bl4);
                    mma16816(acc[mt][ntp * 2 + 0], al[mt], bh4);
                    mma16816(acc[mt][ntp * 2 + 1], ah[mt], bh4 + 2);
                    mma16816(acc[mt][ntp * 2 + 1], ah[mt], bl4 + 2);
                    mma16816(acc[mt][ntp * 2 + 1], al[mt], bh4 + 2);
                }
            }
        }
    }

    // epilogue
#pragma unroll
    for (int mt = 0; mt < 2; mt++) {
#pragma unroll
        for (int nt = 0; nt < 8; nt++) {
            int col = bn + wn + nt * 8 + (lane & 3) * 2;
            float bx = bias[col], by = bias[col + 1];
#pragma unroll
            for (int half = 0; half < 2; half++) {
                int row = bm + wm + mt * 16 + (lane >> 2) + half * 8;
                float v0 = acc[mt][nt][half * 2 + 0] + bx;
                float v1 = acc[mt][nt][half * 2 + 1] + by;
                if (mode == 1) {
                    yout[(size_t)row * 768 + col]     = v0;
                    yout[(size_t)row * 768 + col + 1] = v1;
                } else {
                    int b = row >> 10, s = row & 1023;
                    int h = col >> 6, d = col & 63;
                    size_t base = ((size_t)(b * Hh + h) * S + s) * 64 + d;
                    if (z == 0) {
                        g_qw[base] = v0; g_qw[base + 1] = v1;
                        __nv_bfloat16 h0 = __float2bfloat16(v0);
                        __nv_bfloat16 h1 = __float2bfloat16(v1);
                        g_qhi[base] = h0; g_qhi[base + 1] = h1;
                        g_qlo[base]     = __float2bfloat16(v0 - __bfloat162float(h0));
                        g_qlo[base + 1] = __float2bfloat16(v1 - __bfloat162float(h1));
                    } else if (z == 1) {
                        __nv_bfloat16 h0 = __float2bfloat16(v0);
                        __nv_bfloat16 h1 = __float2bfloat16(v1);
                        g_khi[base] = h0; g_khi[base + 1] = h1;
                        g_klo[base]     = __float2bfloat16(v0 - __bfloat162float(h0));
                        g_klo[base + 1] = __float2bfloat16(v1 - __bfloat162float(h1));
                    } else {
                        g_vw[base] = v0; g_vw[base + 1] = v1;
                    }
                }
            }
        }
    }
}

// ---------------- HMMA QK^T: scores[bh][j][k] = qw.kw (K=64) -----------------
__global__ __launch_bounds__(256) void qk_mma_kernel() {
    extern __shared__ __align__(128) char smem[];
    const uint32_t AH = 0, AL = 16384, BHo = 32768, BL = 49152;
    const uint32_t sbase = smem_to_u32(smem);
    const int tid = threadIdx.x, wid = tid >> 5, lane = tid & 31;
    const int bh = blockIdx.z;
    const int bj = blockIdx.y * 128, bk = blockIdx.x * 128;
    const int wm = (wid >> 1) * 32, wn = (wid & 1) * 64;

    const size_t qb = ((size_t)bh * S + bj) * 64;
    const size_t kb = ((size_t)bh * S + bk) * 64;
#pragma unroll
    for (int i = 0; i < 4; i++) {
        int idx = tid + i * 256;
        int row = idx >> 3, q = idx & 7;
        uint32_t dst = SWZ(row * 128 + q * 16);
        size_t sa = qb + (size_t)row * 64 + q * 8;
        size_t sb = kb + (size_t)row * 64 + q * 8;
        *(uint4*)(smem + AH + dst)  = *(const uint4*)(g_qhi + sa);
        *(uint4*)(smem + AL + dst)  = *(const uint4*)(g_qlo + sa);
        *(uint4*)(smem + BHo + dst) = *(const uint4*)(g_khi + sb);
        *(uint4*)(smem + BL + dst)  = *(const uint4*)(g_klo + sb);
    }
    __syncthreads();

    float acc[2][8][4];
#pragma unroll
    for (int a = 0; a < 2; a++)
#pragma unroll
        for (int b = 0; b < 8; b++)
#pragma unroll
            for (int c = 0; c < 4; c++) acc[a][b][c] = 0.f;

#pragma unroll
    for (int kk = 0; kk < 4; kk++) {
        uint32_t ah[2][4], al[2][4];
        uint32_t aoff = SWZ((wm + (lane & 15)) * 128 + (kk * 2 + (lane >> 4)) * 16);
        ldmx4(ah[0], sbase + AH + aoff);
        ldmx4(ah[1], sbase + AH + aoff + 2048);
        ldmx4(al[0], sbase + AL + aoff);
        ldmx4(al[1], sbase + AL + aoff + 2048);
        uint32_t boff = SWZ((wn + (lane >> 4) * 8 + (lane & 7)) * 128 +
                            (kk * 2 + ((lane >> 3) & 1)) * 16);
#pragma unroll
        for (int ntp = 0; ntp < 4; ntp++) {
            uint32_t bh4[4], bl4[4];
            ldmx4(bh4, sbase + BHo + boff + ntp * 2048);
            ldmx4(bl4, sbase + BL + boff + ntp * 2048);
#pragma unroll
            for (int mt = 0; mt < 2; mt++) {
                mma16816(acc[mt][ntp * 2 + 0], ah[mt], bh4);
                mma16816(acc[mt][ntp * 2 + 0], ah[mt], bl4);
                mma16816(acc[mt][ntp * 2 + 0], al[mt], bh4);
                mma16816(acc[mt][ntp * 2 + 1], ah[mt], bh4 + 2);
                mma16816(acc[mt][ntp * 2 + 1], ah[mt], bl4 + 2);
                mma16816(acc[mt][ntp * 2 + 1], al[mt], bh4 + 2);
            }
        }
    }

#pragma unroll
    for (int mt = 0; mt < 2; mt++) {
#pragma unroll
        for (int nt = 0; nt < 8; nt++) {
            int col = bk + wn + nt * 8 + (lane & 3) * 2;
#pragma unroll
            for (int half = 0; half < 2; half++) {
                int row = bj + wm + mt * 16 + (lane >> 2) + half * 8;
                size_t idx = ((size_t)bh << 20) + ((size_t)row << 10) + col;
                g_scores[idx]     = acc[mt][nt][half * 2 + 0];
                g_scores[idx + 1] = acc[mt][nt][half * 2 + 1];
            }
        }
    }
}

// ---------------- fp32 kernels (unchanged, known correct) -------------------
__global__ __launch_bounds__(192) void pbq_kernel(const float* __restrict__ pb) {
    const int j  = blockIdx.y;
    const int k0 = blockIdx.x * 128;
    __shared__ __align__(16) float Qs[64][48];
    __shared__ __align__(16) float Ps[64][128];
    const int tid = threadIdx.x;
    for (int i = tid; i < BH * 64; i += 192) {
        int bh = i >> 6, d = i & 63;
        Qs[d][bh] = g_qw[((size_t)bh * S + j) * 64 + d];
    }
    for (int i = tid; i < 2048; i += 192) {
        int kk = i >> 4, dq = (i & 15) * 4;
        float4 v = *(const float4*)&pb[((size_t)j * 1024 + k0 + kk) * 64 + dq];
        Ps[dq + 0][kk] = v.x; Ps[dq + 1][kk] = v.y;
        Ps[dq + 2][kk] = v.z; Ps[dq + 3][kk] = v.w;
    }
    __syncthreads();
    const int ty = tid >> 5, tx = tid & 31;
    ull acc[8][2] = {};
#pragma unroll 8
    for (int d = 0; d < 64; d++) {
        float4 a0 = *(const float4*)&Qs[d][ty * 8];
        float4 a1 = *(const float4*)&Qs[d][ty * 8 + 4];
        F4U b; b.f = *(const float4*)&Ps[d][tx * 4];
        float a[8] = {a0.x, a0.y, a0.z, a0.w, a1.x, a1.y, a1.z, a1.w};
#pragma unroll
        for (int i = 0; i < 8; i++) {
            ull ad = dup2(a[i]);
            fma2(acc[i][0], ad, b.u[0]);
            fma2(acc[i][1], ad, b.u[1]);
        }
    }
#pragma unroll
    for (int i = 0; i < 8; i++) {
        int bh = ty * 8 + i;
        size_t base = ((size_t)bh << 20) + ((size_t)j << 10) + k0 + tx * 4;
        UF2 v0, v1; v0.u = acc[i][0]; v1.u = acc[i][1];
        g_scores[base + 0] += v0.f.x;
        g_scores[base + 1] += v0.f.y;
        g_scores[base + 2] += v1.f.x;
        g_scores[base + 3] += v1.f.y;
    }
}

__global__ __launch_bounds__(256) void softmax_kernel(
    const float* __restrict__ amask, const int* __restrict__ vmask)
{
    const int j = blockIdx.x, bh = blockIdx.y, b = bh / Hh;
    const size_t base = ((size_t)bh << 20) + ((size_t)j << 10);
    const int tid = threadIdx.x;
    float x[4];
#pragma unroll
    for (int i = 0; i < 4; i++) {
        int k = tid + i * 256;
        float vv = g_scores[base + k] * 0.125f + amask[j * 1024 + k];
        x[i] = vmask[b * 1024 + k] ? vv : NEGV;
    }
    float m = fmaxf(fmaxf(x[0], x[1]), fmaxf(x[2], x[3]));
#pragma unroll
    for (int o = 16; o > 0; o >>= 1) m = fmaxf(m, __shfl_xor_sync(0xffffffffu, m, o));
    __shared__ float redm[8], reds[8];
    const int lane = tid & 31, w = tid >> 5;
    if (lane == 0) redm[w] = m;
    __syncthreads();
    m = redm[0];
#pragma unroll
    for (int i = 1; i < 8; i++) m = fmaxf(m, redm[i]);
    float s = 0.f;
#pragma unroll
    for (int i = 0; i < 4; i++) { x[i] = __expf(x[i] - m); s += x[i]; }
#pragma unroll
    for (int o = 16; o > 0; o >>= 1) s += __shfl_xor_sync(0xffffffffu, s, o);
    if (lane == 0) reds[w] = s;
    __syncthreads();
    s = reds[0];
#pragma unroll
    for (int i = 1; i < 8; i++) s += reds[i];
    float inv = 1.0f / s;
#pragma unroll
    for (int i = 0; i < 4; i++) g_scores[base + tid + i * 256] = x[i] * inv;
}

__global__ __launch_bounds__(256) void av_kernel() {
    const int bh = blockIdx.y;
    const int bj = blockIdx.x * 128;
    const float* A = g_scores + ((size_t)bh << 20);
    const float* V = g_vw + (size_t)bh * S * 64;
    __shared__ __align__(16) float As[16][128];
    __shared__ __align__(16) float Vs[16][64];
    const int tid = threadIdx.x;
    const int tx = tid & 15, ty = tid >> 4;
    const int r1 = tid >> 2, c1 = (tid & 3) * 4;
    const int vr = tid >> 4, vc = (tid & 15) * 4;
    ull acc[8][2] = {};
    for (int k0 = 0; k0 < 1024; k0 += 16) {
        float4 av0 = *(const float4*)&A[(size_t)(bj + r1)      * 1024 + k0 + c1];
        float4 av1 = *(const float4*)&A[(size_t)(bj + r1 + 64) * 1024 + k0 + c1];
        float4 vv  = *(const float4*)&V[(size_t)(k0 + vr) * 64 + vc];
        __syncthreads();
        As[c1 + 0][r1] = av0.x; As[c1 + 1][r1] = av0.y;
        As[c1 + 2][r1] = av0.z; As[c1 + 3][r1] = av0.w;
        As[c1 + 0][r1 + 64] = av1.x; As[c1 + 1][r1 + 64] = av1.y;
        As[c1 + 2][r1 + 64] = av1.z; As[c1 + 3][r1 + 64] = av1.w;
        *(float4*)&Vs[vr][vc] = vv;
        __syncthreads();
#pragma unroll
        for (int k = 0; k < 16; k++) {
            float4 a0 = *(const float4*)&As[k][ty * 8];
            float4 a1 = *(const float4*)&As[k][ty * 8 + 4];
            F4U b; b.f = *(const float4*)&Vs[k][tx * 4];
            float a[8] = {a0.x, a0.y, a0.z, a0.w, a1.x, a1.y, a1.z, a1.w};
#pragma unroll
            for (int i = 0; i < 8; i++) {
                ull ad = dup2(a[i]);
                fma2(acc[i][0], ad, b.u[0]);
                fma2(acc[i][1], ad, b.u[1]);
            }
        }
    }
    const int b = bh / Hh, h = bh % Hh;
#pragma unroll
    for (int i = 0; i < 8; i++) {
        int jrow = bj + ty * 8 + i;
        size_t idx = (((size_t)b * S + jrow) * Hh + h) * 64 + tx * 4;
        UF2 v0, v1; v0.u = acc[i][0]; v1.u = acc[i][1];
        g_attn[idx + 0] = v0.f.x;
        g_attn[idx + 1] = v0.f.y;
        g_attn[idx + 2] = v1.f.x;
        g_attn[idx + 3] = v1.f.y;
    }
}

__global__ __launch_bounds__(192) void apb_kernel(const float* __restrict__ pb) {
    const int j = blockIdx.x;
    __shared__ __align__(16) float As[32][48];
    __shared__ __align__(16) float Ps[32][64];
    const int tid = threadIdx.x;
    const int ty = tid >> 5, tx = tid & 31;
    ull acc[8] = {};
    for (int k0 = 0; k0 < 1024; k0 += 32) {
        __syncthreads();
        for (int i = tid; i < 48 * 32; i += 192) {
            int bh = i >> 5, kk = i & 31;
            As[kk][bh] = g_scores[((size_t)bh << 20) + ((size_t)j << 10) + k0 + kk];
        }
        for (int i = tid; i < 512; i += 192) {
            int kk = i >> 4, dq = (i & 15) * 4;
            *(float4*)&Ps[kk][dq] =
                *(const float4*)&pb[((size_t)j * 1024 + k0 + kk) * 64 + dq];
        }
        __syncthreads();
#pragma unroll 8
        for (int kk = 0; kk < 32; kk++) {
            float4 a0 = *(const float4*)&As[kk][ty * 8];
            float4 a1 = *(const float4*)&As[kk][ty * 8 + 4];
            UF2 bb; bb.f = *(const float2*)&Ps[kk][tx * 2];
            float a[8] = {a0.x, a0.y, a0.z, a0.w, a1.x, a1.y, a1.z, a1.w};
#pragma unroll
            for (int i = 0; i < 8; i++) fma2(acc[i], dup2(a[i]), bb.u);
        }
    }
#pragma unroll
    for (int i = 0; i < 8; i++) {
        int bh = ty * 8 + i;
        int b = bh / Hh, h = bh % Hh;
        size_t idx = (((size_t)b * S + j) * Hh + h) * 64 + tx * 2;
        UF2 v; v.u = acc[i];
        g_attn[idx + 0] += v.f.x;
        g_attn[idx + 1] += v.f.y;
    }
}

// ---------------------------------------------------------------------------
extern "C" void kernel_launch(void* const* d_in, const int* in_sizes, int n_in,
                              void* d_out, int out_size) {
    const float* q     = (const float*)d_in[0];
    const float* k     = (const float*)d_in[1];
    const float* v     = (const float*)d_in[2];
    const float* amask = (const float*)d_in[3];
    const float* pb    = (const float*)d_in[4];
    const int*   vmask = (const int*)  d_in[5];
    const float* Wq    = (const float*)d_in[6];
    const float* bq    = (const float*)d_in[7];
    const float* Wk    = (const float*)d_in[8];
    const float* bk    = (const float*)d_in[9];
    const float* Wv    = (const float*)d_in[10];
    const float* bv    = (const float*)d_in[11];
    const float* Wo    = (const float*)d_in[12];
    const float* bo    = (const float*)d_in[13];
    float* out = (float*)d_out;

    const int SMEM_MMA = 65536;
    static bool attr_done = false;
    if (!attr_done) {
        cudaFuncSetAttribute(gemm_mma_kernel,
            cudaFuncAttributeMaxDynamicSharedMemorySize, SMEM_MMA);
        cudaFuncSetAttribute(qk_mma_kernel,
            cudaFuncAttributeMaxDynamicSharedMemorySize, SMEM_MMA);
        attr_done = true;
    }

    const int n4 = 4096 * 768 / 4;
    conv_split_kernel<<<n4 / 256, 256>>>(q, 0, n4);
    conv_split_kernel<<<n4 / 256, 256>>>(k, 1, n4);
    conv_split_kernel<<<n4 / 256, 256>>>(v, 2, n4);
    dim3 tthr(32, 32), tgrd(24, 24);
    transpose_conv_kernel<<<tgrd, tthr>>>(Wq, 0);
    transpose_conv_kernel<<<tgrd, tthr>>>(Wk, 1);
    transpose_conv_kernel<<<tgrd, tthr>>>(Wv, 2);
    transpose_conv_kernel<<<tgrd, tthr>>>(Wo, 3);

    gemm_mma_kernel<<<dim3(6, 32, 3), 256, SMEM_MMA>>>(bq, bk, bv, nullptr, 0);
    qk_mma_kernel<<<dim3(8, 8, 48), 256, SMEM_MMA>>>();
    pbq_kernel<<<dim3(8, 1024), 192>>>(pb);
    softmax_kernel<<<dim3(1024, 48), 256>>>(amask, vmask);
    av_kernel<<<dim3(8, 48), 256>>>();
    apb_kernel<<<1024, 192>>>(pb);
    conv_split_kernel<<<n4 / 256, 256>>>(nullptr, 0, n4);
    gemm_mma_kernel<<<dim3(6, 32, 1), 256, SMEM_MMA>>>(bo, nullptr, nullptr, out, 1);
}

// round 4
// speedup vs baseline: 1.4935x; 1.0088x over previous
#include <cuda_runtime.h>
#include <cuda_bf16.h>
#include <cstdint>

// ---------------------------------------------------------------------------
// NEZHA-style MHA. HMMA (mma.sync bf16, hi/lo 3-product) for 4 dense GEMMs +
// QK^T; fp32 f32x2 for pb-einsums / softmax / AV.
// B=4, S=1024, H=12, DK=DV=64, DM=768.  Target compiles as plain sm_103
// (no tcgen05 available in this harness), so tensor work goes via mma.sync.
// ---------------------------------------------------------------------------

#define S 1024
#define Hh 12
#define BH 48
#define NEGV (-1e12f)

typedef unsigned long long ull;

// ---------------- scratch (static device memory) ----------------------------
__device__ float g_qw  [(size_t)BH * S * 64];
__device__ float g_vw  [(size_t)BH * S * 64];
__device__ float g_attn[(size_t)4 * S * 768];
__device__ float g_scores[(size_t)BH * S * S];     // 201 MB

__device__ __align__(16) __nv_bfloat16 g_xhi[(size_t)3 * 4096 * 768];
__device__ __align__(16) __nv_bfloat16 g_xlo[(size_t)3 * 4096 * 768];
__device__ __align__(16) __nv_bfloat16 g_wthi[(size_t)4 * 768 * 768];
__device__ __align__(16) __nv_bfloat16 g_wtlo[(size_t)4 * 768 * 768];
__device__ __align__(16) __nv_bfloat16 g_qhi[(size_t)BH * S * 64];
__device__ __align__(16) __nv_bfloat16 g_qlo[(size_t)BH * S * 64];
__device__ __align__(16) __nv_bfloat16 g_khi[(size_t)BH * S * 64];
__device__ __align__(16) __nv_bfloat16 g_klo[(size_t)BH * S * 64];

// ---------------- helpers ----------------------------------------------------
__device__ __forceinline__ uint32_t smem_to_u32(const void* p) {
    uint32_t a;
    asm("{ .reg .u64 t; cvta.to.shared.u64 t, %1; cvt.u32.u64 %0, t; }"
        : "=r"(a) : "l"(p));
    return a;
}
#define SWZ(o) ((uint32_t)(o) ^ ((((uint32_t)(o)) >> 3) & 0x70))

__device__ __forceinline__ void ldmx4(uint32_t* r, uint32_t a) {
    asm volatile("ldmatrix.sync.aligned.m8n8.x4.shared.b16 {%0,%1,%2,%3}, [%4];"
                 : "=r"(r[0]), "=r"(r[1]), "=r"(r[2]), "=r"(r[3]) : "r"(a));
}
__device__ __forceinline__ void mma16816(float* c, const uint32_t* a,
                                         const uint32_t* b) {
    asm volatile(
        "mma.sync.aligned.m16n8k16.row.col.f32.bf16.bf16.f32 "
        "{%0,%1,%2,%3},{%4,%5,%6,%7},{%8,%9},{%0,%1,%2,%3};"
        : "+f"(c[0]), "+f"(c[1]), "+f"(c[2]), "+f"(c[3])
        : "r"(a[0]), "r"(a[1]), "r"(a[2]), "r"(a[3]), "r"(b[0]), "r"(b[1]));
}

__device__ __forceinline__ void fma2(ull &acc, ull a, ull b) {
    asm("fma.rn.f32x2 %0, %1, %2, %0;" : "+l"(acc) : "l"(a), "l"(b));
}
__device__ __forceinline__ ull dup2(float x) {
    ull r; unsigned xi = __float_as_uint(x);
    asm("mov.b64 %0, {%1, %1};" : "=l"(r) : "r"(xi));
    return r;
}
union F4U { float4 f; ull u[2]; };
union UF2 { ull u; float2 f; };

// ---------------- conversion kernels ----------------------------------------
__global__ void conv_split_kernel(const float* __restrict__ src, int slot, int n4) {
    int i = blockIdx.x * blockDim.x + threadIdx.x;
    if (i >= n4) return;
    const float* s = src ? src : g_attn;
    float4 v = ((const float4*)s)[i];
    __nv_bfloat16* hi = g_xhi + (size_t)slot * 4096 * 768;
    __nv_bfloat16* lo = g_xlo + (size_t)slot * 4096 * 768;
    float vv[4] = {v.x, v.y, v.z, v.w};
#pragma unroll
    for (int c = 0; c < 4; c++) {
        __nv_bfloat16 h = __float2bfloat16(vv[c]);
        hi[(size_t)i * 4 + c] = h;
        lo[(size_t)i * 4 + c] = __float2bfloat16(vv[c] - __bfloat162float(h));
    }
}

__global__ void transpose_conv_kernel(const float* __restrict__ W, int slot) {
    __shared__ float t[32][33];
    int tx = threadIdx.x, ty = threadIdx.y;
    int k = blockIdx.y * 32 + ty, n = blockIdx.x * 32 + tx;
    t[ty][tx] = W[(size_t)k * 768 + n];
    __syncthreads();
    int n2 = blockIdx.x * 32 + ty, k2 = blockIdx.y * 32 + tx;
    float v = t[tx][ty];
    __nv_bfloat16 h = __float2bfloat16(v);
    size_t off = (size_t)slot * 768 * 768 + (size_t)n2 * 768 + k2;
    g_wthi[off] = h;
    g_wtlo[off] = __float2bfloat16(v - __bfloat162float(h));
}

// ---------------- HMMA dense GEMM: [4096x768] @ WT^T -> [4096x768] ----------
// mode 0: QKV (blockIdx.z selects x/W slot + epilogue), mode 1: out projection.
// Tiles 128x128, BK=64, 8 warps (4M x 2N), hi/lo 3-product bf16.
__global__ __launch_bounds__(256) void gemm_mma_kernel(
    const float* __restrict__ b0, const float* __restrict__ b1,
    const float* __restrict__ b2, float* __restrict__ yout, int mode)
{
    extern __shared__ __align__(128) char smem[];
    const uint32_t AH = 0, AL = 16384, BHo = 32768, BL = 49152;
    const uint32_t sbase = smem_to_u32(smem);
    const int tid = threadIdx.x, wid = tid >> 5, lane = tid & 31;
    const int z = blockIdx.z;
    const int bm = blockIdx.y * 128, bn = blockIdx.x * 128;
    const int xsel = (mode == 0) ? z : 0;
    const int wsel = (mode == 0) ? z : 3;
    const __nv_bfloat16* xh = g_xhi + (size_t)xsel * 4096 * 768;
    const __nv_bfloat16* xl = g_xlo + (size_t)xsel * 4096 * 768;
    const __nv_bfloat16* wh = g_wthi + (size_t)wsel * 768 * 768;
    const __nv_bfloat16* wl = g_wtlo + (size_t)wsel * 768 * 768;
    const float* bias = (mode == 1) ? b0 : (z == 0 ? b0 : (z == 1 ? b1 : b2));

    const int wm = (wid >> 1) * 32, wn = (wid & 1) * 64;
    float acc[2][8][4];
#pragma unroll
    for (int a = 0; a < 2; a++)
#pragma unroll
        for (int b = 0; b < 8; b++)
#pragma unroll
            for (int c = 0; c < 4; c++) acc[a][b][c] = 0.f;

    for (int st = 0; st < 12; st++) {
        const int k0 = st * 64;
        __syncthreads();
#pragma unroll
        for (int i = 0; i < 4; i++) {
            int idx = tid + i * 256;
            int row = idx >> 3, q = idx & 7;
            uint32_t dst = SWZ(row * 128 + q * 16);
            size_t sa = (size_t)(bm + row) * 768 + k0 + q * 8;
            size_t sb = (size_t)(bn + row) * 768 + k0 + q * 8;
            *(uint4*)(smem + AH + dst)  = *(const uint4*)(xh + sa);
            *(uint4*)(smem + AL + dst)  = *(const uint4*)(xl + sa);
            *(uint4*)(smem + BHo + dst) = *(const uint4*)(wh + sb);
            *(uint4*)(smem + BL + dst)  = *(const uint4*)(wl + sb);
        }
        __syncthreads();
#pragma unroll
        for (int kk = 0; kk < 4; kk++) {
            uint32_t ah[2][4], al[2][4];
            uint32_t aoff = SWZ((wm + (lane & 15)) * 128 + (kk * 2 + (lane >> 4)) * 16);
            ldmx4(ah[0], sbase + AH + aoff);
            ldmx4(ah[1], sbase + AH + aoff + 2048);
            ldmx4(al[0], sbase + AL + aoff);
            ldmx4(al[1], sbase + AL + aoff + 2048);
            uint32_t boff = SWZ((wn + (lane >> 4) * 8 + (lane & 7)) * 128 +
                                (kk * 2 + ((lane >> 3) & 1)) * 16);
#pragma unroll
            for (int ntp = 0; ntp < 4; ntp++) {
                uint32_t bh4[4], bl4[4];
                ldmx4(bh4, sbase + BHo + boff + ntp * 2048);
                ldmx4(bl4, sbase + BL + boff + ntp * 2048);
#pragma unroll
                for (int mt = 0; mt < 2; mt++) {
                    mma16816(acc[mt][ntp * 2 + 0], ah[mt], bh4);
                    mma16816(acc[mt][ntp * 2 + 0], ah[mt], bl4);
                    mma16816(acc[mt][ntp * 2 + 0], al[mt], bh4);
                    mma16816(acc[mt][ntp * 2 + 1], ah[mt], bh4 + 2);
                    mma16816(acc[mt][ntp * 2 + 1], ah[mt], bl4 + 2);
                    mma16816(acc[mt][ntp * 2 + 1], al[mt], bh4 + 2);
                }
            }
        }
    }

    // epilogue
#pragma unroll
    for (int mt = 0; mt < 2; mt++) {
#pragma unroll
        for (int nt = 0; nt < 8; nt++) {
            int col = bn + wn + nt * 8 + (lane & 3) * 2;
            float bx = bias[col], by = bias[col + 1];
#pragma unroll
            for (int half = 0; half < 2; half++) {
                int row = bm + wm + mt * 16 + (lane >> 2) + half * 8;
                float v0 = acc[mt][nt][half * 2 + 0] + bx;
                float v1 = acc[mt][nt][half * 2 + 1] + by;
                if (mode == 1) {
                    yout[(size_t)row * 768 + col]     = v0;
                    yout[(size_t)row * 768 + col + 1] = v1;
                } else {
                    int b = row >> 10, s = row & 1023;
                    int h = col >> 6, d = col & 63;
                    size_t base = ((size_t)(b * Hh + h) * S + s) * 64 + d;
                    if (z == 0) {
                        g_qw[base] = v0; g_qw[base + 1] = v1;
                        __nv_bfloat16 h0 = __float2bfloat16(v0);
                        __nv_bfloat16 h1 = __float2bfloat16(v1);
                        g_qhi[base] = h0; g_qhi[base + 1] = h1;
                        g_qlo[base]     = __float2bfloat16(v0 - __bfloat162float(h0));
                        g_qlo[base + 1] = __float2bfloat16(v1 - __bfloat162float(h1));
                    } else if (z == 1) {
                        __nv_bfloat16 h0 = __float2bfloat16(v0);
                        __nv_bfloat16 h1 = __float2bfloat16(v1);
                        g_khi[base] = h0; g_khi[base + 1] = h1;
                        g_klo[base]     = __float2bfloat16(v0 - __bfloat162float(h0));
                        g_klo[base + 1] = __float2bfloat16(v1 - __bfloat162float(h1));
                    } else {
                        g_vw[base] = v0; g_vw[base + 1] = v1;
                    }
                }
            }
        }
    }
}

// ---------------- HMMA QK^T: scores[bh][j][k] = qw.kw (K=64) -----------------
__global__ __launch_bounds__(256) void qk_mma_kernel() {
    extern __shared__ __align__(128) char smem[];
    const uint32_t AH = 0, AL = 16384, BHo = 32768, BL = 49152;
    const uint32_t sbase = smem_to_u32(smem);
    const int tid = threadIdx.x, wid = tid >> 5, lane = tid & 31;
    const int bh = blockIdx.z;
    const int bj = blockIdx.y * 128, bk = blockIdx.x * 128;
    const int wm = (wid >> 1) * 32, wn = (wid & 1) * 64;

    const size_t qb = ((size_t)bh * S + bj) * 64;
    const size_t kb = ((size_t)bh * S + bk) * 64;
#pragma unroll
    for (int i = 0; i < 4; i++) {
        int idx = tid + i * 256;
        int row = idx >> 3, q = idx & 7;
        uint32_t dst = SWZ(row * 128 + q * 16);
        size_t sa = qb + (size_t)row * 64 + q * 8;
        size_t sb = kb + (size_t)row * 64 + q * 8;
        *(uint4*)(smem + AH + dst)  = *(const uint4*)(g_qhi + sa);
        *(uint4*)(smem + AL + dst)  = *(const uint4*)(g_qlo + sa);
        *(uint4*)(smem + BHo + dst) = *(const uint4*)(g_khi + sb);
        *(uint4*)(smem + BL + dst)  = *(const uint4*)(g_klo + sb);
    }
    __syncthreads();

    float acc[2][8][4];
#pragma unroll
    for (int a = 0; a < 2; a++)
#pragma unroll
        for (int b = 0; b < 8; b++)
#pragma unroll
            for (int c = 0; c < 4; c++) acc[a][b][c] = 0.f;

#pragma unroll
    for (int kk = 0; kk < 4; kk++) {
        uint32_t ah[2][4], al[2][4];
        uint32_t aoff = SWZ((wm + (lane & 15)) * 128 + (kk * 2 + (lane >> 4)) * 16);
        ldmx4(ah[0], sbase + AH + aoff);
        ldmx4(ah[1], sbase + AH + aoff + 2048);
        ldmx4(al[0], sbase + AL + aoff);
        ldmx4(al[1], sbase + AL + aoff + 2048);
        uint32_t boff = SWZ((wn + (lane >> 4) * 8 + (lane & 7)) * 128 +
                            (kk * 2 + ((lane >> 3) & 1)) * 16);
#pragma unroll
        for (int ntp = 0; ntp < 4; ntp++) {
            uint32_t bh4[4], bl4[4];
            ldmx4(bh4, sbase + BHo + boff + ntp * 2048);
            ldmx4(bl4, sbase + BL + boff + ntp * 2048);
#pragma unroll
            for (int mt = 0; mt < 2; mt++) {
                mma16816(acc[mt][ntp * 2 + 0], ah[mt], bh4);
                mma16816(acc[mt][ntp * 2 + 0], ah[mt], bl4);
                mma16816(acc[mt][ntp * 2 + 0], al[mt], bh4);
                mma16816(acc[mt][ntp * 2 + 1], ah[mt], bh4 + 2);
                mma16816(acc[mt][ntp * 2 + 1], ah[mt], bl4 + 2);
                mma16816(acc[mt][ntp * 2 + 1], al[mt], bh4 + 2);
            }
        }
    }

#pragma unroll
    for (int mt = 0; mt < 2; mt++) {
#pragma unroll
        for (int nt = 0; nt < 8; nt++) {
            int col = bk + wn + nt * 8 + (lane & 3) * 2;
#pragma unroll
            for (int half = 0; half < 2; half++) {
                int row = bj + wm + mt * 16 + (lane >> 2) + half * 8;
                size_t idx = ((size_t)bh << 20) + ((size_t)row << 10) + col;
                g_scores[idx]     = acc[mt][nt][half * 2 + 0];
                g_scores[idx + 1] = acc[mt][nt][half * 2 + 1];
            }
        }
    }
}

// ---------------- fp32 kernels (unchanged, known correct) -------------------
__global__ __launch_bounds__(192) void pbq_kernel(const float* __restrict__ pb) {
    const int j  = blockIdx.y;
    const int k0 = blockIdx.x * 128;
    __shared__ __align__(16) float Qs[64][48];
    __shared__ __align__(16) float Ps[64][128];
    const int tid = threadIdx.x;
    for (int i = tid; i < BH * 64; i += 192) {
        int bh = i >> 6, d = i & 63;
        Qs[d][bh] = g_qw[((size_t)bh * S + j) * 64 + d];
    }
    for (int i = tid; i < 2048; i += 192) {
        int kk = i >> 4, dq = (i & 15) * 4;
        float4 v = *(const float4*)&pb[((size_t)j * 1024 + k0 + kk) * 64 + dq];
        Ps[dq + 0][kk] = v.x; Ps[dq + 1][kk] = v.y;
        Ps[dq + 2][kk] = v.z; Ps[dq + 3][kk] = v.w;
    }
    __syncthreads();
    const int ty = tid >> 5, tx = tid & 31;
    ull acc[8][2] = {};
#pragma unroll 8
    for (int d = 0; d < 64; d++) {
        float4 a0 = *(const float4*)&Qs[d][ty * 8];
        float4 a1 = *(const float4*)&Qs[d][ty * 8 + 4];
        F4U b; b.f = *(const float4*)&Ps[d][tx * 4];
        float a[8] = {a0.x, a0.y, a0.z, a0.w, a1.x, a1.y, a1.z, a1.w};
#pragma unroll
        for (int i = 0; i < 8; i++) {
            ull ad = dup2(a[i]);
            fma2(acc[i][0], ad, b.u[0]);
            fma2(acc[i][1], ad, b.u[1]);
        }
    }
#pragma unroll
    for (int i = 0; i < 8; i++) {
        int bh = ty * 8 + i;
        size_t base = ((size_t)bh << 20) + ((size_t)j << 10) + k0 + tx * 4;
        UF2 v0, v1; v0.u = acc[i][0]; v1.u = acc[i][1];
        g_scores[base + 0] += v0.f.x;
        g_scores[base + 1] += v0.f.y;
        g_scores[base + 2] += v1.f.x;
        g_scores[base + 3] += v1.f.y;
    }
}

__global__ __launch_bounds__(256) void softmax_kernel(
    const float* __restrict__ amask, const int* __restrict__ vmask)
{
    const int j = blockIdx.x, bh = blockIdx.y, b = bh / Hh;
    const size_t base = ((size_t)bh << 20) + ((size_t)j << 10);
    const int tid = threadIdx.x;
    float x[4];
#pragma unroll
    for (int i = 0; i < 4; i++) {
        int k = tid + i * 256;
        float vv = g_scores[base + k] * 0.125f + amask[j * 1024 + k];
        x[i] = vmask[b * 1024 + k] ? vv : NEGV;
    }
    float m = fmaxf(fmaxf(x[0], x[1]), fmaxf(x[2], x[3]));
#pragma unroll
    for (int o = 16; o > 0; o >>= 1) m = fmaxf(m, __shfl_xor_sync(0xffffffffu, m, o));
    __shared__ float redm[8], reds[8];
    const int lane = tid & 31, w = tid >> 5;
    if (lane == 0) redm[w] = m;
    __syncthreads();
    m = redm[0];
#pragma unroll
    for (int i = 1; i < 8; i++) m = fmaxf(m, redm[i]);
    float s = 0.f;
#pragma unroll
    for (int i = 0; i < 4; i++) { x[i] = __expf(x[i] - m); s += x[i]; }
#pragma unroll
    for (int o = 16; o > 0; o >>= 1) s += __shfl_xor_sync(0xffffffffu, s, o);
    if (lane == 0) reds[w] = s;
    __syncthreads();
    s = reds[0];
#pragma unroll
    for (int i = 1; i < 8; i++) s += reds[i];
    float inv = 1.0f / s;
#pragma unroll
    for (int i = 0; i < 4; i++) g_scores[base + tid + i * 256] = x[i] * inv;
}

__global__ __launch_bounds__(256) void av_kernel() {
    const int bh = blockIdx.y;
    const int bj = blockIdx.x * 128;
    const float* A = g_scores + ((size_t)bh << 20);
    const float* V = g_vw + (size_t)bh * S * 64;
    __shared__ __align__(16) float As[16][128];
    __shared__ __align__(16) float Vs[16][64];
    const int tid = threadIdx.x;
    const int tx = tid & 15, ty = tid >> 4;
    const int r1 = tid >> 2, c1 = (tid & 3) * 4;
    const int vr = tid >> 4, vc = (tid & 15) * 4;
    ull acc[8][2] = {};
    for (int k0 = 0; k0 < 1024; k0 += 16) {
        float4 av0 = *(const float4*)&A[(size_t)(bj + r1)      * 1024 + k0 + c1];
        float4 av1 = *(const float4*)&A[(size_t)(bj + r1 + 64) * 1024 + k0 + c1];
        float4 vv  = *(const float4*)&V[(size_t)(k0 + vr) * 64 + vc];
        __syncthreads();
        As[c1 + 0][r1] = av0.x; As[c1 + 1][r1] = av0.y;
        As[c1 + 2][r1] = av0.z; As[c1 + 3][r1] = av0.w;
        As[c1 + 0][r1 + 64] = av1.x; As[c1 + 1][r1 + 64] = av1.y;
        As[c1 + 2][r1 + 64] = av1.z; As[c1 + 3][r1 + 64] = av1.w;
        *(float4*)&Vs[vr][vc] = vv;
        __syncthreads();
#pragma unroll
        for (int k = 0; k < 16; k++) {
            float4 a0 = *(const float4*)&As[k][ty * 8];
            float4 a1 = *(const float4*)&As[k][ty * 8 + 4];
            F4U b; b.f = *(const float4*)&Vs[k][tx * 4];
            float a[8] = {a0.x, a0.y, a0.z, a0.w, a1.x, a1.y, a1.z, a1.w};
#pragma unroll
            for (int i = 0; i < 8; i++) {
                ull ad = dup2(a[i]);
                fma2(acc[i][0], ad, b.u[0]);
                fma2(acc[i][1], ad, b.u[1]);
            }
        }
    }
    const int b = bh / Hh, h = bh % Hh;
#pragma unroll
    for (int i = 0; i < 8; i++) {
        int jrow = bj + ty * 8 + i;
        size_t idx = (((size_t)b * S + jrow) * Hh + h) * 64 + tx * 4;
        UF2 v0, v1; v0.u = acc[i][0]; v1.u = acc[i][1];
        g_attn[idx + 0] = v0.f.x;
        g_attn[idx + 1] = v0.f.y;
        g_attn[idx + 2] = v1.f.x;
        g_attn[idx + 3] = v1.f.y;
    }
}

__global__ __launch_bounds__(192) void apb_kernel(const float* __restrict__ pb) {
    const int j = blockIdx.x;
    __shared__ __align__(16) float As[32][48];
    __shared__ __align__(16) float Ps[32][64];
    const int tid = threadIdx.x;
    const int ty = tid >> 5, tx = tid & 31;
    ull acc[8] = {};
    for (int k0 = 0; k0 < 1024; k0 += 32) {
        __syncthreads();
        for (int i = tid; i < 48 * 32; i += 192) {
            int bh = i >> 5, kk = i & 31;
            As[kk][bh] = g_scores[((size_t)bh << 20) + ((size_t)j << 10) + k0 + kk];
        }
        for (int i = tid; i < 512; i += 192) {
            int kk = i >> 4, dq = (i & 15) * 4;
            *(float4*)&Ps[kk][dq] =
                *(const float4*)&pb[((size_t)j * 1024 + k0 + kk) * 64 + dq];
        }
        __syncthreads();
#pragma unroll 8
        for (int kk = 0; kk < 32; kk++) {
            float4 a0 = *(const float4*)&As[kk][ty * 8];
            float4 a1 = *(const float4*)&As[kk][ty * 8 + 4];
            UF2 bb; bb.f = *(const float2*)&Ps[kk][tx * 2];
            float a[8] = {a0.x, a0.y, a0.z, a0.w, a1.x, a1.y, a1.z, a1.w};
#pragma unroll
            for (int i = 0; i < 8; i++) fma2(acc[i], dup2(a[i]), bb.u);
        }
    }
#pragma unroll
    for (int i = 0; i < 8; i++) {
        int bh = ty * 8 + i;
        int b = bh / Hh, h = bh % Hh;
        size_t idx = (((size_t)b * S + j) * Hh + h) * 64 + tx * 2;
        UF2 v; v.u = acc[i];
        g_attn[idx + 0] += v.f.x;
        g_attn[idx + 1] += v.f.y;
    }
}

// ---------------------------------------------------------------------------
extern "C" void kernel_launch(void* const* d_in, const int* in_sizes, int n_in,
                              void* d_out, int out_size) {
    const float* q     = (const float*)d_in[0];
    const float* k     = (const float*)d_in[1];
    const float* v     = (const float*)d_in[2];
    const float* amask = (const float*)d_in[3];
    const float* pb    = (const float*)d_in[4];
    const int*   vmask = (const int*)  d_in[5];
    const float* Wq    = (const float*)d_in[6];
    const float* bq    = (const float*)d_in[7];
    const float* Wk    = (const float*)d_in[8];
    const float* bk    = (const float*)d_in[9];
    const float* Wv    = (const float*)d_in[10];
    const float* bv    = (const float*)d_in[11];
    const float* Wo    = (const float*)d_in[12];
    const float* bo    = (const float*)d_in[13];
    float* out = (float*)d_out;

    const int SMEM_MMA = 65536;
    static bool attr_done = false;
    if (!attr_done) {
        cudaFuncSetAttribute(gemm_mma_kernel,
            cudaFuncAttributeMaxDynamicSharedMemorySize, SMEM_MMA);
        cudaFuncSetAttribute(qk_mma_kernel,
            cudaFuncAttributeMaxDynamicSharedMemorySize, SMEM_MMA);
        attr_done = true;
    }

    const int n4 = 4096 * 768 / 4;
    conv_split_kernel<<<n4 / 256, 256>>>(q, 0, n4);
    conv_split_kernel<<<n4 / 256, 256>>>(k, 1, n4);
    conv_split_kernel<<<n4 / 256, 256>>>(v, 2, n4);
    dim3 tthr(32, 32), tgrd(24, 24);
    transpose_conv_kernel<<<tgrd, tthr>>>(Wq, 0);
    transpose_conv_kernel<<<tgrd, tthr>>>(Wk, 1);
    transpose_conv_kernel<<<tgrd, tthr>>>(Wv, 2);
    transpose_conv_kernel<<<tgrd, tthr>>>(Wo, 3);

    gemm_mma_kernel<<<dim3(6, 32, 3), 256, SMEM_MMA>>>(bq, bk, bv, nullptr, 0);
    qk_mma_kernel<<<dim3(8, 8, 48), 256, SMEM_MMA>>>();
    pbq_kernel<<<dim3(8, 1024), 192>>>(pb);
    softmax_kernel<<<dim3(1024, 48), 256>>>(amask, vmask);
    av_kernel<<<dim3(8, 48), 256>>>();
    apb_kernel<<<1024, 192>>>(pb);
    conv_split_kernel<<<n4 / 256, 256>>>(nullptr, 0, n4);
    gemm_mma_kernel<<<dim3(6, 32, 1), 256, SMEM_MMA>>>(bo, nullptr, nullptr, out, 1);
}

// round 5
// speedup vs baseline: 1.5145x; 1.0141x over previous
#include <cuda_runtime.h>
#include <cuda_bf16.h>
#include <cstdint>

// ---------------------------------------------------------------------------
// NEZHA-style MHA, fully HMMA (mma.sync bf16 hi/lo 3-product).
// B=4, S=1024, H=12, DK=DV=64, DM=768.
// ---------------------------------------------------------------------------

#define S 1024
#define Hh 12
#define BH 48
#define NEGV (-1e12f)

// ---------------- scratch -----------------------------------------------------
__device__ float g_attn[(size_t)4 * S * 768];
__device__ float g_scores[(size_t)BH * S * S];     // 201 MB

__device__ __align__(16) __nv_bfloat16 g_xhi[(size_t)3 * 4096 * 768];
__device__ __align__(16) __nv_bfloat16 g_xlo[(size_t)3 * 4096 * 768];
__device__ __align__(16) __nv_bfloat16 g_wthi[(size_t)4 * 768 * 768];
__device__ __align__(16) __nv_bfloat16 g_wtlo[(size_t)4 * 768 * 768];
__device__ __align__(16) __nv_bfloat16 g_qhi[(size_t)BH * S * 64];
__device__ __align__(16) __nv_bfloat16 g_qlo[(size_t)BH * S * 64];
__device__ __align__(16) __nv_bfloat16 g_khi[(size_t)BH * S * 64];
__device__ __align__(16) __nv_bfloat16 g_klo[(size_t)BH * S * 64];
__device__ __align__(16) __nv_bfloat16 g_vwthi[(size_t)BH * 64 * S];  // [bh][d][s]
__device__ __align__(16) __nv_bfloat16 g_vwtlo[(size_t)BH * 64 * S];
__device__ __align__(16) __nv_bfloat16 g_Ahi[(size_t)BH * S * S];    // 100 MB
__device__ __align__(16) __nv_bfloat16 g_Alo[(size_t)BH * S * S];

// ---------------- helpers -----------------------------------------------------
__device__ __forceinline__ uint32_t smem_to_u32(const void* p) {
    uint32_t a;
    asm("{ .reg .u64 t; cvta.to.shared.u64 t, %1; cvt.u32.u64 %0, t; }"
        : "=r"(a) : "l"(p));
    return a;
}
#define SWZ(o)    ((uint32_t)(o) ^ ((((uint32_t)(o)) >> 3) & 0x70))
#define SWZ256(o) ((uint32_t)(o) ^ ((((uint32_t)(o)) >> 4) & 0x70))

__device__ __forceinline__ void ldmx4(uint32_t* r, uint32_t a) {
    asm volatile("ldmatrix.sync.aligned.m8n8.x4.shared.b16 {%0,%1,%2,%3}, [%4];"
                 : "=r"(r[0]), "=r"(r[1]), "=r"(r[2]), "=r"(r[3]) : "r"(a));
}
__device__ __forceinline__ void mma16816(float* c, const uint32_t* a,
                                         const uint32_t* b) {
    asm volatile(
        "mma.sync.aligned.m16n8k16.row.col.f32.bf16.bf16.f32 "
        "{%0,%1,%2,%3},{%4,%5,%6,%7},{%8,%9},{%0,%1,%2,%3};"
        : "+f"(c[0]), "+f"(c[1]), "+f"(c[2]), "+f"(c[3])
        : "r"(a[0]), "r"(a[1]), "r"(a[2]), "r"(a[3]), "r"(b[0]), "r"(b[1]));
}
__device__ __forceinline__ uint32_t bfpack(__nv_bfloat16 a, __nv_bfloat16 b) {
    __nv_bfloat162 t(a, b);
    return *(uint32_t*)&t;
}
__device__ __forceinline__ void split4(float4 v, uint2& hi, uint2& lo) {
    __nv_bfloat16 h0 = __float2bfloat16(v.x), h1 = __float2bfloat16(v.y),
                  h2 = __float2bfloat16(v.z), h3 = __float2bfloat16(v.w);
    hi.x = bfpack(h0, h1); hi.y = bfpack(h2, h3);
    lo.x = bfpack(__float2bfloat16(v.x - __bfloat162float(h0)),
                  __float2bfloat16(v.y - __bfloat162float(h1)));
    lo.y = bfpack(__float2bfloat16(v.z - __bfloat162float(h2)),
                  __float2bfloat16(v.w - __bfloat162float(h3)));
}

// ---------------- conversion kernels ------------------------------------------
__global__ void conv_split_kernel(const float* __restrict__ src, int slot, int n4) {
    int i = blockIdx.x * blockDim.x + threadIdx.x;
    if (i >= n4) return;
    const float* s = src ? src : g_attn;
    float4 v = ((const float4*)s)[i];
    uint2 h, l; split4(v, h, l);
    *(uint2*)(g_xhi + (size_t)slot * 4096 * 768 + (size_t)i * 4) = h;
    *(uint2*)(g_xlo + (size_t)slot * 4096 * 768 + (size_t)i * 4) = l;
}

__global__ void transpose_conv_kernel(const float* __restrict__ W, int slot) {
    __shared__ float t[32][33];
    int tx = threadIdx.x, ty = threadIdx.y;
    int k = blockIdx.y * 32 + ty, n = blockIdx.x * 32 + tx;
    t[ty][tx] = W[(size_t)k * 768 + n];
    __syncthreads();
    int n2 = blockIdx.x * 32 + ty, k2 = blockIdx.y * 32 + tx;
    float v = t[tx][ty];
    __nv_bfloat16 h = __float2bfloat16(v);
    size_t off = (size_t)slot * 768 * 768 + (size_t)n2 * 768 + k2;
    g_wthi[off] = h;
    g_wtlo[off] = __float2bfloat16(v - __bfloat162float(h));
}

// ---------------- HMMA dense GEMM ---------------------------------------------
// mode 0: QKV (z = 0/1/2); z==2 writes vw^T hi/lo. mode 1: output projection.
__global__ __launch_bounds__(256) void gemm_mma_kernel(
    const float* __restrict__ b0, const float* __restrict__ b1,
    const float* __restrict__ b2, float* __restrict__ yout, int mode)
{
    extern __shared__ __align__(128) char smem[];
    const uint32_t AHo = 0, ALo = 16384, BHo = 32768, BLo = 49152;
    const uint32_t sbase = smem_to_u32(smem);
    const int tid = threadIdx.x, wid = tid >> 5, lane = tid & 31;
    const int z = blockIdx.z;
    const int bm = blockIdx.y * 128, bn = blockIdx.x * 128;
    const int xsel = (mode == 0) ? z : 0;
    const int wsel = (mode == 0) ? z : 3;
    const __nv_bfloat16* xh = g_xhi + (size_t)xsel * 4096 * 768;
    const __nv_bfloat16* xl = g_xlo + (size_t)xsel * 4096 * 768;
    const __nv_bfloat16* wh = g_wthi + (size_t)wsel * 768 * 768;
    const __nv_bfloat16* wl = g_wtlo + (size_t)wsel * 768 * 768;
    const float* bias = (mode == 1) ? b0 : (z == 0 ? b0 : (z == 1 ? b1 : b2));

    const int wm = (wid >> 1) * 32, wn = (wid & 1) * 64;
    float acc[2][8][4];
#pragma unroll
    for (int a = 0; a < 2; a++)
#pragma unroll
        for (int b = 0; b < 8; b++)
#pragma unroll
            for (int c = 0; c < 4; c++) acc[a][b][c] = 0.f;

    for (int st = 0; st < 12; st++) {
        const int k0 = st * 64;
        __syncthreads();
#pragma unroll
        for (int i = 0; i < 4; i++) {
            int idx = tid + i * 256;
            int row = idx >> 3, q = idx & 7;
            uint32_t dst = SWZ(row * 128 + q * 16);
            size_t sa = (size_t)(bm + row) * 768 + k0 + q * 8;
            size_t sb = (size_t)(bn + row) * 768 + k0 + q * 8;
            *(uint4*)(smem + AHo + dst) = *(const uint4*)(xh + sa);
            *(uint4*)(smem + ALo + dst) = *(const uint4*)(xl + sa);
            *(uint4*)(smem + BHo + dst) = *(const uint4*)(wh + sb);
            *(uint4*)(smem + BLo + dst) = *(const uint4*)(wl + sb);
        }
        __syncthreads();
#pragma unroll
        for (int kk = 0; kk < 4; kk++) {
            uint32_t ah[2][4], al[2][4];
            uint32_t aoff = SWZ((wm + (lane & 15)) * 128 + (kk * 2 + (lane >> 4)) * 16);
            ldmx4(ah[0], sbase + AHo + aoff);
            ldmx4(ah[1], sbase + AHo + aoff + 2048);
            ldmx4(al[0], sbase + ALo + aoff);
            ldmx4(al[1], sbase + ALo + aoff + 2048);
            uint32_t boff = SWZ((wn + (lane >> 4) * 8 + (lane & 7)) * 128 +
                                (kk * 2 + ((lane >> 3) & 1)) * 16);
#pragma unroll
            for (int ntp = 0; ntp < 4; ntp++) {
                uint32_t bh4[4], bl4[4];
                ldmx4(bh4, sbase + BHo + boff + ntp * 2048);
                ldmx4(bl4, sbase + BLo + boff + ntp * 2048);
#pragma unroll
                for (int mt = 0; mt < 2; mt++) {
                    mma16816(acc[mt][ntp * 2 + 0], ah[mt], bh4);
                    mma16816(acc[mt][ntp * 2 + 0], ah[mt], bl4);
                    mma16816(acc[mt][ntp * 2 + 0], al[mt], bh4);
                    mma16816(acc[mt][ntp * 2 + 1], ah[mt], bh4 + 2);
                    mma16816(acc[mt][ntp * 2 + 1], ah[mt], bl4 + 2);
                    mma16816(acc[mt][ntp * 2 + 1], al[mt], bh4 + 2);
                }
            }
        }
    }

    if (mode == 0 && z == 2) {
        // V projection: smem-transpose to vw^T hi/lo [bh][d][s].
        __syncthreads();
        __nv_bfloat16* Th = (__nv_bfloat16*)smem;               // [128][136]
        __nv_bfloat16* Tl = (__nv_bfloat16*)(smem + 34816);
#pragma unroll
        for (int mt = 0; mt < 2; mt++) {
#pragma unroll
            for (int nt = 0; nt < 8; nt++) {
                int cl = wn + nt * 8 + (lane & 3) * 2;
                float bx = bias[bn + cl], by = bias[bn + cl + 1];
#pragma unroll
                for (int half = 0; half < 2; half++) {
                    int rl = wm + mt * 16 + (lane >> 2) + half * 8;
                    float v0 = acc[mt][nt][half * 2 + 0] + bx;
                    float v1 = acc[mt][nt][half * 2 + 1] + by;
                    __nv_bfloat16 h0 = __float2bfloat16(v0);
                    __nv_bfloat16 h1 = __float2bfloat16(v1);
                    Th[cl * 136 + rl] = h0;
                    Tl[cl * 136 + rl] = __float2bfloat16(v0 - __bfloat162float(h0));
                    Th[(cl + 1) * 136 + rl] = h1;
                    Tl[(cl + 1) * 136 + rl] = __float2bfloat16(v1 - __bfloat162float(h1));
                }
            }
        }
        __syncthreads();
        int b = bm >> 10, s0 = bm & 1023;
#pragma unroll
        for (int it = 0; it < 8; it++) {
            int g = tid + it * 256;
            int cl = g >> 4, q = g & 15;
            int cg = bn + cl, h = cg >> 6, d = cg & 63;
            size_t o = (((size_t)(b * Hh + h)) * 64 + d) * 1024 + s0 + q * 8;
            *(uint4*)(g_vwthi + o) = *(uint4*)&Th[cl * 136 + q * 8];
            *(uint4*)(g_vwtlo + o) = *(uint4*)&Tl[cl * 136 + q * 8];
        }
        return;
    }

#pragma unroll
    for (int mt = 0; mt < 2; mt++) {
#pragma unroll
        for (int nt = 0; nt < 8; nt++) {
            int col = bn + wn + nt * 8 + (lane & 3) * 2;
            float bx = bias[col], by = bias[col + 1];
#pragma unroll
            for (int half = 0; half < 2; half++) {
                int row = bm + wm + mt * 16 + (lane >> 2) + half * 8;
                float v0 = acc[mt][nt][half * 2 + 0] + bx;
                float v1 = acc[mt][nt][half * 2 + 1] + by;
                if (mode == 1) {
                    yout[(size_t)row * 768 + col]     = v0;
                    yout[(size_t)row * 768 + col + 1] = v1;
                } else {
                    int b = row >> 10, s = row & 1023;
                    int h = col >> 6, d = col & 63;
                    size_t base = ((size_t)(b * Hh + h) * S + s) * 64 + d;
                    __nv_bfloat16 h0 = __float2bfloat16(v0);
                    __nv_bfloat16 h1 = __float2bfloat16(v1);
                    if (z == 0) {
                        g_qhi[base] = h0; g_qhi[base + 1] = h1;
                        g_qlo[base]     = __float2bfloat16(v0 - __bfloat162float(h0));
                        g_qlo[base + 1] = __float2bfloat16(v1 - __bfloat162float(h1));
                    } else {
                        g_khi[base] = h0; g_khi[base + 1] = h1;
                        g_klo[base]     = __float2bfloat16(v0 - __bfloat162float(h0));
                        g_klo[base + 1] = __float2bfloat16(v1 - __bfloat162float(h1));
                    }
                }
            }
        }
    }
}

// ---------------- HMMA QK^T ----------------------------------------------------
__global__ __launch_bounds__(256) void qk_mma_kernel() {
    extern __shared__ __align__(128) char smem[];
    const uint32_t AHo = 0, ALo = 16384, BHo = 32768, BLo = 49152;
    const uint32_t sbase = smem_to_u32(smem);
    const int tid = threadIdx.x, wid = tid >> 5, lane = tid & 31;
    const int bh = blockIdx.z;
    const int bj = blockIdx.y * 128, bk = blockIdx.x * 128;
    const int wm = (wid >> 1) * 32, wn = (wid & 1) * 64;

    const size_t qb = ((size_t)bh * S + bj) * 64;
    const size_t kb = ((size_t)bh * S + bk) * 64;
#pragma unroll
    for (int i = 0; i < 4; i++) {
        int idx = tid + i * 256;
        int row = idx >> 3, q = idx & 7;
        uint32_t dst = SWZ(row * 128 + q * 16);
        size_t sa = qb + (size_t)row * 64 + q * 8;
        size_t sb = kb + (size_t)row * 64 + q * 8;
        *(uint4*)(smem + AHo + dst) = *(const uint4*)(g_qhi + sa);
        *(uint4*)(smem + ALo + dst) = *(const uint4*)(g_qlo + sa);
        *(uint4*)(smem + BHo + dst) = *(const uint4*)(g_khi + sb);
        *(uint4*)(smem + BLo + dst) = *(const uint4*)(g_klo + sb);
    }
    __syncthreads();

    float acc[2][8][4];
#pragma unroll
    for (int a = 0; a < 2; a++)
#pragma unroll
        for (int b = 0; b < 8; b++)
#pragma unroll
            for (int c = 0; c < 4; c++) acc[a][b][c] = 0.f;

#pragma unroll
    for (int kk = 0; kk < 4; kk++) {
        uint32_t ah[2][4], al[2][4];
        uint32_t aoff = SWZ((wm + (lane & 15)) * 128 + (kk * 2 + (lane >> 4)) * 16);
        ldmx4(ah[0], sbase + AHo + aoff);
        ldmx4(ah[1], sbase + AHo + aoff + 2048);
        ldmx4(al[0], sbase + ALo + aoff);
        ldmx4(al[1], sbase + ALo + aoff + 2048);
        uint32_t boff = SWZ((wn + (lane >> 4) * 8 + (lane & 7)) * 128 +
                            (kk * 2 + ((lane >> 3) & 1)) * 16);
#pragma unroll
        for (int ntp = 0; ntp < 4; ntp++) {
            uint32_t bh4[4], bl4[4];
            ldmx4(bh4, sbase + BHo + boff + ntp * 2048);
            ldmx4(bl4, sbase + BLo + boff + ntp * 2048);
#pragma unroll
            for (int mt = 0; mt < 2; mt++) {
                mma16816(acc[mt][ntp * 2 + 0], ah[mt], bh4);
                mma16816(acc[mt][ntp * 2 + 0], ah[mt], bl4);
                mma16816(acc[mt][ntp * 2 + 0], al[mt], bh4);
                mma16816(acc[mt][ntp * 2 + 1], ah[mt], bh4 + 2);
                mma16816(acc[mt][ntp * 2 + 1], ah[mt], bl4 + 2);
                mma16816(acc[mt][ntp * 2 + 1], al[mt], bh4 + 2);
            }
        }
    }

#pragma unroll
    for (int mt = 0; mt < 2; mt++) {
#pragma unroll
        for (int nt = 0; nt < 8; nt++) {
            int col = bk + wn + nt * 8 + (lane & 3) * 2;
#pragma unroll
            for (int half = 0; half < 2; half++) {
                int row = bj + wm + mt * 16 + (lane >> 2) + half * 8;
                size_t idx = ((size_t)bh << 20) + ((size_t)row << 10) + col;
                g_scores[idx]     = acc[mt][nt][half * 2 + 0];
                g_scores[idx + 1] = acc[mt][nt][half * 2 + 1];
            }
        }
    }
}

// ---------------------------------------------------------------------------
// Fused: scores += qw·pb (MMA), scale+mask+softmax, A -> bf16 hi/lo global.
// Grid (3 thirds of bh, 1024 j), 256 threads. smem 123392 B.
// ---------------------------------------------------------------------------
__global__ __launch_bounds__(256) void fused_pbq_sm_kernel(
    const float* __restrict__ pb, const float* __restrict__ amask,
    const int* __restrict__ vmask)
{
    extern __shared__ __align__(128) char smem[];
    float* Sf = (float*)smem;                     // [16][1032] fp32
    const uint32_t PBH = 66048, PBL = 82432;      // [128][64] bf16 swizzled
    const uint32_t QHo = 98816, QLo = 100864;     // [16][64] bf16 swizzled
    float*  AM = (float*)(smem + 102912);         // [1024]
    float2* MV = (float2*)(smem + 107008);        // [2][1024] {m, neg}
    const uint32_t sbase = smem_to_u32(smem);
    const int tid = threadIdx.x, wid = tid >> 5, lane = tid & 31;
    const int t = blockIdx.x, j = blockIdx.y;
    const int bh0 = t * 16, bmin = bh0 / Hh;

    // load scores rows
#pragma unroll
    for (int it = 0; it < 16; it++) {
        int idx = tid + it * 256;
        int row = idx >> 8, k4 = idx & 255;
        *(float4*)&Sf[row * 1032 + k4 * 4] =
            *(const float4*)(g_scores + (((size_t)(bh0 + row)) << 20) +
                             ((size_t)j << 10) + k4 * 4);
    }
    // load Q hi/lo
    if (tid < 128) {
        int r = tid >> 3, q = tid & 7;
        uint32_t dst = SWZ(r * 128 + q * 16);
        size_t src = ((size_t)(bh0 + r) * 1024 + j) * 64 + q * 8;
        *(uint4*)(smem + QHo + dst) = *(const uint4*)(g_qhi + src);
        *(uint4*)(smem + QLo + dst) = *(const uint4*)(g_qlo + src);
    }
    // amask row + vmask -> {m, neg}
    *(float4*)&AM[tid * 4] = *(const float4*)(amask + (size_t)j * 1024 + tid * 4);
#pragma unroll
    for (int r2 = 0; r2 < 2; r2++) {
        int4 m = *(const int4*)(vmask + (size_t)(bmin + r2) * 1024 + tid * 4);
        MV[r2 * 1024 + tid * 4 + 0] = make_float2(m.x ? 1.f : 0.f, m.x ? 0.f : NEGV);
        MV[r2 * 1024 + tid * 4 + 1] = make_float2(m.y ? 1.f : 0.f, m.y ? 0.f : NEGV);
        MV[r2 * 1024 + tid * 4 + 2] = make_float2(m.z ? 1.f : 0.f, m.z ? 0.f : NEGV);
        MV[r2 * 1024 + tid * 4 + 3] = make_float2(m.w ? 1.f : 0.f, m.w ? 0.f : NEGV);
    }
    __syncthreads();

    // hoist Q fragments (M=16, K=64)
    uint32_t ah[4][4], al[4][4];
#pragma unroll
    for (int ks = 0; ks < 4; ks++) {
        uint32_t aoff = SWZ((lane & 15) * 128 + (ks * 2 + (lane >> 4)) * 16);
        ldmx4(ah[ks], sbase + QHo + aoff);
        ldmx4(al[ks], sbase + QLo + aoff);
    }

    // pbq: 8 chunks of 128 k-columns
    for (int c = 0; c < 8; c++) {
        const int k0 = c * 128;
        __syncthreads();
#pragma unroll
        for (int it = 0; it < 8; it++) {
            int idx = tid + it * 256;
            int kk = idx >> 4, q4 = idx & 15;
            float4 v = *(const float4*)(pb + ((size_t)j * 1024 + k0 + kk) * 64 + q4 * 4);
            uint2 hi, lo; split4(v, hi, lo);
            uint32_t dst = SWZ(kk * 128 + q4 * 8);
            *(uint2*)(smem + PBH + dst) = hi;
            *(uint2*)(smem + PBL + dst) = lo;
        }
        __syncthreads();
        float frag[2][4] = {{0.f, 0.f, 0.f, 0.f}, {0.f, 0.f, 0.f, 0.f}};
#pragma unroll
        for (int ks = 0; ks < 4; ks++) {
            uint32_t boff = SWZ((wid * 16 + (lane >> 4) * 8 + (lane & 7)) * 128 +
                                (ks * 2 + ((lane >> 3) & 1)) * 16);
            uint32_t bh4[4], bl4[4];
            ldmx4(bh4, sbase + PBH + boff);
            ldmx4(bl4, sbase + PBL + boff);
            mma16816(frag[0], ah[ks], bh4);
            mma16816(frag[0], ah[ks], bl4);
            mma16816(frag[0], al[ks], bh4);
            mma16816(frag[1], ah[ks], bh4 + 2);
            mma16816(frag[1], ah[ks], bl4 + 2);
            mma16816(frag[1], al[ks], bh4 + 2);
        }
        int r0 = lane >> 2, c0 = (lane & 3) * 2;
#pragma unroll
        for (int nt = 0; nt < 2; nt++)
#pragma unroll
            for (int e = 0; e < 4; e++) {
                int row = r0 + (e >> 1) * 8;
                int col = k0 + wid * 16 + nt * 8 + c0 + (e & 1);
                Sf[row * 1032 + col] += frag[nt][e];
            }
    }
    __syncthreads();

    // softmax: warp w handles rows 2w, 2w+1
#pragma unroll
    for (int rr = 0; rr < 2; rr++) {
        int row = wid * 2 + rr;
        int bsel = (bh0 + row) / Hh - bmin;
        float x[32];
        float mx = -3.4e38f;
#pragma unroll
        for (int i = 0; i < 32; i++) {
            int k = lane + i * 32;
            float2 mv = MV[bsel * 1024 + k];
            float val = fmaf(Sf[row * 1032 + k], 0.125f, AM[k]);
            x[i] = fmaf(val, mv.x, mv.y);
            mx = fmaxf(mx, x[i]);
        }
#pragma unroll
        for (int o = 16; o > 0; o >>= 1) mx = fmaxf(mx, __shfl_xor_sync(~0u, mx, o));
        float sum = 0.f;
#pragma unroll
        for (int i = 0; i < 32; i++) { x[i] = __expf(x[i] - mx); sum += x[i]; }
#pragma unroll
        for (int o = 16; o > 0; o >>= 1) sum += __shfl_xor_sync(~0u, sum, o);
        float inv = 1.f / sum;
#pragma unroll
        for (int i = 0; i < 32; i++) Sf[row * 1032 + lane + i * 32] = x[i] * inv;
    }
    __syncthreads();

    // write A bf16 hi/lo
    const int row = tid >> 4, kb = (tid & 15) * 64;
    const size_t obase = (((size_t)(bh0 + row)) << 20) + ((size_t)j << 10);
#pragma unroll
    for (int g = 0; g < 8; g++) {
        int k = kb + g * 8;
        float4 a = *(float4*)&Sf[row * 1032 + k];
        float4 b = *(float4*)&Sf[row * 1032 + k + 4];
        uint2 h0, l0, h1, l1;
        split4(a, h0, l0); split4(b, h1, l1);
        uint4 Hq = make_uint4(h0.x, h0.y, h1.x, h1.y);
        uint4 Lq = make_uint4(l0.x, l0.y, l1.x, l1.y);
        *(uint4*)(g_Ahi + obase + k) = Hq;
        *(uint4*)(g_Alo + obase + k) = Lq;
    }
}

// ---------------------------------------------------------------------------
// apb: attn[b][j][h][d] = sum_k A[bh][j][k] * pb[j][k][d]   (writes "=")
// Grid 1024 (j). M=64 (48 bh + pad), N=64 (d), K=1024 in 8 chunks.
// ---------------------------------------------------------------------------
__global__ __launch_bounds__(256) void apb_mma_kernel(const float* __restrict__ pb) {
    extern __shared__ __align__(128) char smem[];
    const uint32_t AHs = 0, ALs = 16384, PTH = 32768, PTL = 49152;
    const uint32_t sbase = smem_to_u32(smem);
    const int tid = threadIdx.x, wid = tid >> 5, lane = tid & 31;
    const int j = blockIdx.x;
    const int mt = wid >> 1, nb = (wid & 1) * 32;

    float facc[4][4];
#pragma unroll
    for (int a = 0; a < 4; a++)
#pragma unroll
        for (int b = 0; b < 4; b++) facc[a][b] = 0.f;

    for (int c = 0; c < 8; c++) {
        const int k0 = c * 128;
        __syncthreads();
        // A rows (48 real, 16 zero)
#pragma unroll
        for (int it = 0; it < 8; it++) {
            int idx = tid + it * 256;
            int buf = idx >> 10, rc = idx & 1023;
            int row = rc >> 4, q = rc & 15;
            uint32_t dst = SWZ256(row * 256 + q * 16);
            uint4 v = make_uint4(0, 0, 0, 0);
            if (row < 48) {
                const __nv_bfloat16* src = buf ? g_Alo : g_Ahi;
                v = *(const uint4*)(src + (((size_t)row) << 20) +
                                    ((size_t)j << 10) + k0 + q * 8);
            }
            *(uint4*)(smem + (buf ? ALs : AHs) + dst) = v;
        }
        // pb^T chunk hi/lo
#pragma unroll
        for (int it = 0; it < 8; it++) {
            int idx = tid + it * 256;
            int kk = idx >> 4, q4 = idx & 15;
            float4 v = *(const float4*)(pb + ((size_t)j * 1024 + k0 + kk) * 64 + q4 * 4);
            float vv[4] = {v.x, v.y, v.z, v.w};
#pragma unroll
            for (int i = 0; i < 4; i++) {
                int d = q4 * 4 + i;
                __nv_bfloat16 h = __float2bfloat16(vv[i]);
                uint32_t o = SWZ256(d * 256 + kk * 2);
                *(__nv_bfloat16*)(smem + PTH + o) = h;
                *(__nv_bfloat16*)(smem + PTL + o) =
                    __float2bfloat16(vv[i] - __bfloat162float(h));
            }
        }
        __syncthreads();
#pragma unroll
        for (int ks = 0; ks < 8; ks++) {
            uint32_t a_h[4], a_l[4];
            uint32_t aoff = SWZ256((mt * 16 + (lane & 15)) * 256 +
                                   (ks * 2 + (lane >> 4)) * 16);
            ldmx4(a_h, sbase + AHs + aoff);
            ldmx4(a_l, sbase + ALs + aoff);
#pragma unroll
            for (int np = 0; np < 2; np++) {
                uint32_t boff = SWZ256((nb + np * 16 + (lane >> 4) * 8 + (lane & 7)) * 256 +
                                       (ks * 2 + ((lane >> 3) & 1)) * 16);
                uint32_t b_h[4], b_l[4];
                ldmx4(b_h, sbase + PTH + boff);
                ldmx4(b_l, sbase + PTL + boff);
                mma16816(facc[np * 2 + 0], a_h, b_h);
                mma16816(facc[np * 2 + 0], a_h, b_l);
                mma16816(facc[np * 2 + 0], a_l, b_h);
                mma16816(facc[np * 2 + 1], a_h, b_h + 2);
                mma16816(facc[np * 2 + 1], a_h, b_l + 2);
                mma16816(facc[np * 2 + 1], a_l, b_h + 2);
            }
        }
    }
#pragma unroll
    for (int nt = 0; nt < 4; nt++) {
        int d = nb + nt * 8 + (lane & 3) * 2;
#pragma unroll
        for (int half = 0; half < 2; half++) {
            int bh = mt * 16 + (lane >> 2) + half * 8;
            if (bh < 48) {
                int b = bh / Hh, h = bh % Hh;
                size_t o = ((size_t)(b * 1024 + j)) * 768 + h * 64 + d;
                g_attn[o]     = facc[nt][half * 2 + 0];
                g_attn[o + 1] = facc[nt][half * 2 + 1];
            }
        }
    }
}

// ---------------------------------------------------------------------------
// av: attn[b][j][h][d] += sum_k A[bh][j][k] * vw[bh][k][d]
// Grid (8 j-tiles, 48 bh). M=128 (j), N=64 (d), K=1024 in 8 chunks.
// ---------------------------------------------------------------------------
__global__ __launch_bounds__(256) void av_mma_kernel() {
    extern __shared__ __align__(128) char smem[];
    const uint32_t AHs = 0, ALs = 32768, VHs = 65536, VLs = 81920;
    const uint32_t sbase = smem_to_u32(smem);
    const int tid = threadIdx.x, wid = tid >> 5, lane = tid & 31;
    const int bh = blockIdx.y, j0 = blockIdx.x * 128;

    float facc[8][4];
#pragma unroll
    for (int a = 0; a < 8; a++)
#pragma unroll
        for (int b = 0; b < 4; b++) facc[a][b] = 0.f;

    for (int c = 0; c < 8; c++) {
        const int k0 = c * 128;
        __syncthreads();
#pragma unroll
        for (int it = 0; it < 16; it++) {
            int idx = tid + it * 256;
            int buf = idx >> 11, rc = idx & 2047;
            int row = rc >> 4, q = rc & 15;
            const __nv_bfloat16* src = buf ? g_Alo : g_Ahi;
            uint32_t dst = SWZ256(row * 256 + q * 16);
            *(uint4*)(smem + (buf ? ALs : AHs) + dst) =
                *(const uint4*)(src + (((size_t)bh) << 20) +
                                ((size_t)(j0 + row) << 10) + k0 + q * 8);
        }
#pragma unroll
        for (int it = 0; it < 8; it++) {
            int idx = tid + it * 256;
            int buf = idx >> 10, rc = idx & 1023;
            int d = rc >> 4, q = rc & 15;
            const __nv_bfloat16* src = buf ? g_vwtlo : g_vwthi;
            uint32_t dst = SWZ256(d * 256 + q * 16);
            *(uint4*)(smem + (buf ? VLs : VHs) + dst) =
                *(const uint4*)(src + ((size_t)bh * 64 + d) * 1024 + k0 + q * 8);
        }
        __syncthreads();
#pragma unroll
        for (int ks = 0; ks < 8; ks++) {
            uint32_t a_h[4], a_l[4];
            uint32_t aoff = SWZ256((wid * 16 + (lane & 15)) * 256 +
                                   (ks * 2 + (lane >> 4)) * 16);
            ldmx4(a_h, sbase + AHs + aoff);
            ldmx4(a_l, sbase + ALs + aoff);
#pragma unroll
            for (int np = 0; np < 4; np++) {
                uint32_t boff = SWZ256((np * 16 + (lane >> 4) * 8 + (lane & 7)) * 256 +
                                       (ks * 2 + ((lane >> 3) & 1)) * 16);
                uint32_t b_h[4], b_l[4];
                ldmx4(b_h, sbase + VHs + boff);
                ldmx4(b_l, sbase + VLs + boff);
                mma16816(facc[np * 2 + 0], a_h, b_h);
                mma16816(facc[np * 2 + 0], a_h, b_l);
                mma16816(facc[np * 2 + 0], a_l, b_h);
                mma16816(facc[np * 2 + 1], a_h, b_h + 2);
                mma16816(facc[np * 2 + 1], a_h, b_l + 2);
                mma16816(facc[np * 2 + 1], a_l, b_h + 2);
            }
        }
    }
    const int b = bh / Hh, h = bh % Hh;
#pragma unroll
    for (int nt = 0; nt < 8; nt++) {
        int d = nt * 8 + (lane & 3) * 2;
#pragma unroll
        for (int half = 0; half < 2; half++) {
            int s = j0 + wid * 16 + (lane >> 2) + half * 8;
            size_t o = ((size_t)(b * 1024 + s)) * 768 + h * 64 + d;
            g_attn[o]     += facc[nt][half * 2 + 0];
            g_attn[o + 1] += facc[nt][half * 2 + 1];
        }
    }
}

// ---------------------------------------------------------------------------
extern "C" void kernel_launch(void* const* d_in, const int* in_sizes, int n_in,
                              void* d_out, int out_size) {
    const float* q     = (const float*)d_in[0];
    const float* k     = (const float*)d_in[1];
    const float* v     = (const float*)d_in[2];
    const float* amask = (const float*)d_in[3];
    const float* pb    = (const float*)d_in[4];
    const int*   vmask = (const int*)  d_in[5];
    const float* Wq    = (const float*)d_in[6];
    const float* bq    = (const float*)d_in[7];
    const float* Wk    = (const float*)d_in[8];
    const float* bk    = (const float*)d_in[9];
    const float* Wv    = (const float*)d_in[10];
    const float* bv    = (const float*)d_in[11];
    const float* Wo    = (const float*)d_in[12];
    const float* bo    = (const float*)d_in[13];
    float* out = (float*)d_out;

    const int SM_GEMM = 69632, SM_QK = 65536, SM_FUSED = 123392;
    const int SM_APB = 65536, SM_AV = 98304;
    static bool attr_done = false;
    if (!attr_done) {
        cudaFuncSetAttribute(gemm_mma_kernel, cudaFuncAttributeMaxDynamicSharedMemorySize, SM_GEMM);
        cudaFuncSetAttribute(qk_mma_kernel, cudaFuncAttributeMaxDynamicSharedMemorySize, SM_QK);
        cudaFuncSetAttribute(fused_pbq_sm_kernel, cudaFuncAttributeMaxDynamicSharedMemorySize, SM_FUSED);
        cudaFuncSetAttribute(apb_mma_kernel, cudaFuncAttributeMaxDynamicSharedMemorySize, SM_APB);
        cudaFuncSetAttribute(av_mma_kernel, cudaFuncAttributeMaxDynamicSharedMemorySize, SM_AV);
        attr_done = true;
    }

    const int n4 = 4096 * 768 / 4;
    conv_split_kernel<<<n4 / 256, 256>>>(q, 0, n4);
    conv_split_kernel<<<n4 / 256, 256>>>(k, 1, n4);
    conv_split_kernel<<<n4 / 256, 256>>>(v, 2, n4);
    dim3 tthr(32, 32), tgrd(24, 24);
    transpose_conv_kernel<<<tgrd, tthr>>>(Wq, 0);
    transpose_conv_kernel<<<tgrd, tthr>>>(Wk, 1);
    transpose_conv_kernel<<<tgrd, tthr>>>(Wv, 2);
    transpose_conv_kernel<<<tgrd, tthr>>>(Wo, 3);

    gemm_mma_kernel<<<dim3(6, 32, 3), 256, SM_GEMM>>>(bq, bk, bv, nullptr, 0);
    qk_mma_kernel<<<dim3(8, 8, 48), 256, SM_QK>>>();
    fused_pbq_sm_kernel<<<dim3(3, 1024), 256, SM_FUSED>>>(pb, amask, vmask);
    apb_mma_kernel<<<1024, 256, SM_APB>>>(pb);
    av_mma_kernel<<<dim3(8, 48), 256, SM_AV>>>();
    conv_split_kernel<<<n4 / 256, 256>>>(nullptr, 0, n4);
    gemm_mma_kernel<<<dim3(6, 32, 1), 256, SM_GEMM>>>(bo, nullptr, nullptr, out, 1);
}

// round 6
// speedup vs baseline: 2.0311x; 1.3411x over previous
#include <cuda_runtime.h>
#include <cuda_bf16.h>
#include <cstdint>

// ---------------------------------------------------------------------------
// NEZHA-style MHA, fully HMMA (mma.sync bf16 hi/lo 3-product; pb single bf16
// pre-converted). B=4, S=1024, H=12, DK=DV=64, DM=768.
// ---------------------------------------------------------------------------

#define S 1024
#define Hh 12
#define BH 48
#define NEGV (-1e12f)

// ---------------- scratch -----------------------------------------------------
__device__ float g_attn[(size_t)4 * S * 768];
__device__ float g_scores[(size_t)BH * S * S];     // 201 MB

__device__ __align__(16) __nv_bfloat16 g_xhi[(size_t)3 * 4096 * 768];
__device__ __align__(16) __nv_bfloat16 g_xlo[(size_t)3 * 4096 * 768];
__device__ __align__(16) __nv_bfloat16 g_wthi[(size_t)4 * 768 * 768];
__device__ __align__(16) __nv_bfloat16 g_wtlo[(size_t)4 * 768 * 768];
__device__ __align__(16) __nv_bfloat16 g_qhi[(size_t)BH * S * 64];
__device__ __align__(16) __nv_bfloat16 g_qlo[(size_t)BH * S * 64];
__device__ __align__(16) __nv_bfloat16 g_khi[(size_t)BH * S * 64];
__device__ __align__(16) __nv_bfloat16 g_klo[(size_t)BH * S * 64];
__device__ __align__(16) __nv_bfloat16 g_vwthi[(size_t)BH * 64 * S];  // [bh][d][s]
__device__ __align__(16) __nv_bfloat16 g_vwtlo[(size_t)BH * 64 * S];
__device__ __align__(16) __nv_bfloat16 g_Ahi[(size_t)BH * S * S];    // 100 MB
__device__ __align__(16) __nv_bfloat16 g_Alo[(size_t)BH * S * S];
__device__ __align__(16) __nv_bfloat16 g_pbh [(size_t)S * S * 64];   // [j][k][d] 128MB
__device__ __align__(16) __nv_bfloat16 g_pbth[(size_t)S * 64 * S];   // [j][d][k] 128MB

// ---------------- helpers -----------------------------------------------------
__device__ __forceinline__ uint32_t smem_to_u32(const void* p) {
    uint32_t a;
    asm("{ .reg .u64 t; cvta.to.shared.u64 t, %1; cvt.u32.u64 %0, t; }"
        : "=r"(a) : "l"(p));
    return a;
}
#define SWZ(o)    ((uint32_t)(o) ^ ((((uint32_t)(o)) >> 3) & 0x70))
#define SWZ256(o) ((uint32_t)(o) ^ ((((uint32_t)(o)) >> 4) & 0x70))

__device__ __forceinline__ void ldmx4(uint32_t* r, uint32_t a) {
    asm volatile("ldmatrix.sync.aligned.m8n8.x4.shared.b16 {%0,%1,%2,%3}, [%4];"
                 : "=r"(r[0]), "=r"(r[1]), "=r"(r[2]), "=r"(r[3]) : "r"(a));
}
__device__ __forceinline__ void mma16816(float* c, const uint32_t* a,
                                         const uint32_t* b) {
    asm volatile(
        "mma.sync.aligned.m16n8k16.row.col.f32.bf16.bf16.f32 "
        "{%0,%1,%2,%3},{%4,%5,%6,%7},{%8,%9},{%0,%1,%2,%3};"
        : "+f"(c[0]), "+f"(c[1]), "+f"(c[2]), "+f"(c[3])
        : "r"(a[0]), "r"(a[1]), "r"(a[2]), "r"(a[3]), "r"(b[0]), "r"(b[1]));
}
__device__ __forceinline__ uint32_t bfpack(__nv_bfloat16 a, __nv_bfloat16 b) {
    __nv_bfloat162 t(a, b);
    return *(uint32_t*)&t;
}
__device__ __forceinline__ void split4(float4 v, uint2& hi, uint2& lo) {
    __nv_bfloat16 h0 = __float2bfloat16(v.x), h1 = __float2bfloat16(v.y),
                  h2 = __float2bfloat16(v.z), h3 = __float2bfloat16(v.w);
    hi.x = bfpack(h0, h1); hi.y = bfpack(h2, h3);
    lo.x = bfpack(__float2bfloat16(v.x - __bfloat162float(h0)),
                  __float2bfloat16(v.y - __bfloat162float(h1)));
    lo.y = bfpack(__float2bfloat16(v.z - __bfloat162float(h2)),
                  __float2bfloat16(v.w - __bfloat162float(h3)));
}

// ---------------- conversion kernels ------------------------------------------
__global__ void conv_split_kernel(const float* __restrict__ src, int slot, int n4) {
    int i = blockIdx.x * blockDim.x + threadIdx.x;
    if (i >= n4) return;
    const float* s = src ? src : g_attn;
    float4 v = ((const float4*)s)[i];
    uint2 h, l; split4(v, h, l);
    *(uint2*)(g_xhi + (size_t)slot * 4096 * 768 + (size_t)i * 4) = h;
    *(uint2*)(g_xlo + (size_t)slot * 4096 * 768 + (size_t)i * 4) = l;
}

__global__ void transpose_conv_kernel(const float* __restrict__ W, int slot) {
    __shared__ float t[32][33];
    int tx = threadIdx.x, ty = threadIdx.y;
    int k = blockIdx.y * 32 + ty, n = blockIdx.x * 32 + tx;
    t[ty][tx] = W[(size_t)k * 768 + n];
    __syncthreads();
    int n2 = blockIdx.x * 32 + ty, k2 = blockIdx.y * 32 + tx;
    float v = t[tx][ty];
    __nv_bfloat16 h = __float2bfloat16(v);
    size_t off = (size_t)slot * 768 * 768 + (size_t)n2 * 768 + k2;
    g_wthi[off] = h;
    g_wtlo[off] = __float2bfloat16(v - __bfloat162float(h));
}

// pb fp32 -> bf16: natural [j][k][64] and transposed [j][64][k]. grid (8, 1024).
__global__ __launch_bounds__(256) void pbconv_kernel(const float* __restrict__ pb) {
    __shared__ __align__(16) __nv_bfloat16 T[64][136];
    const int c = blockIdx.x, j = blockIdx.y, tid = threadIdx.x;
    const int k0 = c * 128;
#pragma unroll
    for (int it = 0; it < 8; it++) {
        int idx = tid + it * 256;          // 2048 = 128 k x 16 d-granules
        int kk = idx >> 4, q4 = idx & 15;
        size_t off = ((size_t)j * 1024 + k0 + kk) * 64 + q4 * 4;
        float4 v = *(const float4*)(pb + off);
        __nv_bfloat16 h0 = __float2bfloat16(v.x), h1 = __float2bfloat16(v.y),
                      h2 = __float2bfloat16(v.z), h3 = __float2bfloat16(v.w);
        uint2 pk; pk.x = bfpack(h0, h1); pk.y = bfpack(h2, h3);
        *(uint2*)(g_pbh + off) = pk;
        int d = q4 * 4;
        T[d + 0][kk] = h0; T[d + 1][kk] = h1;
        T[d + 2][kk] = h2; T[d + 3][kk] = h3;
    }
    __syncthreads();
#pragma unroll
    for (int it = 0; it < 4; it++) {
        int idx = tid + it * 256;          // 1024 = 64 d x 16 k-granules
        int d = idx >> 4, g = idx & 15;
        *(uint4*)(g_pbth + ((size_t)j * 64 + d) * 1024 + k0 + g * 8) =
            *(uint4*)&T[d][g * 8];
    }
}

// ---------------- HMMA dense GEMM ---------------------------------------------
// mode 0: QKV (z = 0/1/2); z==2 writes vw^T hi/lo. mode 1: output projection.
__global__ __launch_bounds__(256) void gemm_mma_kernel(
    const float* __restrict__ b0, const float* __restrict__ b1,
    const float* __restrict__ b2, float* __restrict__ yout, int mode)
{
    extern __shared__ __align__(128) char smem[];
    const uint32_t AHo = 0, ALo = 16384, BHo = 32768, BLo = 49152;
    const uint32_t sbase = smem_to_u32(smem);
    const int tid = threadIdx.x, wid = tid >> 5, lane = tid & 31;
    const int z = blockIdx.z;
    const int bm = blockIdx.y * 128, bn = blockIdx.x * 128;
    const int xsel = (mode == 0) ? z : 0;
    const int wsel = (mode == 0) ? z : 3;
    const __nv_bfloat16* xh = g_xhi + (size_t)xsel * 4096 * 768;
    const __nv_bfloat16* xl = g_xlo + (size_t)xsel * 4096 * 768;
    const __nv_bfloat16* wh = g_wthi + (size_t)wsel * 768 * 768;
    const __nv_bfloat16* wl = g_wtlo + (size_t)wsel * 768 * 768;
    const float* bias = (mode == 1) ? b0 : (z == 0 ? b0 : (z == 1 ? b1 : b2));

    const int wm = (wid >> 1) * 32, wn = (wid & 1) * 64;
    float acc[2][8][4];
#pragma unroll
    for (int a = 0; a < 2; a++)
#pragma unroll
        for (int b = 0; b < 8; b++)
#pragma unroll
            for (int c = 0; c < 4; c++) acc[a][b][c] = 0.f;

    for (int st = 0; st < 12; st++) {
        const int k0 = st * 64;
        __syncthreads();
#pragma unroll
        for (int i = 0; i < 4; i++) {
            int idx = tid + i * 256;
            int row = idx >> 3, q = idx & 7;
            uint32_t dst = SWZ(row * 128 + q * 16);
            size_t sa = (size_t)(bm + row) * 768 + k0 + q * 8;
            size_t sb = (size_t)(bn + row) * 768 + k0 + q * 8;
            *(uint4*)(smem + AHo + dst) = *(const uint4*)(xh + sa);
            *(uint4*)(smem + ALo + dst) = *(const uint4*)(xl + sa);
            *(uint4*)(smem + BHo + dst) = *(const uint4*)(wh + sb);
            *(uint4*)(smem + BLo + dst) = *(const uint4*)(wl + sb);
        }
        __syncthreads();
#pragma unroll
        for (int kk = 0; kk < 4; kk++) {
            uint32_t ah[2][4], al[2][4];
            uint32_t aoff = SWZ((wm + (lane & 15)) * 128 + (kk * 2 + (lane >> 4)) * 16);
            ldmx4(ah[0], sbase + AHo + aoff);
            ldmx4(ah[1], sbase + AHo + aoff + 2048);
            ldmx4(al[0], sbase + ALo + aoff);
            ldmx4(al[1], sbase + ALo + aoff + 2048);
            uint32_t boff = SWZ((wn + (lane >> 4) * 8 + (lane & 7)) * 128 +
                                (kk * 2 + ((lane >> 3) & 1)) * 16);
#pragma unroll
            for (int ntp = 0; ntp < 4; ntp++) {
                uint32_t bh4[4], bl4[4];
                ldmx4(bh4, sbase + BHo + boff + ntp * 2048);
                ldmx4(bl4, sbase + BLo + boff + ntp * 2048);
#pragma unroll
                for (int mt = 0; mt < 2; mt++) {
                    mma16816(acc[mt][ntp * 2 + 0], ah[mt], bh4);
                    mma16816(acc[mt][ntp * 2 + 0], ah[mt], bl4);
                    mma16816(acc[mt][ntp * 2 + 0], al[mt], bh4);
                    mma16816(acc[mt][ntp * 2 + 1], ah[mt], bh4 + 2);
                    mma16816(acc[mt][ntp * 2 + 1], ah[mt], bl4 + 2);
                    mma16816(acc[mt][ntp * 2 + 1], al[mt], bh4 + 2);
                }
            }
        }
    }

    if (mode == 0 && z == 2) {
        __syncthreads();
        __nv_bfloat16* Th = (__nv_bfloat16*)smem;               // [128][136]
        __nv_bfloat16* Tl = (__nv_bfloat16*)(smem + 34816);
#pragma unroll
        for (int mt = 0; mt < 2; mt++) {
#pragma unroll
            for (int nt = 0; nt < 8; nt++) {
                int cl = wn + nt * 8 + (lane & 3) * 2;
                float bx = bias[bn + cl], by = bias[bn + cl + 1];
#pragma unroll
                for (int half = 0; half < 2; half++) {
                    int rl = wm + mt * 16 + (lane >> 2) + half * 8;
                    float v0 = acc[mt][nt][half * 2 + 0] + bx;
                    float v1 = acc[mt][nt][half * 2 + 1] + by;
                    __nv_bfloat16 h0 = __float2bfloat16(v0);
                    __nv_bfloat16 h1 = __float2bfloat16(v1);
                    Th[cl * 136 + rl] = h0;
                    Tl[cl * 136 + rl] = __float2bfloat16(v0 - __bfloat162float(h0));
                    Th[(cl + 1) * 136 + rl] = h1;
                    Tl[(cl + 1) * 136 + rl] = __float2bfloat16(v1 - __bfloat162float(h1));
                }
            }
        }
        __syncthreads();
        int b = bm >> 10, s0 = bm & 1023;
#pragma unroll
        for (int it = 0; it < 8; it++) {
            int g = tid + it * 256;
            int cl = g >> 4, q = g & 15;
            int cg = bn + cl, h = cg >> 6, d = cg & 63;
            size_t o = (((size_t)(b * Hh + h)) * 64 + d) * 1024 + s0 + q * 8;
            *(uint4*)(g_vwthi + o) = *(uint4*)&Th[cl * 136 + q * 8];
            *(uint4*)(g_vwtlo + o) = *(uint4*)&Tl[cl * 136 + q * 8];
        }
        return;
    }

#pragma unroll
    for (int mt = 0; mt < 2; mt++) {
#pragma unroll
        for (int nt = 0; nt < 8; nt++) {
            int col = bn + wn + nt * 8 + (lane & 3) * 2;
            float bx = bias[col], by = bias[col + 1];
#pragma unroll
            for (int half = 0; half < 2; half++) {
                int row = bm + wm + mt * 16 + (lane >> 2) + half * 8;
                float v0 = acc[mt][nt][half * 2 + 0] + bx;
                float v1 = acc[mt][nt][half * 2 + 1] + by;
                if (mode == 1) {
                    yout[(size_t)row * 768 + col]     = v0;
                    yout[(size_t)row * 768 + col + 1] = v1;
                } else {
                    int b = row >> 10, s = row & 1023;
                    int h = col >> 6, d = col & 63;
                    size_t base = ((size_t)(b * Hh + h) * S + s) * 64 + d;
                    __nv_bfloat16 h0 = __float2bfloat16(v0);
                    __nv_bfloat16 h1 = __float2bfloat16(v1);
                    if (z == 0) {
                        g_qhi[base] = h0; g_qhi[base + 1] = h1;
                        g_qlo[base]     = __float2bfloat16(v0 - __bfloat162float(h0));
                        g_qlo[base + 1] = __float2bfloat16(v1 - __bfloat162float(h1));
                    } else {
                        g_khi[base] = h0; g_khi[base + 1] = h1;
                        g_klo[base]     = __float2bfloat16(v0 - __bfloat162float(h0));
                        g_klo[base + 1] = __float2bfloat16(v1 - __bfloat162float(h1));
                    }
                }
            }
        }
    }
}

// ---------------- HMMA QK^T ----------------------------------------------------
__global__ __launch_bounds__(256) void qk_mma_kernel() {
    extern __shared__ __align__(128) char smem[];
    const uint32_t AHo = 0, ALo = 16384, BHo = 32768, BLo = 49152;
    const uint32_t sbase = smem_to_u32(smem);
    const int tid = threadIdx.x, wid = tid >> 5, lane = tid & 31;
    const int bh = blockIdx.z;
    const int bj = blockIdx.y * 128, bk = blockIdx.x * 128;
    const int wm = (wid >> 1) * 32, wn = (wid & 1) * 64;

    const size_t qb = ((size_t)bh * S + bj) * 64;
    const size_t kb = ((size_t)bh * S + bk) * 64;
#pragma unroll
    for (int i = 0; i < 4; i++) {
        int idx = tid + i * 256;
        int row = idx >> 3, q = idx & 7;
        uint32_t dst = SWZ(row * 128 + q * 16);
        size_t sa = qb + (size_t)row * 64 + q * 8;
        size_t sb = kb + (size_t)row * 64 + q * 8;
        *(uint4*)(smem + AHo + dst) = *(const uint4*)(g_qhi + sa);
        *(uint4*)(smem + ALo + dst) = *(const uint4*)(g_qlo + sa);
        *(uint4*)(smem + BHo + dst) = *(const uint4*)(g_khi + sb);
        *(uint4*)(smem + BLo + dst) = *(const uint4*)(g_klo + sb);
    }
    __syncthreads();

    float acc[2][8][4];
#pragma unroll
    for (int a = 0; a < 2; a++)
#pragma unroll
        for (int b = 0; b < 8; b++)
#pragma unroll
            for (int c = 0; c < 4; c++) acc[a][b][c] = 0.f;

#pragma unroll
    for (int kk = 0; kk < 4; kk++) {
        uint32_t ah[2][4], al[2][4];
        uint32_t aoff = SWZ((wm + (lane & 15)) * 128 + (kk * 2 + (lane >> 4)) * 16);
        ldmx4(ah[0], sbase + AHo + aoff);
        ldmx4(ah[1], sbase + AHo + aoff + 2048);
        ldmx4(al[0], sbase + ALo + aoff);
        ldmx4(al[1], sbase + ALo + aoff + 2048);
        uint32_t boff = SWZ((wn + (lane >> 4) * 8 + (lane & 7)) * 128 +
                            (kk * 2 + ((lane >> 3) & 1)) * 16);
#pragma unroll
        for (int ntp = 0; ntp < 4; ntp++) {
            uint32_t bh4[4], bl4[4];
            ldmx4(bh4, sbase + BHo + boff + ntp * 2048);
            ldmx4(bl4, sbase + BLo + boff + ntp * 2048);
#pragma unroll
            for (int mt = 0; mt < 2; mt++) {
                mma16816(acc[mt][ntp * 2 + 0], ah[mt], bh4);
                mma16816(acc[mt][ntp * 2 + 0], ah[mt], bl4);
                mma16816(acc[mt][ntp * 2 + 0], al[mt], bh4);
                mma16816(acc[mt][ntp * 2 + 1], ah[mt], bh4 + 2);
                mma16816(acc[mt][ntp * 2 + 1], ah[mt], bl4 + 2);
                mma16816(acc[mt][ntp * 2 + 1], al[mt], bh4 + 2);
            }
        }
    }

#pragma unroll
    for (int mt = 0; mt < 2; mt++) {
#pragma unroll
        for (int nt = 0; nt < 8; nt++) {
            int col = bk + wn + nt * 8 + (lane & 3) * 2;
#pragma unroll
            for (int half = 0; half < 2; half++) {
                int row = bj + wm + mt * 16 + (lane >> 2) + half * 8;
                size_t idx = ((size_t)bh << 20) + ((size_t)row << 10) + col;
                g_scores[idx]     = acc[mt][nt][half * 2 + 0];
                g_scores[idx + 1] = acc[mt][nt][half * 2 + 1];
            }
        }
    }
}

// ---------------------------------------------------------------------------
// Fused: scores += qw·pb (2-MMA, pb bf16), scale+mask+softmax, A -> hi/lo.
// Grid (3, 1024), 256 threads, smem 107008 (2 blocks/SM).
// ---------------------------------------------------------------------------
__global__ __launch_bounds__(256) void fused_pbq_sm_kernel(
    const float* __restrict__ amask, const int* __restrict__ vmask)
{
    extern __shared__ __align__(128) char smem[];
    float* Sf = (float*)smem;                     // [16][1032] fp32 = 66048
    const uint32_t PBH = 66048;                   // [128][64] bf16, 16KB
    const uint32_t QHo = 82432, QLo = 84480;      // [16][64] bf16
    float*  AM = (float*)(smem + 86528);          // [1024]
    float2* MV = (float2*)(smem + 90624);         // [2][1024] {m, neg}
    const uint32_t sbase = smem_to_u32(smem);
    const int tid = threadIdx.x, wid = tid >> 5, lane = tid & 31;
    const int t = blockIdx.x, j = blockIdx.y;
    const int bh0 = t * 16, bmin = bh0 / Hh;

#pragma unroll
    for (int it = 0; it < 16; it++) {
        int idx = tid + it * 256;
        int row = idx >> 8, k4 = idx & 255;
        *(float4*)&Sf[row * 1032 + k4 * 4] =
            *(const float4*)(g_scores + (((size_t)(bh0 + row)) << 20) +
                             ((size_t)j << 10) + k4 * 4);
    }
    if (tid < 128) {
        int r = tid >> 3, q = tid & 7;
        uint32_t dst = SWZ(r * 128 + q * 16);
        size_t src = ((size_t)(bh0 + r) * 1024 + j) * 64 + q * 8;
        *(uint4*)(smem + QHo + dst) = *(const uint4*)(g_qhi + src);
        *(uint4*)(smem + QLo + dst) = *(const uint4*)(g_qlo + src);
    }
    *(float4*)&AM[tid * 4] = *(const float4*)(amask + (size_t)j * 1024 + tid * 4);
#pragma unroll
    for (int r2 = 0; r2 < 2; r2++) {
        int4 m = *(const int4*)(vmask + (size_t)(bmin + r2) * 1024 + tid * 4);
        MV[r2 * 1024 + tid * 4 + 0] = make_float2(m.x ? 1.f : 0.f, m.x ? 0.f : NEGV);
        MV[r2 * 1024 + tid * 4 + 1] = make_float2(m.y ? 1.f : 0.f, m.y ? 0.f : NEGV);
        MV[r2 * 1024 + tid * 4 + 2] = make_float2(m.z ? 1.f : 0.f, m.z ? 0.f : NEGV);
        MV[r2 * 1024 + tid * 4 + 3] = make_float2(m.w ? 1.f : 0.f, m.w ? 0.f : NEGV);
    }
    __syncthreads();

    uint32_t ah[4][4], al[4][4];
#pragma unroll
    for (int ks = 0; ks < 4; ks++) {
        uint32_t aoff = SWZ((lane & 15) * 128 + (ks * 2 + (lane >> 4)) * 16);
        ldmx4(ah[ks], sbase + QHo + aoff);
        ldmx4(al[ks], sbase + QLo + aoff);
    }

    for (int c = 0; c < 8; c++) {
        const int k0 = c * 128;
        __syncthreads();
#pragma unroll
        for (int it = 0; it < 4; it++) {
            int idx = tid + it * 256;         // 1024 x 16B = 16KB
            int kk = idx >> 3, q = idx & 7;
            uint32_t dst = SWZ(kk * 128 + q * 16);
            *(uint4*)(smem + PBH + dst) =
                *(const uint4*)(g_pbh + ((size_t)j * 1024 + k0 + kk) * 64 + q * 8);
        }
        __syncthreads();
        float frag[2][4] = {{0.f, 0.f, 0.f, 0.f}, {0.f, 0.f, 0.f, 0.f}};
#pragma unroll
        for (int ks = 0; ks < 4; ks++) {
            uint32_t boff = SWZ((wid * 16 + (lane >> 4) * 8 + (lane & 7)) * 128 +
                                (ks * 2 + ((lane >> 3) & 1)) * 16);
            uint32_t bh4[4];
            ldmx4(bh4, sbase + PBH + boff);
            mma16816(frag[0], ah[ks], bh4);
            mma16816(frag[0], al[ks], bh4);
            mma16816(frag[1], ah[ks], bh4 + 2);
            mma16816(frag[1], al[ks], bh4 + 2);
        }
        int r0 = lane >> 2, c0 = (lane & 3) * 2;
#pragma unroll
        for (int nt = 0; nt < 2; nt++)
#pragma unroll
            for (int e = 0; e < 4; e++) {
                int row = r0 + (e >> 1) * 8;
                int col = k0 + wid * 16 + nt * 8 + c0 + (e & 1);
                Sf[row * 1032 + col] += frag[nt][e];
            }
    }
    __syncthreads();

#pragma unroll
    for (int rr = 0; rr < 2; rr++) {
        int row = wid * 2 + rr;
        int bsel = (bh0 + row) / Hh - bmin;
        float x[32];
        float mx = -3.4e38f;
#pragma unroll
        for (int i = 0; i < 32; i++) {
            int k = lane + i * 32;
            float2 mv = MV[bsel * 1024 + k];
            float val = fmaf(Sf[row * 1032 + k], 0.125f, AM[k]);
            x[i] = fmaf(val, mv.x, mv.y);
            mx = fmaxf(mx, x[i]);
        }
#pragma unroll
        for (int o = 16; o > 0; o >>= 1) mx = fmaxf(mx, __shfl_xor_sync(~0u, mx, o));
        float sum = 0.f;
#pragma unroll
        for (int i = 0; i < 32; i++) { x[i] = __expf(x[i] - mx); sum += x[i]; }
#pragma unroll
        for (int o = 16; o > 0; o >>= 1) sum += __shfl_xor_sync(~0u, sum, o);
        float inv = 1.f / sum;
#pragma unroll
        for (int i = 0; i < 32; i++) Sf[row * 1032 + lane + i * 32] = x[i] * inv;
    }
    __syncthreads();

    const int row = tid >> 4, kb = (tid & 15) * 64;
    const size_t obase = (((size_t)(bh0 + row)) << 20) + ((size_t)j << 10);
#pragma unroll
    for (int g = 0; g < 8; g++) {
        int k = kb + g * 8;
        float4 a = *(float4*)&Sf[row * 1032 + k];
        float4 b = *(float4*)&Sf[row * 1032 + k + 4];
        uint2 h0, l0, h1, l1;
        split4(a, h0, l0); split4(b, h1, l1);
        *(uint4*)(g_Ahi + obase + k) = make_uint4(h0.x, h0.y, h1.x, h1.y);
        *(uint4*)(g_Alo + obase + k) = make_uint4(l0.x, l0.y, l1.x, l1.y);
    }
}

// ---------------------------------------------------------------------------
// apb: attn[b][j][h][d] = sum_k A[bh][j][k] * pb[j][k][d]. Grid 1024, smem 48KB.
// ---------------------------------------------------------------------------
__global__ __launch_bounds__(256) void apb_mma_kernel() {
    extern __shared__ __align__(128) char smem[];
    const uint32_t AHs = 0, ALs = 16384, PTH = 32768;
    const uint32_t sbase = smem_to_u32(smem);
    const int tid = threadIdx.x, wid = tid >> 5, lane = tid & 31;
    const int j = blockIdx.x;
    const int mt = wid >> 1, nb = (wid & 1) * 32;

    float facc[4][4];
#pragma unroll
    for (int a = 0; a < 4; a++)
#pragma unroll
        for (int b = 0; b < 4; b++) facc[a][b] = 0.f;

    for (int c = 0; c < 8; c++) {
        const int k0 = c * 128;
        __syncthreads();
#pragma unroll
        for (int it = 0; it < 8; it++) {
            int idx = tid + it * 256;
            int buf = idx >> 10, rc = idx & 1023;
            int row = rc >> 4, q = rc & 15;
            uint32_t dst = SWZ256(row * 256 + q * 16);
            uint4 v = make_uint4(0, 0, 0, 0);
            if (row < 48) {
                const __nv_bfloat16* src = buf ? g_Alo : g_Ahi;
                v = *(const uint4*)(src + (((size_t)row) << 20) +
                                    ((size_t)j << 10) + k0 + q * 8);
            }
            *(uint4*)(smem + (buf ? ALs : AHs) + dst) = v;
        }
#pragma unroll
        for (int it = 0; it < 4; it++) {
            int idx = tid + it * 256;        // 1024 = 64 d x 16 granules
            int d = idx >> 4, g = idx & 15;
            uint32_t dst = SWZ256(d * 256 + g * 16);
            *(uint4*)(smem + PTH + dst) =
                *(const uint4*)(g_pbth + ((size_t)j * 64 + d) * 1024 + k0 + g * 8);
        }
        __syncthreads();
#pragma unroll
        for (int ks = 0; ks < 8; ks++) {
            uint32_t a_h[4], a_l[4];
            uint32_t aoff = SWZ256((mt * 16 + (lane & 15)) * 256 +
                                   (ks * 2 + (lane >> 4)) * 16);
            ldmx4(a_h, sbase + AHs + aoff);
            ldmx4(a_l, sbase + ALs + aoff);
#pragma unroll
            for (int np = 0; np < 2; np++) {
                uint32_t boff = SWZ256((nb + np * 16 + (lane >> 4) * 8 + (lane & 7)) * 256 +
                                       (ks * 2 + ((lane >> 3) & 1)) * 16);
                uint32_t b_h[4];
                ldmx4(b_h, sbase + PTH + boff);
                mma16816(facc[np * 2 + 0], a_h, b_h);
                mma16816(facc[np * 2 + 0], a_l, b_h);
                mma16816(facc[np * 2 + 1], a_h, b_h + 2);
                mma16816(facc[np * 2 + 1], a_l, b_h + 2);
            }
        }
    }
#pragma unroll
    for (int nt = 0; nt < 4; nt++) {
        int d = nb + nt * 8 + (lane & 3) * 2;
#pragma unroll
        for (int half = 0; half < 2; half++) {
            int bh = mt * 16 + (lane >> 2) + half * 8;
            if (bh < 48) {
                int b = bh / Hh, h = bh % Hh;
                size_t o = ((size_t)(b * 1024 + j)) * 768 + h * 64 + d;
                g_attn[o]     = facc[nt][half * 2 + 0];
                g_attn[o + 1] = facc[nt][half * 2 + 1];
            }
        }
    }
}

// ---------------------------------------------------------------------------
// av: attn += A·vw. Grid (8, 48). M=128, N=64, K=1024.
// ---------------------------------------------------------------------------
__global__ __launch_bounds__(256) void av_mma_kernel() {
    extern __shared__ __align__(128) char smem[];
    const uint32_t AHs = 0, ALs = 32768, VHs = 65536, VLs = 81920;
    const uint32_t sbase = smem_to_u32(smem);
    const int tid = threadIdx.x, wid = tid >> 5, lane = tid & 31;
    const int bh = blockIdx.y, j0 = blockIdx.x * 128;

    float facc[8][4];
#pragma unroll
    for (int a = 0; a < 8; a++)
#pragma unroll
        for (int b = 0; b < 4; b++) facc[a][b] = 0.f;

    for (int c = 0; c < 8; c++) {
        const int k0 = c * 128;
        __syncthreads();
#pragma unroll
        for (int it = 0; it < 16; it++) {
            int idx = tid + it * 256;
            int buf = idx >> 11, rc = idx & 2047;
            int row = rc >> 4, q = rc & 15;
            const __nv_bfloat16* src = buf ? g_Alo : g_Ahi;
            uint32_t dst = SWZ256(row * 256 + q * 16);
            *(uint4*)(smem + (buf ? ALs : AHs) + dst) =
                *(const uint4*)(src + (((size_t)bh) << 20) +
                                ((size_t)(j0 + row) << 10) + k0 + q * 8);
        }
#pragma unroll
        for (int it = 0; it < 8; it++) {
            int idx = tid + it * 256;
            int buf = idx >> 10, rc = idx & 1023;
            int d = rc >> 4, q = rc & 15;
            const __nv_bfloat16* src = buf ? g_vwtlo : g_vwthi;
            uint32_t dst = SWZ256(d * 256 + q * 16);
            *(uint4*)(smem + (buf ? VLs : VHs) + dst) =
                *(const uint4*)(src + ((size_t)bh * 64 + d) * 1024 + k0 + q * 8);
        }
        __syncthreads();
#pragma unroll
        for (int ks = 0; ks < 8; ks++) {
            uint32_t a_h[4], a_l[4];
            uint32_t aoff = SWZ256((wid * 16 + (lane & 15)) * 256 +
                                   (ks * 2 + (lane >> 4)) * 16);
            ldmx4(a_h, sbase + AHs + aoff);
            ldmx4(a_l, sbase + ALs + aoff);
#pragma unroll
            for (int np = 0; np < 4; np++) {
                uint32_t boff = SWZ256((np * 16 + (lane >> 4) * 8 + (lane & 7)) * 256 +
                                       (ks * 2 + ((lane >> 3) & 1)) * 16);
                uint32_t b_h[4], b_l[4];
                ldmx4(b_h, sbase + VHs + boff);
                ldmx4(b_l, sbase + VLs + boff);
                mma16816(facc[np * 2 + 0], a_h, b_h);
                mma16816(facc[np * 2 + 0], a_h, b_l);
                mma16816(facc[np * 2 + 0], a_l, b_h);
                mma16816(facc[np * 2 + 1], a_h, b_h + 2);
                mma16816(facc[np * 2 + 1], a_h, b_l + 2);
                mma16816(facc[np * 2 + 1], a_l, b_h + 2);
            }
        }
    }
    const int b = bh / Hh, h = bh % Hh;
#pragma unroll
    for (int nt = 0; nt < 8; nt++) {
        int d = nt * 8 + (lane & 3) * 2;
#pragma unroll
        for (int half = 0; half < 2; half++) {
            int s = j0 + wid * 16 + (lane >> 2) + half * 8;
            size_t o = ((size_t)(b * 1024 + s)) * 768 + h * 64 + d;
            g_attn[o]     += facc[nt][half * 2 + 0];
            g_attn[o + 1] += facc[nt][half * 2 + 1];
        }
    }
}

// ---------------------------------------------------------------------------
extern "C" void kernel_launch(void* const* d_in, const int* in_sizes, int n_in,
                              void* d_out, int out_size) {
    const float* q     = (const float*)d_in[0];
    const float* k     = (const float*)d_in[1];
    const float* v     = (const float*)d_in[2];
    const float* amask = (const float*)d_in[3];
    const float* pb    = (const float*)d_in[4];
    const int*   vmask = (const int*)  d_in[5];
    const float* Wq    = (const float*)d_in[6];
    const float* bq    = (const float*)d_in[7];
    const float* Wk    = (const float*)d_in[8];
    const float* bk    = (const float*)d_in[9];
    const float* Wv    = (const float*)d_in[10];
    const float* bv    = (const float*)d_in[11];
    const float* Wo    = (const float*)d_in[12];
    const float* bo    = (const float*)d_in[13];
    float* out = (float*)d_out;

    const int SM_GEMM = 69632, SM_QK = 65536, SM_FUSED = 107008;
    const int SM_APB = 49152, SM_AV = 98304;
    static bool attr_done = false;
    if (!attr_done) {
        cudaFuncSetAttribute(gemm_mma_kernel, cudaFuncAttributeMaxDynamicSharedMemorySize, SM_GEMM);
        cudaFuncSetAttribute(qk_mma_kernel, cudaFuncAttributeMaxDynamicSharedMemorySize, SM_QK);
        cudaFuncSetAttribute(fused_pbq_sm_kernel, cudaFuncAttributeMaxDynamicSharedMemorySize, SM_FUSED);
        cudaFuncSetAttribute(apb_mma_kernel, cudaFuncAttributeMaxDynamicSharedMemorySize, SM_APB);
        cudaFuncSetAttribute(av_mma_kernel, cudaFuncAttributeMaxDynamicSharedMemorySize, SM_AV);
        attr_done = true;
    }

    const int n4 = 4096 * 768 / 4;
    pbconv_kernel<<<dim3(8, 1024), 256>>>(pb);
    conv_split_kernel<<<n4 / 256, 256>>>(q, 0, n4);
    conv_split_kernel<<<n4 / 256, 256>>>(k, 1, n4);
    conv_split_kernel<<<n4 / 256, 256>>>(v, 2, n4);
    dim3 tthr(32, 32), tgrd(24, 24);
    transpose_conv_kernel<<<tgrd, tthr>>>(Wq, 0);
    transpose_conv_kernel<<<tgrd, tthr>>>(Wk, 1);
    transpose_conv_kernel<<<tgrd, tthr>>>(Wv, 2);
    transpose_conv_kernel<<<tgrd, tthr>>>(Wo, 3);

    gemm_mma_kernel<<<dim3(6, 32, 3), 256, SM_GEMM>>>(bq, bk, bv, nullptr, 0);
    qk_mma_kernel<<<dim3(8, 8, 48), 256, SM_QK>>>();
    fused_pbq_sm_kernel<<<dim3(3, 1024), 256, SM_FUSED>>>(amask, vmask);
    apb_mma_kernel<<<1024, 256, SM_APB>>>();
    av_mma_kernel<<<dim3(8, 48), 256, SM_AV>>>();
    conv_split_kernel<<<n4 / 256, 256>>>(nullptr, 0, n4);
    gemm_mma_kernel<<<dim3(6, 32, 1), 256, SM_GEMM>>>(bo, nullptr, nullptr, out, 1);
}

// round 8
// speedup vs baseline: 2.0573x; 1.0129x over previous
#include <cuda_runtime.h>
#include <cuda_bf16.h>
#include <cstdint>

// ---------------------------------------------------------------------------
// NEZHA-style MHA, fully HMMA (mma.sync bf16 hi/lo; pb single bf16).
// apb fused into the softmax kernel (phase C, trans-ldmatrix on pb tiles).
// B=4, S=1024, H=12, DK=DV=64, DM=768.
// ---------------------------------------------------------------------------

#define S 1024
#define Hh 12
#define BH 48
#define NEGV (-1e12f)

// ---------------- scratch -----------------------------------------------------
__device__ float g_attn[(size_t)4 * S * 768];
__device__ float g_scores[(size_t)BH * S * S];     // 201 MB

__device__ __align__(16) __nv_bfloat16 g_xhi[(size_t)3 * 4096 * 768];
__device__ __align__(16) __nv_bfloat16 g_xlo[(size_t)3 * 4096 * 768];
__device__ __align__(16) __nv_bfloat16 g_wthi[(size_t)4 * 768 * 768];
__device__ __align__(16) __nv_bfloat16 g_wtlo[(size_t)4 * 768 * 768];
__device__ __align__(16) __nv_bfloat16 g_qhi[(size_t)BH * S * 64];
__device__ __align__(16) __nv_bfloat16 g_qlo[(size_t)BH * S * 64];
__device__ __align__(16) __nv_bfloat16 g_khi[(size_t)BH * S * 64];
__device__ __align__(16) __nv_bfloat16 g_klo[(size_t)BH * S * 64];
__device__ __align__(16) __nv_bfloat16 g_vwthi[(size_t)BH * 64 * S];  // [bh][d][s]
__device__ __align__(16) __nv_bfloat16 g_vwtlo[(size_t)BH * 64 * S];
__device__ __align__(16) __nv_bfloat16 g_Ahi[(size_t)BH * S * S];    // 100 MB
__device__ __align__(16) __nv_bfloat16 g_Alo[(size_t)BH * S * S];
__device__ __align__(16) __nv_bfloat16 g_pbh [(size_t)S * S * 64];   // [j][k][d] 128MB

// ---------------- helpers -----------------------------------------------------
__device__ __forceinline__ uint32_t smem_to_u32(const void* p) {
    uint32_t a;
    asm("{ .reg .u64 t; cvta.to.shared.u64 t, %1; cvt.u32.u64 %0, t; }"
        : "=r"(a) : "l"(p));
    return a;
}
#define SWZ(o)    ((uint32_t)(o) ^ ((((uint32_t)(o)) >> 3) & 0x70))
#define SWZ256(o) ((uint32_t)(o) ^ ((((uint32_t)(o)) >> 4) & 0x70))

__device__ __forceinline__ void ldmx4(uint32_t* r, uint32_t a) {
    asm volatile("ldmatrix.sync.aligned.m8n8.x4.shared.b16 {%0,%1,%2,%3}, [%4];"
                 : "=r"(r[0]), "=r"(r[1]), "=r"(r[2]), "=r"(r[3]) : "r"(a));
}
__device__ __forceinline__ void ldmx2t(uint32_t* r, uint32_t a) {
    asm volatile("ldmatrix.sync.aligned.m8n8.x2.trans.shared.b16 {%0,%1}, [%2];"
                 : "=r"(r[0]), "=r"(r[1]) : "r"(a));
}
__device__ __forceinline__ void mma16816(float* c, const uint32_t* a,
                                         const uint32_t* b) {
    asm volatile(
        "mma.sync.aligned.m16n8k16.row.col.f32.bf16.bf16.f32 "
        "{%0,%1,%2,%3},{%4,%5,%6,%7},{%8,%9},{%0,%1,%2,%3};"
        : "+f"(c[0]), "+f"(c[1]), "+f"(c[2]), "+f"(c[3])
        : "r"(a[0]), "r"(a[1]), "r"(a[2]), "r"(a[3]), "r"(b[0]), "r"(b[1]));
}
__device__ __forceinline__ uint32_t bfpack(__nv_bfloat16 a, __nv_bfloat16 b) {
    __nv_bfloat162 t(a, b);
    return *(uint32_t*)&t;
}
__device__ __forceinline__ void split4(float4 v, uint2& hi, uint2& lo) {
    __nv_bfloat16 h0 = __float2bfloat16(v.x), h1 = __float2bfloat16(v.y),
                  h2 = __float2bfloat16(v.z), h3 = __float2bfloat16(v.w);
    hi.x = bfpack(h0, h1); hi.y = bfpack(h2, h3);
    lo.x = bfpack(__float2bfloat16(v.x - __bfloat162float(h0)),
                  __float2bfloat16(v.y - __bfloat162float(h1)));
    lo.y = bfpack(__float2bfloat16(v.z - __bfloat162float(h2)),
                  __float2bfloat16(v.w - __bfloat162float(h3)));
}

// ---------------- conversion kernels ------------------------------------------
__global__ void conv_split_kernel(const float* __restrict__ src, int slot, int n4) {
    int i = blockIdx.x * blockDim.x + threadIdx.x;
    if (i >= n4) return;
    const float* s = src ? src : g_attn;
    float4 v = ((const float4*)s)[i];
    uint2 h, l; split4(v, h, l);
    *(uint2*)(g_xhi + (size_t)slot * 4096 * 768 + (size_t)i * 4) = h;
    *(uint2*)(g_xlo + (size_t)slot * 4096 * 768 + (size_t)i * 4) = l;
}

__global__ void transpose_conv_kernel(const float* __restrict__ W, int slot) {
    __shared__ float t[32][33];
    int tx = threadIdx.x, ty = threadIdx.y;
    int k = blockIdx.y * 32 + ty, n = blockIdx.x * 32 + tx;
    t[ty][tx] = W[(size_t)k * 768 + n];
    __syncthreads();
    int n2 = blockIdx.x * 32 + ty, k2 = blockIdx.y * 32 + tx;
    float v = t[tx][ty];
    __nv_bfloat16 h = __float2bfloat16(v);
    size_t off = (size_t)slot * 768 * 768 + (size_t)n2 * 768 + k2;
    g_wthi[off] = h;
    g_wtlo[off] = __float2bfloat16(v - __bfloat162float(h));
}

// pb fp32 -> bf16 [j][k][d], flat elementwise.
__global__ __launch_bounds__(256) void pbconv_kernel(const float* __restrict__ pb, int n4) {
    int i = blockIdx.x * blockDim.x + threadIdx.x;
    if (i >= n4) return;
    float4 v = ((const float4*)pb)[i];
    uint2 pk;
    pk.x = bfpack(__float2bfloat16(v.x), __float2bfloat16(v.y));
    pk.y = bfpack(__float2bfloat16(v.z), __float2bfloat16(v.w));
    *(uint2*)(g_pbh + (size_t)i * 4) = pk;
}

// ---------------- HMMA dense GEMM ---------------------------------------------
__global__ __launch_bounds__(256) void gemm_mma_kernel(
    const float* __restrict__ b0, const float* __restrict__ b1,
    const float* __restrict__ b2, float* __restrict__ yout, int mode)
{
    extern __shared__ __align__(128) char smem[];
    const uint32_t AHo = 0, ALo = 16384, BHo = 32768, BLo = 49152;
    const uint32_t sbase = smem_to_u32(smem);
    const int tid = threadIdx.x, wid = tid >> 5, lane = tid & 31;
    const int z = blockIdx.z;
    const int bm = blockIdx.y * 128, bn = blockIdx.x * 128;
    const int xsel = (mode == 0) ? z : 0;
    const int wsel = (mode == 0) ? z : 3;
    const __nv_bfloat16* xh = g_xhi + (size_t)xsel * 4096 * 768;
    const __nv_bfloat16* xl = g_xlo + (size_t)xsel * 4096 * 768;
    const __nv_bfloat16* wh = g_wthi + (size_t)wsel * 768 * 768;
    const __nv_bfloat16* wl = g_wtlo + (size_t)wsel * 768 * 768;
    const float* bias = (mode == 1) ? b0 : (z == 0 ? b0 : (z == 1 ? b1 : b2));

    const int wm = (wid >> 1) * 32, wn = (wid & 1) * 64;
    float acc[2][8][4];
#pragma unroll
    for (int a = 0; a < 2; a++)
#pragma unroll
        for (int b = 0; b < 8; b++)
#pragma unroll
            for (int c = 0; c < 4; c++) acc[a][b][c] = 0.f;

    for (int st = 0; st < 12; st++) {
        const int k0 = st * 64;
        __syncthreads();
#pragma unroll
        for (int i = 0; i < 4; i++) {
            int idx = tid + i * 256;
            int row = idx >> 3, q = idx & 7;
            uint32_t dst = SWZ(row * 128 + q * 16);
            size_t sa = (size_t)(bm + row) * 768 + k0 + q * 8;
            size_t sb = (size_t)(bn + row) * 768 + k0 + q * 8;
            *(uint4*)(smem + AHo + dst) = *(const uint4*)(xh + sa);
            *(uint4*)(smem + ALo + dst) = *(const uint4*)(xl + sa);
            *(uint4*)(smem + BHo + dst) = *(const uint4*)(wh + sb);
            *(uint4*)(smem + BLo + dst) = *(const uint4*)(wl + sb);
        }
        __syncthreads();
#pragma unroll
        for (int kk = 0; kk < 4; kk++) {
            uint32_t ah[2][4], al[2][4];
            uint32_t aoff = SWZ((wm + (lane & 15)) * 128 + (kk * 2 + (lane >> 4)) * 16);
            ldmx4(ah[0], sbase + AHo + aoff);
            ldmx4(ah[1], sbase + AHo + aoff + 2048);
            ldmx4(al[0], sbase + ALo + aoff);
            ldmx4(al[1], sbase + ALo + aoff + 2048);
            uint32_t boff = SWZ((wn + (lane >> 4) * 8 + (lane & 7)) * 128 +
                                (kk * 2 + ((lane >> 3) & 1)) * 16);
#pragma unroll
            for (int ntp = 0; ntp < 4; ntp++) {
                uint32_t bh4[4], bl4[4];
                ldmx4(bh4, sbase + BHo + boff + ntp * 2048);
                ldmx4(bl4, sbase + BLo + boff + ntp * 2048);
#pragma unroll
                for (int mt = 0; mt < 2; mt++) {
                    mma16816(acc[mt][ntp * 2 + 0], ah[mt], bh4);
                    mma16816(acc[mt][ntp * 2 + 0], ah[mt], bl4);
                    mma16816(acc[mt][ntp * 2 + 0], al[mt], bh4);
                    mma16816(acc[mt][ntp * 2 + 1], ah[mt], bh4 + 2);
                    mma16816(acc[mt][ntp * 2 + 1], ah[mt], bl4 + 2);
                    mma16816(acc[mt][ntp * 2 + 1], al[mt], bh4 + 2);
                }
            }
        }
    }

    if (mode == 0 && z == 2) {
        __syncthreads();
        __nv_bfloat16* Th = (__nv_bfloat16*)smem;               // [128][136]
        __nv_bfloat16* Tl = (__nv_bfloat16*)(smem + 34816);
#pragma unroll
        for (int mt = 0; mt < 2; mt++) {
#pragma unroll
            for (int nt = 0; nt < 8; nt++) {
                int cl = wn + nt * 8 + (lane & 3) * 2;
                float bx = bias[bn + cl], by = bias[bn + cl + 1];
#pragma unroll
                for (int half = 0; half < 2; half++) {
                    int rl = wm + mt * 16 + (lane >> 2) + half * 8;
                    float v0 = acc[mt][nt][half * 2 + 0] + bx;
                    float v1 = acc[mt][nt][half * 2 + 1] + by;
                    __nv_bfloat16 h0 = __float2bfloat16(v0);
                    __nv_bfloat16 h1 = __float2bfloat16(v1);
                    Th[cl * 136 + rl] = h0;
                    Tl[cl * 136 + rl] = __float2bfloat16(v0 - __bfloat162float(h0));
                    Th[(cl + 1) * 136 + rl] = h1;
                    Tl[(cl + 1) * 136 + rl] = __float2bfloat16(v1 - __bfloat162float(h1));
                }
            }
        }
        __syncthreads();
        int b = bm >> 10, s0 = bm & 1023;
#pragma unroll
        for (int it = 0; it < 8; it++) {
            int g = tid + it * 256;
            int cl = g >> 4, q = g & 15;
            int cg = bn + cl, h = cg >> 6, d = cg & 63;
            size_t o = (((size_t)(b * Hh + h)) * 64 + d) * 1024 + s0 + q * 8;
            *(uint4*)(g_vwthi + o) = *(uint4*)&Th[cl * 136 + q * 8];
            *(uint4*)(g_vwtlo + o) = *(uint4*)&Tl[cl * 136 + q * 8];
        }
        return;
    }

#pragma unroll
    for (int mt = 0; mt < 2; mt++) {
#pragma unroll
        for (int nt = 0; nt < 8; nt++) {
            int col = bn + wn + nt * 8 + (lane & 3) * 2;
            float bx = bias[col], by = bias[col + 1];
#pragma unroll
            for (int half = 0; half < 2; half++) {
                int row = bm + wm + mt * 16 + (lane >> 2) + half * 8;
                float v0 = acc[mt][nt][half * 2 + 0] + bx;
                float v1 = acc[mt][nt][half * 2 + 1] + by;
                if (mode == 1) {
                    yout[(size_t)row * 768 + col]     = v0;
                    yout[(size_t)row * 768 + col + 1] = v1;
                } else {
                    int b = row >> 10, s = row & 1023;
                    int h = col >> 6, d = col & 63;
                    size_t base = ((size_t)(b * Hh + h) * S + s) * 64 + d;
                    __nv_bfloat16 h0 = __float2bfloat16(v0);
                    __nv_bfloat16 h1 = __float2bfloat16(v1);
                    if (z == 0) {
                        g_qhi[base] = h0; g_qhi[base + 1] = h1;
                        g_qlo[base]     = __float2bfloat16(v0 - __bfloat162float(h0));
                        g_qlo[base + 1] = __float2bfloat16(v1 - __bfloat162float(h1));
                    } else {
                        g_khi[base] = h0; g_khi[base + 1] = h1;
                        g_klo[base]     = __float2bfloat16(v0 - __bfloat162float(h0));
                        g_klo[base + 1] = __float2bfloat16(v1 - __bfloat162float(h1));
                    }
                }
            }
        }
    }
}

// ---------------- HMMA QK^T ----------------------------------------------------
__global__ __launch_bounds__(256) void qk_mma_kernel() {
    extern __shared__ __align__(128) char smem[];
    const uint32_t AHo = 0, ALo = 16384, BHo = 32768, BLo = 49152;
    const uint32_t sbase = smem_to_u32(smem);
    const int tid = threadIdx.x, wid = tid >> 5, lane = tid & 31;
    const int bh = blockIdx.z;
    const int bj = blockIdx.y * 128, bk = blockIdx.x * 128;
    const int wm = (wid >> 1) * 32, wn = (wid & 1) * 64;

    const size_t qb = ((size_t)bh * S + bj) * 64;
    const size_t kb = ((size_t)bh * S + bk) * 64;
#pragma unroll
    for (int i = 0; i < 4; i++) {
        int idx = tid + i * 256;
        int row = idx >> 3, q = idx & 7;
        uint32_t dst = SWZ(row * 128 + q * 16);
        size_t sa = qb + (size_t)row * 64 + q * 8;
        size_t sb = kb + (size_t)row * 64 + q * 8;
        *(uint4*)(smem + AHo + dst) = *(const uint4*)(g_qhi + sa);
        *(uint4*)(smem + ALo + dst) = *(const uint4*)(g_qlo + sa);
        *(uint4*)(smem + BHo + dst) = *(const uint4*)(g_khi + sb);
        *(uint4*)(smem + BLo + dst) = *(const uint4*)(g_klo + sb);
    }
    __syncthreads();

    float acc[2][8][4];
#pragma unroll
    for (int a = 0; a < 2; a++)
#pragma unroll
        for (int b = 0; b < 8; b++)
#pragma unroll
            for (int c = 0; c < 4; c++) acc[a][b][c] = 0.f;

#pragma unroll
    for (int kk = 0; kk < 4; kk++) {
        uint32_t ah[2][4], al[2][4];
        uint32_t aoff = SWZ((wm + (lane & 15)) * 128 + (kk * 2 + (lane >> 4)) * 16);
        ldmx4(ah[0], sbase + AHo + aoff);
        ldmx4(ah[1], sbase + AHo + aoff + 2048);
        ldmx4(al[0], sbase + ALo + aoff);
        ldmx4(al[1], sbase + ALo + aoff + 2048);
        uint32_t boff = SWZ((wn + (lane >> 4) * 8 + (lane & 7)) * 128 +
                            (kk * 2 + ((lane >> 3) & 1)) * 16);
#pragma unroll
        for (int ntp = 0; ntp < 4; ntp++) {
            uint32_t bh4[4], bl4[4];
            ldmx4(bh4, sbase + BHo + boff + ntp * 2048);
            ldmx4(bl4, sbase + BLo + boff + ntp * 2048);
#pragma unroll
            for (int mt = 0; mt < 2; mt++) {
                mma16816(acc[mt][ntp * 2 + 0], ah[mt], bh4);
                mma16816(acc[mt][ntp * 2 + 0], ah[mt], bl4);
                mma16816(acc[mt][ntp * 2 + 0], al[mt], bh4);
                mma16816(acc[mt][ntp * 2 + 1], ah[mt], bh4 + 2);
                mma16816(acc[mt][ntp * 2 + 1], ah[mt], bl4 + 2);
                mma16816(acc[mt][ntp * 2 + 1], al[mt], bh4 + 2);
            }
        }
    }

#pragma unroll
    for (int mt = 0; mt < 2; mt++) {
#pragma unroll
        for (int nt = 0; nt < 8; nt++) {
            int col = bk + wn + nt * 8 + (lane & 3) * 2;
#pragma unroll
            for (int half = 0; half < 2; half++) {
                int row = bj + wm + mt * 16 + (lane >> 2) + half * 8;
                size_t idx = ((size_t)bh << 20) + ((size_t)row << 10) + col;
                g_scores[idx]     = acc[mt][nt][half * 2 + 0];
                g_scores[idx + 1] = acc[mt][nt][half * 2 + 1];
            }
        }
    }
}

// ---------------------------------------------------------------------------
// Fused: scores += qw·pb (MMA), scale+mask+softmax, A -> bf16 hi/lo global,
// then phase C: attn[bh][j][:] = A·pb via trans-ldmatrix on pb tiles.
// Grid (3, 1024), 256 threads, smem 107008.
// ---------------------------------------------------------------------------
__global__ __launch_bounds__(256) void fused_pbq_sm_kernel(
    const float* __restrict__ amask, const int* __restrict__ vmask)
{
    extern __shared__ __align__(128) char smem[];
    float* Sf = (float*)smem;                     // [16][1032] fp32 = 66048
    const uint32_t PBH = 66048;                   // [128][64] bf16, 16KB
    const uint32_t QHo = 82432, QLo = 84480;      // [16][64] bf16
    float*  AM = (float*)(smem + 86528);          // [1024]
    float2* MV = (float2*)(smem + 90624);         // [2][1024] {m, neg} 16KB
    const uint32_t AHc = 90624, ALc = 94720;      // reuse MV space in phase C
    const uint32_t sbase = smem_to_u32(smem);
    const int tid = threadIdx.x, wid = tid >> 5, lane = tid & 31;
    const int t = blockIdx.x, j = blockIdx.y;
    const int bh0 = t * 16, bmin = bh0 / Hh;

#pragma unroll
    for (int it = 0; it < 16; it++) {
        int idx = tid + it * 256;
        int row = idx >> 8, k4 = idx & 255;
        *(float4*)&Sf[row * 1032 + k4 * 4] =
            *(const float4*)(g_scores + (((size_t)(bh0 + row)) << 20) +
                             ((size_t)j << 10) + k4 * 4);
    }
    if (tid < 128) {
        int r = tid >> 3, q = tid & 7;
        uint32_t dst = SWZ(r * 128 + q * 16);
        size_t src = ((size_t)(bh0 + r) * 1024 + j) * 64 + q * 8;
        *(uint4*)(smem + QHo + dst) = *(const uint4*)(g_qhi + src);
        *(uint4*)(smem + QLo + dst) = *(const uint4*)(g_qlo + src);
    }
    *(float4*)&AM[tid * 4] = *(const float4*)(amask + (size_t)j * 1024 + tid * 4);
#pragma unroll
    for (int r2 = 0; r2 < 2; r2++) {
        int4 m = *(const int4*)(vmask + (size_t)(bmin + r2) * 1024 + tid * 4);
        MV[r2 * 1024 + tid * 4 + 0] = make_float2(m.x ? 1.f : 0.f, m.x ? 0.f : NEGV);
        MV[r2 * 1024 + tid * 4 + 1] = make_float2(m.y ? 1.f : 0.f, m.y ? 0.f : NEGV);
        MV[r2 * 1024 + tid * 4 + 2] = make_float2(m.z ? 1.f : 0.f, m.z ? 0.f : NEGV);
        MV[r2 * 1024 + tid * 4 + 3] = make_float2(m.w ? 1.f : 0.f, m.w ? 0.f : NEGV);
    }
    __syncthreads();

    uint32_t ah[4][4], al[4][4];
#pragma unroll
    for (int ks = 0; ks < 4; ks++) {
        uint32_t aoff = SWZ((lane & 15) * 128 + (ks * 2 + (lane >> 4)) * 16);
        ldmx4(ah[ks], sbase + QHo + aoff);
        ldmx4(al[ks], sbase + QLo + aoff);
    }

    // ---- phase B: scores += qw·pb ----
    for (int c = 0; c < 8; c++) {
        const int k0 = c * 128;
        __syncthreads();
#pragma unroll
        for (int it = 0; it < 4; it++) {
            int idx = tid + it * 256;
            int kk = idx >> 3, q = idx & 7;
            uint32_t dst = SWZ(kk * 128 + q * 16);
            *(uint4*)(smem + PBH + dst) =
                *(const uint4*)(g_pbh + ((size_t)j * 1024 + k0 + kk) * 64 + q * 8);
        }
        __syncthreads();
        float frag[2][4] = {{0.f, 0.f, 0.f, 0.f}, {0.f, 0.f, 0.f, 0.f}};
#pragma unroll
        for (int ks = 0; ks < 4; ks++) {
            uint32_t boff = SWZ((wid * 16 + (lane >> 4) * 8 + (lane & 7)) * 128 +
                                (ks * 2 + ((lane >> 3) & 1)) * 16);
            uint32_t bh4[4];
            ldmx4(bh4, sbase + PBH + boff);
            mma16816(frag[0], ah[ks], bh4);
            mma16816(frag[0], al[ks], bh4);
            mma16816(frag[1], ah[ks], bh4 + 2);
            mma16816(frag[1], al[ks], bh4 + 2);
        }
        int r0 = lane >> 2, c0 = (lane & 3) * 2;
#pragma unroll
        for (int nt = 0; nt < 2; nt++)
#pragma unroll
            for (int e = 0; e < 4; e++) {
                int row = r0 + (e >> 1) * 8;
                int col = k0 + wid * 16 + nt * 8 + c0 + (e & 1);
                Sf[row * 1032 + col] += frag[nt][e];
            }
    }
    __syncthreads();

    // ---- softmax ----
#pragma unroll
    for (int rr = 0; rr < 2; rr++) {
        int row = wid * 2 + rr;
        int bsel = (bh0 + row) / Hh - bmin;
        float x[32];
        float mx = -3.4e38f;
#pragma unroll
        for (int i = 0; i < 32; i++) {
            int k = lane + i * 32;
            float2 mv = MV[bsel * 1024 + k];
            float val = fmaf(Sf[row * 1032 + k], 0.125f, AM[k]);
            x[i] = fmaf(val, mv.x, mv.y);
            mx = fmaxf(mx, x[i]);
        }
#pragma unroll
        for (int o = 16; o > 0; o >>= 1) mx = fmaxf(mx, __shfl_xor_sync(~0u, mx, o));
        float sum = 0.f;
#pragma unroll
        for (int i = 0; i < 32; i++) { x[i] = __expf(x[i] - mx); sum += x[i]; }
#pragma unroll
        for (int o = 16; o > 0; o >>= 1) sum += __shfl_xor_sync(~0u, sum, o);
        float inv = 1.f / sum;
#pragma unroll
        for (int i = 0; i < 32; i++) Sf[row * 1032 + lane + i * 32] = x[i] * inv;
    }
    __syncthreads();

    // ---- write A bf16 hi/lo ----
    {
        const int row = tid >> 4, kb = (tid & 15) * 64;
        const size_t obase = (((size_t)(bh0 + row)) << 20) + ((size_t)j << 10);
#pragma unroll
        for (int g = 0; g < 8; g++) {
            int k = kb + g * 8;
            float4 a = *(float4*)&Sf[row * 1032 + k];
            float4 b = *(float4*)&Sf[row * 1032 + k + 4];
            uint2 h0, l0, h1, l1;
            split4(a, h0, l0); split4(b, h1, l1);
            *(uint4*)(g_Ahi + obase + k) = make_uint4(h0.x, h0.y, h1.x, h1.y);
            *(uint4*)(g_Alo + obase + k) = make_uint4(l0.x, l0.y, l1.x, l1.y);
        }
    }

    // ---- phase C: attn[bh0..+15][d] = A·pb  (warp w owns d = w*8..w*8+7) ----
    float facc[4] = {0.f, 0.f, 0.f, 0.f};
    const int w16 = wid * 16;   // byte offset of d-col block
    for (int c = 0; c < 8; c++) {
        const int k0 = c * 128;
        __syncthreads();
#pragma unroll
        for (int it = 0; it < 4; it++) {
            int idx = tid + it * 256;
            int kk = idx >> 3, q = idx & 7;
            uint32_t dst = SWZ(kk * 128 + q * 16);
            *(uint4*)(smem + PBH + dst) =
                *(const uint4*)(g_pbh + ((size_t)j * 1024 + k0 + kk) * 64 + q * 8);
        }
        {
            int row = tid >> 4, col = (tid & 15) * 8;
            float4 a = *(float4*)&Sf[row * 1032 + k0 + col];
            float4 b = *(float4*)&Sf[row * 1032 + k0 + col + 4];
            uint2 h0, l0, h1, l1;
            split4(a, h0, l0); split4(b, h1, l1);
            uint32_t dst = SWZ256(row * 256 + col * 2);
            *(uint4*)(smem + AHc + dst) = make_uint4(h0.x, h0.y, h1.x, h1.y);
            *(uint4*)(smem + ALc + dst) = make_uint4(l0.x, l0.y, l1.x, l1.y);
        }
        __syncthreads();
#pragma unroll
        for (int ks = 0; ks < 8; ks++) {
            uint32_t a_h[4], a_l[4];
            uint32_t aoff = SWZ256((lane & 15) * 256 + (ks * 2 + (lane >> 4)) * 16);
            ldmx4(a_h, sbase + AHc + aoff);
            ldmx4(a_l, sbase + ALc + aoff);
            uint32_t bt[2];
            uint32_t boff = SWZ((ks * 16 + (lane & 15)) * 128 + w16);
            ldmx2t(bt, sbase + PBH + boff);
            mma16816(facc, a_h, bt);
            mma16816(facc, a_l, bt);
        }
    }
    {
        int d = wid * 8 + (lane & 3) * 2;
#pragma unroll
        for (int half = 0; half < 2; half++) {
            int bh = bh0 + (lane >> 2) + half * 8;
            int b = bh / Hh, h = bh % Hh;
            size_t o = ((size_t)(b * 1024 + j)) * 768 + h * 64 + d;
            g_attn[o]     = facc[half * 2 + 0];
            g_attn[o + 1] = facc[half * 2 + 1];
        }
    }
}

// ---------------------------------------------------------------------------
// av: attn += A·vw. Grid (8, 48). M=128, N=64, K=1024.
// ---------------------------------------------------------------------------
__global__ __launch_bounds__(256) void av_mma_kernel() {
    extern __shared__ __align__(128) char smem[];
    const uint32_t AHs = 0, ALs = 32768, VHs = 65536, VLs = 81920;
    const uint32_t sbase = smem_to_u32(smem);
    const int tid = threadIdx.x, wid = tid >> 5, lane = tid & 31;
    const int bh = blockIdx.y, j0 = blockIdx.x * 128;

    float facc[8][4];
#pragma unroll
    for (int a = 0; a < 8; a++)
#pragma unroll
        for (int b = 0; b < 4; b++) facc[a][b] = 0.f;

    for (int c = 0; c < 8; c++) {
        const int k0 = c * 128;
        __syncthreads();
#pragma unroll
        for (int it = 0; it < 16; it++) {
            int idx = tid + it * 256;
            int buf = idx >> 11, rc = idx & 2047;
            int row = rc >> 4, q = rc & 15;
            const __nv_bfloat16* src = buf ? g_Alo : g_Ahi;
            uint32_t dst = SWZ256(row * 256 + q * 16);
            *(uint4*)(smem + (buf ? ALs : AHs) + dst) =
                *(const uint4*)(src + (((size_t)bh) << 20) +
                                ((size_t)(j0 + row) << 10) + k0 + q * 8);
        }
#pragma unroll
        for (int it = 0; it < 8; it++) {
            int idx = tid + it * 256;
            int buf = idx >> 10, rc = idx & 1023;
            int d = rc >> 4, q = rc & 15;
            const __nv_bfloat16* src = buf ? g_vwtlo : g_vwthi;
            uint32_t dst = SWZ256(d * 256 + q * 16);
            *(uint4*)(smem + (buf ? VLs : VHs) + dst) =
                *(const uint4*)(src + ((size_t)bh * 64 + d) * 1024 + k0 + q * 8);
        }
        __syncthreads();
#pragma unroll
        for (int ks = 0; ks < 8; ks++) {
            uint32_t a_h[4], a_l[4];
            uint32_t aoff = SWZ256((wid * 16 + (lane & 15)) * 256 +
                                   (ks * 2 + (lane >> 4)) * 16);
            ldmx4(a_h, sbase + AHs + aoff);
            ldmx4(a_l, sbase + ALs + aoff);
#pragma unroll
            for (int np = 0; np < 4; np++) {
                uint32_t boff = SWZ256((np * 16 + (lane >> 4) * 8 + (lane & 7)) * 256 +
                                       (ks * 2 + ((lane >> 3) & 1)) * 16);
                uint32_t b_h[4], b_l[4];
                ldmx4(b_h, sbase + VHs + boff);
                ldmx4(b_l, sbase + VLs + boff);
                mma16816(facc[np * 2 + 0], a_h, b_h);
                mma16816(facc[np * 2 + 0], a_h, b_l);
                mma16816(facc[np * 2 + 0], a_l, b_h);
                mma16816(facc[np * 2 + 1], a_h, b_h + 2);
                mma16816(facc[np * 2 + 1], a_h, b_l + 2);
                mma16816(facc[np * 2 + 1], a_l, b_h + 2);
            }
        }
    }
    const int b = bh / Hh, h = bh % Hh;
#pragma unroll
    for (int nt = 0; nt < 8; nt++) {
        int d = nt * 8 + (lane & 3) * 2;
#pragma unroll
        for (int half = 0; half < 2; half++) {
            int s = j0 + wid * 16 + (lane >> 2) + half * 8;
            size_t o = ((size_t)(b * 1024 + s)) * 768 + h * 64 + d;
            g_attn[o]     += facc[nt][half * 2 + 0];
            g_attn[o + 1] += facc[nt][half * 2 + 1];
        }
    }
}

// ---------------------------------------------------------------------------
extern "C" void kernel_launch(void* const* d_in, const int* in_sizes, int n_in,
                              void* d_out, int out_size) {
    const float* q     = (const float*)d_in[0];
    const float* k     = (const float*)d_in[1];
    const float* v     = (const float*)d_in[2];
    const float* amask = (const float*)d_in[3];
    const float* pb    = (const float*)d_in[4];
    const int*   vmask = (const int*)  d_in[5];
    const float* Wq    = (const float*)d_in[6];
    const float* bq    = (const float*)d_in[7];
    const float* Wk    = (const float*)d_in[8];
    const float* bk    = (const float*)d_in[9];
    const float* Wv    = (const float*)d_in[10];
    const float* bv    = (const float*)d_in[11];
    const float* Wo    = (const float*)d_in[12];
    const float* bo    = (const float*)d_in[13];
    float* out = (float*)d_out;

    const int SM_GEMM = 69632, SM_QK = 65536, SM_FUSED = 107008, SM_AV = 98304;
    static bool attr_done = false;
    if (!attr_done) {
        cudaFuncSetAttribute(gemm_mma_kernel, cudaFuncAttributeMaxDynamicSharedMemorySize, SM_GEMM);
        cudaFuncSetAttribute(qk_mma_kernel, cudaFuncAttributeMaxDynamicSharedMemorySize, SM_QK);
        cudaFuncSetAttribute(fused_pbq_sm_kernel, cudaFuncAttributeMaxDynamicSharedMemorySize, SM_FUSED);
        cudaFuncSetAttribute(av_mma_kernel, cudaFuncAttributeMaxDynamicSharedMemorySize, SM_AV);
        attr_done = true;
    }

    const int n4 = 4096 * 768 / 4;
    const int pb4 = 1024 * 1024 * 64 / 4;
    pbconv_kernel<<<pb4 / 256, 256>>>(pb, pb4);
    conv_split_kernel<<<n4 / 256, 256>>>(q, 0, n4);
    conv_split_kernel<<<n4 / 256, 256>>>(k, 1, n4);
    conv_split_kernel<<<n4 / 256, 256>>>(v, 2, n4);
    dim3 tthr(32, 32), tgrd(24, 24);
    transpose_conv_kernel<<<tgrd, tthr>>>(Wq, 0);
    transpose_conv_kernel<<<tgrd, tthr>>>(Wk, 1);
    transpose_conv_kernel<<<tgrd, tthr>>>(Wv, 2);
    transpose_conv_kernel<<<tgrd, tthr>>>(Wo, 3);

    gemm_mma_kernel<<<dim3(6, 32, 3), 256, SM_GEMM>>>(bq, bk, bv, nullptr, 0);
    qk_mma_kernel<<<dim3(8, 8, 48), 256, SM_QK>>>();
    fused_pbq_sm_kernel<<<dim3(3, 1024), 256, SM_FUSED>>>(amask, vmask);
    av_mma_kernel<<<dim3(8, 48), 256, SM_AV>>>();
    conv_split_kernel<<<n4 / 256, 256>>>(nullptr, 0, n4);
    gemm_mma_kernel<<<dim3(6, 32, 1), 256, SM_GEMM>>>(bo, nullptr, nullptr, out, 1);
}

// round 9
// speedup vs baseline: 2.9378x; 1.4280x over previous
#include <cuda_runtime.h>
#include <cuda_fp16.h>
#include <cstdint>

// ---------------------------------------------------------------------------
// NEZHA-style MHA, all single-fp16 HMMA (mma.sync m16n8k16 f16, fp32 accum).
// B=4, S=1024, H=12, DK=DV=64, DM=768.
// ---------------------------------------------------------------------------

#define S 1024
#define Hh 12
#define BH 48
#define NEGV (-1e12f)

// ---------------- scratch -----------------------------------------------------
__device__ float g_attn[(size_t)4 * S * 768];
__device__ float g_scores[(size_t)BH * S * S];     // 201 MB

__device__ __align__(16) __half g_x16[(size_t)3 * 4096 * 768];
__device__ __align__(16) __half g_wt16[(size_t)4 * 768 * 768];
__device__ __align__(16) __half g_q16[(size_t)BH * S * 64];
__device__ __align__(16) __half g_k16[(size_t)BH * S * 64];
__device__ __align__(16) __half g_vwt16[(size_t)BH * 64 * S];   // [bh][d][s]
__device__ __align__(16) __half g_A16[(size_t)BH * S * S];      // 100 MB
__device__ __align__(16) __half g_pb16[(size_t)S * S * 64];     // [j][k][d] 128MB

// ---------------- helpers -----------------------------------------------------
__device__ __forceinline__ uint32_t smem_to_u32(const void* p) {
    uint32_t a;
    asm("{ .reg .u64 t; cvta.to.shared.u64 t, %1; cvt.u32.u64 %0, t; }"
        : "=r"(a) : "l"(p));
    return a;
}
#define SWZ(o)    ((uint32_t)(o) ^ ((((uint32_t)(o)) >> 3) & 0x70))
#define SWZ256(o) ((uint32_t)(o) ^ ((((uint32_t)(o)) >> 4) & 0x70))

__device__ __forceinline__ void ldmx4(uint32_t* r, uint32_t a) {
    asm volatile("ldmatrix.sync.aligned.m8n8.x4.shared.b16 {%0,%1,%2,%3}, [%4];"
                 : "=r"(r[0]), "=r"(r[1]), "=r"(r[2]), "=r"(r[3]) : "r"(a));
}
__device__ __forceinline__ void ldmx2t(uint32_t* r, uint32_t a) {
    asm volatile("ldmatrix.sync.aligned.m8n8.x2.trans.shared.b16 {%0,%1}, [%2];"
                 : "=r"(r[0]), "=r"(r[1]) : "r"(a));
}
__device__ __forceinline__ void mmah(float* c, const uint32_t* a,
                                     const uint32_t* b) {
    asm volatile(
        "mma.sync.aligned.m16n8k16.row.col.f32.f16.f16.f32 "
        "{%0,%1,%2,%3},{%4,%5,%6,%7},{%8,%9},{%0,%1,%2,%3};"
        : "+f"(c[0]), "+f"(c[1]), "+f"(c[2]), "+f"(c[3])
        : "r"(a[0]), "r"(a[1]), "r"(a[2]), "r"(a[3]), "r"(b[0]), "r"(b[1]));
}
__device__ __forceinline__ uint32_t hpack(float a, float b) {
    __half2 t = __floats2half2_rn(a, b);
    return *(uint32_t*)&t;
}
__device__ __forceinline__ uint2 cvt4(float4 v) {
    uint2 r;
    r.x = hpack(v.x, v.y);
    r.y = hpack(v.z, v.w);
    return r;
}

// ---------------- conversion kernels ------------------------------------------
__global__ void conv16_kernel(const float* __restrict__ src, int slot, int n4) {
    int i = blockIdx.x * blockDim.x + threadIdx.x;
    if (i >= n4) return;
    const float* s = src ? src : g_attn;
    float4 v = ((const float4*)s)[i];
    *(uint2*)(g_x16 + (size_t)slot * 4096 * 768 + (size_t)i * 4) = cvt4(v);
}

__global__ void transpose_conv_kernel(const float* __restrict__ W, int slot) {
    __shared__ float t[32][33];
    int tx = threadIdx.x, ty = threadIdx.y;
    int k = blockIdx.y * 32 + ty, n = blockIdx.x * 32 + tx;
    t[ty][tx] = W[(size_t)k * 768 + n];
    __syncthreads();
    int n2 = blockIdx.x * 32 + ty, k2 = blockIdx.y * 32 + tx;
    g_wt16[(size_t)slot * 768 * 768 + (size_t)n2 * 768 + k2] = __float2half(t[tx][ty]);
}

__global__ __launch_bounds__(256) void pbconv_kernel(const float* __restrict__ pb, int n4) {
    int i = blockIdx.x * blockDim.x + threadIdx.x;
    if (i >= n4) return;
    float4 v = ((const float4*)pb)[i];
    *(uint2*)(g_pb16 + (size_t)i * 4) = cvt4(v);
}

// ---------------- HMMA dense GEMM (single fp16) --------------------------------
// mode 0: QKV (z=0/1/2; z==2 writes vw^T). mode 1: output projection.
__global__ __launch_bounds__(256) void gemm_mma_kernel(
    const float* __restrict__ b0, const float* __restrict__ b1,
    const float* __restrict__ b2, float* __restrict__ yout, int mode)
{
    extern __shared__ __align__(128) char smem[];
    const uint32_t Ao = 0, Bo = 16384;
    const uint32_t sbase = smem_to_u32(smem);
    const int tid = threadIdx.x, wid = tid >> 5, lane = tid & 31;
    const int z = blockIdx.z;
    const int bm = blockIdx.y * 128, bn = blockIdx.x * 128;
    const int xsel = (mode == 0) ? z : 0;
    const int wsel = (mode == 0) ? z : 3;
    const __half* xx = g_x16 + (size_t)xsel * 4096 * 768;
    const __half* wt = g_wt16 + (size_t)wsel * 768 * 768;
    const float* bias = (mode == 1) ? b0 : (z == 0 ? b0 : (z == 1 ? b1 : b2));

    const int wm = (wid >> 1) * 32, wn = (wid & 1) * 64;
    float acc[2][8][4];
#pragma unroll
    for (int a = 0; a < 2; a++)
#pragma unroll
        for (int b = 0; b < 8; b++)
#pragma unroll
            for (int c = 0; c < 4; c++) acc[a][b][c] = 0.f;

    for (int st = 0; st < 12; st++) {
        const int k0 = st * 64;
        __syncthreads();
#pragma unroll
        for (int i = 0; i < 8; i++) {
            int idx = tid + i * 256;
            int buf = idx >> 10, rc = idx & 1023;
            int row = rc >> 3, q = rc & 7;
            uint32_t dst = SWZ(row * 128 + q * 16);
            const __half* src = buf ? (wt + (size_t)(bn + row) * 768 + k0 + q * 8)
                                    : (xx + (size_t)(bm + row) * 768 + k0 + q * 8);
            *(uint4*)(smem + (buf ? Bo : Ao) + dst) = *(const uint4*)src;
        }
        __syncthreads();
#pragma unroll
        for (int kk = 0; kk < 4; kk++) {
            uint32_t a4[2][4];
            uint32_t aoff = SWZ((wm + (lane & 15)) * 128 + (kk * 2 + (lane >> 4)) * 16);
            ldmx4(a4[0], sbase + Ao + aoff);
            ldmx4(a4[1], sbase + Ao + aoff + 2048);
            uint32_t boff = SWZ((wn + (lane >> 4) * 8 + (lane & 7)) * 128 +
                                (kk * 2 + ((lane >> 3) & 1)) * 16);
#pragma unroll
            for (int ntp = 0; ntp < 4; ntp++) {
                uint32_t b4[4];
                ldmx4(b4, sbase + Bo + boff + ntp * 2048);
#pragma unroll
                for (int mt = 0; mt < 2; mt++) {
                    mmah(acc[mt][ntp * 2 + 0], a4[mt], b4);
                    mmah(acc[mt][ntp * 2 + 1], a4[mt], b4 + 2);
                }
            }
        }
    }

    if (mode == 0 && z == 2) {
        // V projection: smem-transpose to vw^T fp16 [bh][d][s].
        __syncthreads();
        __half* Th = (__half*)smem;               // [128][136]
#pragma unroll
        for (int mt = 0; mt < 2; mt++) {
#pragma unroll
            for (int nt = 0; nt < 8; nt++) {
                int cl = wn + nt * 8 + (lane & 3) * 2;
                float bx = bias[bn + cl], by = bias[bn + cl + 1];
#pragma unroll
                for (int half = 0; half < 2; half++) {
                    int rl = wm + mt * 16 + (lane >> 2) + half * 8;
                    Th[cl * 136 + rl]       = __float2half(acc[mt][nt][half * 2 + 0] + bx);
                    Th[(cl + 1) * 136 + rl] = __float2half(acc[mt][nt][half * 2 + 1] + by);
                }
            }
        }
        __syncthreads();
        int b = bm >> 10, s0 = bm & 1023;
#pragma unroll
        for (int it = 0; it < 8; it++) {
            int g = tid + it * 256;
            int cl = g >> 4, q = g & 15;
            int cg = bn + cl, h = cg >> 6, d = cg & 63;
            size_t o = (((size_t)(b * Hh + h)) * 64 + d) * 1024 + s0 + q * 8;
            *(uint4*)(g_vwt16 + o) = *(uint4*)&Th[cl * 136 + q * 8];
        }
        return;
    }

#pragma unroll
    for (int mt = 0; mt < 2; mt++) {
#pragma unroll
        for (int nt = 0; nt < 8; nt++) {
            int col = bn + wn + nt * 8 + (lane & 3) * 2;
            float bx = bias[col], by = bias[col + 1];
#pragma unroll
            for (int half = 0; half < 2; half++) {
                int row = bm + wm + mt * 16 + (lane >> 2) + half * 8;
                float v0 = acc[mt][nt][half * 2 + 0] + bx;
                float v1 = acc[mt][nt][half * 2 + 1] + by;
                if (mode == 1) {
                    yout[(size_t)row * 768 + col]     = v0;
                    yout[(size_t)row * 768 + col + 1] = v1;
                } else {
                    int b = row >> 10, s = row & 1023;
                    int h = col >> 6, d = col & 63;
                    size_t base = ((size_t)(b * Hh + h) * S + s) * 64 + d;
                    __half* dstp = (z == 0) ? g_q16 : g_k16;
                    dstp[base]     = __float2half(v0);
                    dstp[base + 1] = __float2half(v1);
                }
            }
        }
    }
}

// ---------------- HMMA QK^T (single fp16) --------------------------------------
__global__ __launch_bounds__(256) void qk_mma_kernel() {
    extern __shared__ __align__(128) char smem[];
    const uint32_t Ao = 0, Bo = 16384;
    const uint32_t sbase = smem_to_u32(smem);
    const int tid = threadIdx.x, wid = tid >> 5, lane = tid & 31;
    const int bh = blockIdx.z;
    const int bj = blockIdx.y * 128, bk = blockIdx.x * 128;
    const int wm = (wid >> 1) * 32, wn = (wid & 1) * 64;

    const size_t qb = ((size_t)bh * S + bj) * 64;
    const size_t kb = ((size_t)bh * S + bk) * 64;
#pragma unroll
    for (int i = 0; i < 8; i++) {
        int idx = tid + i * 256;
        int buf = idx >> 10, rc = idx & 1023;
        int row = rc >> 3, q = rc & 7;
        uint32_t dst = SWZ(row * 128 + q * 16);
        const __half* src = buf ? (g_k16 + kb + (size_t)row * 64 + q * 8)
                                : (g_q16 + qb + (size_t)row * 64 + q * 8);
        *(uint4*)(smem + (buf ? Bo : Ao) + dst) = *(const uint4*)src;
    }
    __syncthreads();

    float acc[2][8][4];
#pragma unroll
    for (int a = 0; a < 2; a++)
#pragma unroll
        for (int b = 0; b < 8; b++)
#pragma unroll
            for (int c = 0; c < 4; c++) acc[a][b][c] = 0.f;

#pragma unroll
    for (int kk = 0; kk < 4; kk++) {
        uint32_t a4[2][4];
        uint32_t aoff = SWZ((wm + (lane & 15)) * 128 + (kk * 2 + (lane >> 4)) * 16);
        ldmx4(a4[0], sbase + Ao + aoff);
        ldmx4(a4[1], sbase + Ao + aoff + 2048);
        uint32_t boff = SWZ((wn + (lane >> 4) * 8 + (lane & 7)) * 128 +
                            (kk * 2 + ((lane >> 3) & 1)) * 16);
#pragma unroll
        for (int ntp = 0; ntp < 4; ntp++) {
            uint32_t b4[4];
            ldmx4(b4, sbase + Bo + boff + ntp * 2048);
#pragma unroll
            for (int mt = 0; mt < 2; mt++) {
                mmah(acc[mt][ntp * 2 + 0], a4[mt], b4);
                mmah(acc[mt][ntp * 2 + 1], a4[mt], b4 + 2);
            }
        }
    }

#pragma unroll
    for (int mt = 0; mt < 2; mt++) {
#pragma unroll
        for (int nt = 0; nt < 8; nt++) {
            int col = bk + wn + nt * 8 + (lane & 3) * 2;
#pragma unroll
            for (int half = 0; half < 2; half++) {
                int row = bj + wm + mt * 16 + (lane >> 2) + half * 8;
                size_t idx = ((size_t)bh << 20) + ((size_t)row << 10) + col;
                g_scores[idx]     = acc[mt][nt][half * 2 + 0];
                g_scores[idx + 1] = acc[mt][nt][half * 2 + 1];
            }
        }
    }
}

// ---------------------------------------------------------------------------
// Fused: scores += qw·pb (MMA), scale+mask+softmax, A -> fp16 global,
// phase C: attn[bh][j][:] = A·pb via trans-ldmatrix. Grid (3, 1024).
// ---------------------------------------------------------------------------
__global__ __launch_bounds__(256) void fused_pbq_sm_kernel(
    const float* __restrict__ amask, const int* __restrict__ vmask)
{
    extern __shared__ __align__(128) char smem[];
    float* Sf = (float*)smem;                     // [16][1032] fp32 = 66048
    const uint32_t PBH = 66048;                   // [128][64] fp16, 16KB
    const uint32_t QHo = 82432;                   // [16][64] fp16, 2KB
    float*  AM = (float*)(smem + 84480);          // [1024] -> 88576
    float2* MV = (float2*)(smem + 88576);         // [2][1024] {m,neg} 16KB -> 104960
    const uint32_t AHc = 88576;                   // reuse MV space in phase C (4KB)
    const uint32_t sbase = smem_to_u32(smem);
    const int tid = threadIdx.x, wid = tid >> 5, lane = tid & 31;
    const int t = blockIdx.x, j = blockIdx.y;
    const int bh0 = t * 16, bmin = bh0 / Hh;

#pragma unroll
    for (int it = 0; it < 16; it++) {
        int idx = tid + it * 256;
        int row = idx >> 8, k4 = idx & 255;
        *(float4*)&Sf[row * 1032 + k4 * 4] =
            *(const float4*)(g_scores + (((size_t)(bh0 + row)) << 20) +
                             ((size_t)j << 10) + k4 * 4);
    }
    if (tid < 128) {
        int r = tid >> 3, q = tid & 7;
        uint32_t dst = SWZ(r * 128 + q * 16);
        size_t src = ((size_t)(bh0 + r) * 1024 + j) * 64 + q * 8;
        *(uint4*)(smem + QHo + dst) = *(const uint4*)(g_q16 + src);
    }
    *(float4*)&AM[tid * 4] = *(const float4*)(amask + (size_t)j * 1024 + tid * 4);
#pragma unroll
    for (int r2 = 0; r2 < 2; r2++) {
        int4 m = *(const int4*)(vmask + (size_t)(bmin + r2) * 1024 + tid * 4);
        MV[r2 * 1024 + tid * 4 + 0] = make_float2(m.x ? 1.f : 0.f, m.x ? 0.f : NEGV);
        MV[r2 * 1024 + tid * 4 + 1] = make_float2(m.y ? 1.f : 0.f, m.y ? 0.f : NEGV);
        MV[r2 * 1024 + tid * 4 + 2] = make_float2(m.z ? 1.f : 0.f, m.z ? 0.f : NEGV);
        MV[r2 * 1024 + tid * 4 + 3] = make_float2(m.w ? 1.f : 0.f, m.w ? 0.f : NEGV);
    }
    __syncthreads();

    uint32_t aq[4][4];
#pragma unroll
    for (int ks = 0; ks < 4; ks++) {
        uint32_t aoff = SWZ((lane & 15) * 128 + (ks * 2 + (lane >> 4)) * 16);
        ldmx4(aq[ks], sbase + QHo + aoff);
    }

    // ---- phase B: scores += qw·pb ----
    for (int c = 0; c < 8; c++) {
        const int k0 = c * 128;
        __syncthreads();
#pragma unroll
        for (int it = 0; it < 4; it++) {
            int idx = tid + it * 256;
            int kk = idx >> 3, q = idx & 7;
            uint32_t dst = SWZ(kk * 128 + q * 16);
            *(uint4*)(smem + PBH + dst) =
                *(const uint4*)(g_pb16 + ((size_t)j * 1024 + k0 + kk) * 64 + q * 8);
        }
        __syncthreads();
        float frag[2][4] = {{0.f, 0.f, 0.f, 0.f}, {0.f, 0.f, 0.f, 0.f}};
#pragma unroll
        for (int ks = 0; ks < 4; ks++) {
            uint32_t boff = SWZ((wid * 16 + (lane >> 4) * 8 + (lane & 7)) * 128 +
                                (ks * 2 + ((lane >> 3) & 1)) * 16);
            uint32_t b4[4];
            ldmx4(b4, sbase + PBH + boff);
            mmah(frag[0], aq[ks], b4);
            mmah(frag[1], aq[ks], b4 + 2);
        }
        int r0 = lane >> 2, c0 = (lane & 3) * 2;
#pragma unroll
        for (int nt = 0; nt < 2; nt++)
#pragma unroll
            for (int e = 0; e < 4; e++) {
                int row = r0 + (e >> 1) * 8;
                int col = k0 + wid * 16 + nt * 8 + c0 + (e & 1);
                Sf[row * 1032 + col] += frag[nt][e];
            }
    }
    __syncthreads();

    // ---- softmax ----
#pragma unroll
    for (int rr = 0; rr < 2; rr++) {
        int row = wid * 2 + rr;
        int bsel = (bh0 + row) / Hh - bmin;
        float x[32];
        float mx = -3.4e38f;
#pragma unroll
        for (int i = 0; i < 32; i++) {
            int k = lane + i * 32;
            float2 mv = MV[bsel * 1024 + k];
            float val = fmaf(Sf[row * 1032 + k], 0.125f, AM[k]);
            x[i] = fmaf(val, mv.x, mv.y);
            mx = fmaxf(mx, x[i]);
        }
#pragma unroll
        for (int o = 16; o > 0; o >>= 1) mx = fmaxf(mx, __shfl_xor_sync(~0u, mx, o));
        float sum = 0.f;
#pragma unroll
        for (int i = 0; i < 32; i++) { x[i] = __expf(x[i] - mx); sum += x[i]; }
#pragma unroll
        for (int o = 16; o > 0; o >>= 1) sum += __shfl_xor_sync(~0u, sum, o);
        float inv = 1.f / sum;
#pragma unroll
        for (int i = 0; i < 32; i++) Sf[row * 1032 + lane + i * 32] = x[i] * inv;
    }
    __syncthreads();

    // ---- write A fp16 ----
    {
        const int row = tid >> 4, kb = (tid & 15) * 64;
        const size_t obase = (((size_t)(bh0 + row)) << 20) + ((size_t)j << 10);
#pragma unroll
        for (int g = 0; g < 8; g++) {
            int k = kb + g * 8;
            uint2 p0 = cvt4(*(float4*)&Sf[row * 1032 + k]);
            uint2 p1 = cvt4(*(float4*)&Sf[row * 1032 + k + 4]);
            *(uint4*)(g_A16 + obase + k) = make_uint4(p0.x, p0.y, p1.x, p1.y);
        }
    }

    // ---- phase C: attn[bh0..+15][d] = A·pb (warp w owns d = w*8..w*8+7) ----
    float facc[4] = {0.f, 0.f, 0.f, 0.f};
    const int w16 = wid * 16;
    for (int c = 0; c < 8; c++) {
        const int k0 = c * 128;
        __syncthreads();
#pragma unroll
        for (int it = 0; it < 4; it++) {
            int idx = tid + it * 256;
            int kk = idx >> 3, q = idx & 7;
            uint32_t dst = SWZ(kk * 128 + q * 16);
            *(uint4*)(smem + PBH + dst) =
                *(const uint4*)(g_pb16 + ((size_t)j * 1024 + k0 + kk) * 64 + q * 8);
        }
        {
            int row = tid >> 4, col = (tid & 15) * 8;
            uint2 p0 = cvt4(*(float4*)&Sf[row * 1032 + k0 + col]);
            uint2 p1 = cvt4(*(float4*)&Sf[row * 1032 + k0 + col + 4]);
            uint32_t dst = SWZ256(row * 256 + col * 2);
            *(uint4*)(smem + AHc + dst) = make_uint4(p0.x, p0.y, p1.x, p1.y);
        }
        __syncthreads();
#pragma unroll
        for (int ks = 0; ks < 8; ks++) {
            uint32_t a4[4];
            uint32_t aoff = SWZ256((lane & 15) * 256 + (ks * 2 + (lane >> 4)) * 16);
            ldmx4(a4, sbase + AHc + aoff);
            uint32_t bt[2];
            uint32_t boff = SWZ((ks * 16 + (lane & 15)) * 128 + w16);
            ldmx2t(bt, sbase + PBH + boff);
            mmah(facc, a4, bt);
        }
    }
    {
        int d = wid * 8 + (lane & 3) * 2;
#pragma unroll
        for (int half = 0; half < 2; half++) {
            int bh = bh0 + (lane >> 2) + half * 8;
            int b = bh / Hh, h = bh % Hh;
            size_t o = ((size_t)(b * 1024 + j)) * 768 + h * 64 + d;
            g_attn[o]     = facc[half * 2 + 0];
            g_attn[o + 1] = facc[half * 2 + 1];
        }
    }
}

// ---------------------------------------------------------------------------
// av: attn += A·vw. Grid (8, 48). M=128, N=64, K=1024. Single fp16.
// ---------------------------------------------------------------------------
__global__ __launch_bounds__(256) void av_mma_kernel() {
    extern __shared__ __align__(128) char smem[];
    const uint32_t Ao = 0, Vo = 32768;
    const uint32_t sbase = smem_to_u32(smem);
    const int tid = threadIdx.x, wid = tid >> 5, lane = tid & 31;
    const int bh = blockIdx.y, j0 = blockIdx.x * 128;

    float facc[8][4];
#pragma unroll
    for (int a = 0; a < 8; a++)
#pragma unroll
        for (int b = 0; b < 4; b++) facc[a][b] = 0.f;

    for (int c = 0; c < 8; c++) {
        const int k0 = c * 128;
        __syncthreads();
#pragma unroll
        for (int it = 0; it < 12; it++) {
            int idx = tid + it * 256;
            if (idx < 2048) {
                int row = idx >> 4, q = idx & 15;
                uint32_t dst = SWZ256(row * 256 + q * 16);
                *(uint4*)(smem + Ao + dst) =
                    *(const uint4*)(g_A16 + (((size_t)bh) << 20) +
                                    ((size_t)(j0 + row) << 10) + k0 + q * 8);
            } else {
                int rc = idx - 2048;
                int d = rc >> 4, q = rc & 15;
                uint32_t dst = SWZ256(d * 256 + q * 16);
                *(uint4*)(smem + Vo + dst) =
                    *(const uint4*)(g_vwt16 + ((size_t)bh * 64 + d) * 1024 + k0 + q * 8);
            }
        }
        __syncthreads();
#pragma unroll
        for (int ks = 0; ks < 8; ks++) {
            uint32_t a4[4];
            uint32_t aoff = SWZ256((wid * 16 + (lane & 15)) * 256 +
                                   (ks * 2 + (lane >> 4)) * 16);
            ldmx4(a4, sbase + Ao + aoff);
#pragma unroll
            for (int np = 0; np < 4; np++) {
                uint32_t boff = SWZ256((np * 16 + (lane >> 4) * 8 + (lane & 7)) * 256 +
                                       (ks * 2 + ((lane >> 3) & 1)) * 16);
                uint32_t b4[4];
                ldmx4(b4, sbase + Vo + boff);
                mmah(facc[np * 2 + 0], a4, b4);
                mmah(facc[np * 2 + 1], a4, b4 + 2);
            }
        }
    }
    const int b = bh / Hh, h = bh % Hh;
#pragma unroll
    for (int nt = 0; nt < 8; nt++) {
        int d = nt * 8 + (lane & 3) * 2;
#pragma unroll
        for (int half = 0; half < 2; half++) {
            int s = j0 + wid * 16 + (lane >> 2) + half * 8;
            size_t o = ((size_t)(b * 1024 + s)) * 768 + h * 64 + d;
            g_attn[o]     += facc[nt][half * 2 + 0];
            g_attn[o + 1] += facc[nt][half * 2 + 1];
        }
    }
}

// ---------------------------------------------------------------------------
extern "C" void kernel_launch(void* const* d_in, const int* in_sizes, int n_in,
                              void* d_out, int out_size) {
    const float* q     = (const float*)d_in[0];
    const float* k     = (const float*)d_in[1];
    const float* v     = (const float*)d_in[2];
    const float* amask = (const float*)d_in[3];
    const float* pb    = (const float*)d_in[4];
    const int*   vmask = (const int*)  d_in[5];
    const float* Wq    = (const float*)d_in[6];
    const float* bq    = (const float*)d_in[7];
    const float* Wk    = (const float*)d_in[8];
    const float* bk    = (const float*)d_in[9];
    const float* Wv    = (const float*)d_in[10];
    const float* bv    = (const float*)d_in[11];
    const float* Wo    = (const float*)d_in[12];
    const float* bo    = (const float*)d_in[13];
    float* out = (float*)d_out;

    const int SM_GEMM = 36864, SM_QK = 32768, SM_FUSED = 104960, SM_AV = 49152;
    static bool attr_done = false;
    if (!attr_done) {
        cudaFuncSetAttribute(gemm_mma_kernel, cudaFuncAttributeMaxDynamicSharedMemorySize, SM_GEMM);
        cudaFuncSetAttribute(qk_mma_kernel, cudaFuncAttributeMaxDynamicSharedMemorySize, SM_QK);
        cudaFuncSetAttribute(fused_pbq_sm_kernel, cudaFuncAttributeMaxDynamicSharedMemorySize, SM_FUSED);
        cudaFuncSetAttribute(av_mma_kernel, cudaFuncAttributeMaxDynamicSharedMemorySize, SM_AV);
        attr_done = true;
    }

    const int n4 = 4096 * 768 / 4;
    const int pb4 = 1024 * 1024 * 64 / 4;
    pbconv_kernel<<<pb4 / 256, 256>>>(pb, pb4);
    conv16_kernel<<<n4 / 256, 256>>>(q, 0, n4);
    conv16_kernel<<<n4 / 256, 256>>>(k, 1, n4);
    conv16_kernel<<<n4 / 256, 256>>>(v, 2, n4);
    dim3 tthr(32, 32), tgrd(24, 24);
    transpose_conv_kernel<<<tgrd, tthr>>>(Wq, 0);
    transpose_conv_kernel<<<tgrd, tthr>>>(Wk, 1);
    transpose_conv_kernel<<<tgrd, tthr>>>(Wv, 2);
    transpose_conv_kernel<<<tgrd, tthr>>>(Wo, 3);

    gemm_mma_kernel<<<dim3(6, 32, 3), 256, SM_GEMM>>>(bq, bk, bv, nullptr, 0);
    qk_mma_kernel<<<dim3(8, 8, 48), 256, SM_QK>>>();
    fused_pbq_sm_kernel<<<dim3(3, 1024), 256, SM_FUSED>>>(amask, vmask);
    av_mma_kernel<<<dim3(8, 48), 256, SM_AV>>>();
    conv16_kernel<<<n4 / 256, 256>>>(nullptr, 0, n4);
    gemm_mma_kernel<<<dim3(6, 32, 1), 256, SM_GEMM>>>(bo, nullptr, nullptr, out, 1);
}

// round 10
// speedup vs baseline: 3.7197x; 1.2662x over previous
#include <cuda_runtime.h>
#include <cuda_fp16.h>
#include <cstdint>

// ---------------------------------------------------------------------------
// NEZHA-style MHA, all single-fp16 HMMA (mma.sync m16n8k16 f16, fp32 accum),
// cp.async double-buffered mainloops. B=4, S=1024, H=12, DK=DV=64, DM=768.
// ---------------------------------------------------------------------------

#define S 1024
#define Hh 12
#define BH 48
#define NEGV (-1e12f)

// ---------------- scratch -----------------------------------------------------
__device__ float g_attn[(size_t)4 * S * 768];
__device__ float g_scores[(size_t)BH * S * S];     // 201 MB

__device__ __align__(16) __half g_x16[(size_t)3 * 4096 * 768];
__device__ __align__(16) __half g_wt16[(size_t)4 * 768 * 768];
__device__ __align__(16) __half g_q16[(size_t)BH * S * 64];
__device__ __align__(16) __half g_k16[(size_t)BH * S * 64];
__device__ __align__(16) __half g_vwt16[(size_t)BH * 64 * S];   // [bh][d][s]
__device__ __align__(16) __half g_A16[(size_t)BH * S * S];      // 100 MB
__device__ __align__(16) __half g_pb16[(size_t)S * S * 64];     // [j][k][d] 128MB

// ---------------- helpers -----------------------------------------------------
__device__ __forceinline__ uint32_t smem_to_u32(const void* p) {
    uint32_t a;
    asm("{ .reg .u64 t; cvta.to.shared.u64 t, %1; cvt.u32.u64 %0, t; }"
        : "=r"(a) : "l"(p));
    return a;
}
#define SWZ(o)    ((uint32_t)(o) ^ ((((uint32_t)(o)) >> 3) & 0x70))
#define SWZ256(o) ((uint32_t)(o) ^ ((((uint32_t)(o)) >> 4) & 0x70))

__device__ __forceinline__ void ldmx4(uint32_t* r, uint32_t a) {
    asm volatile("ldmatrix.sync.aligned.m8n8.x4.shared.b16 {%0,%1,%2,%3}, [%4];"
                 : "=r"(r[0]), "=r"(r[1]), "=r"(r[2]), "=r"(r[3]) : "r"(a));
}
__device__ __forceinline__ void ldmx2t(uint32_t* r, uint32_t a) {
    asm volatile("ldmatrix.sync.aligned.m8n8.x2.trans.shared.b16 {%0,%1}, [%2];"
                 : "=r"(r[0]), "=r"(r[1]) : "r"(a));
}
__device__ __forceinline__ void mmah(float* c, const uint32_t* a,
                                     const uint32_t* b) {
    asm volatile(
        "mma.sync.aligned.m16n8k16.row.col.f32.f16.f16.f32 "
        "{%0,%1,%2,%3},{%4,%5,%6,%7},{%8,%9},{%0,%1,%2,%3};"
        : "+f"(c[0]), "+f"(c[1]), "+f"(c[2]), "+f"(c[3])
        : "r"(a[0]), "r"(a[1]), "r"(a[2]), "r"(a[3]), "r"(b[0]), "r"(b[1]));
}
__device__ __forceinline__ uint32_t hpack(float a, float b) {
    __half2 t = __floats2half2_rn(a, b);
    return *(uint32_t*)&t;
}
__device__ __forceinline__ uint2 cvt4(float4 v) {
    uint2 r;
    r.x = hpack(v.x, v.y);
    r.y = hpack(v.z, v.w);
    return r;
}
__device__ __forceinline__ void cpa16(uint32_t dst, const void* src) {
    asm volatile("cp.async.cg.shared.global [%0], [%1], 16;"
                 :: "r"(dst), "l"(src) : "memory");
}
__device__ __forceinline__ void cpa_commit() {
    asm volatile("cp.async.commit_group;" ::: "memory");
}
__device__ __forceinline__ void cpa_wait0() {
    asm volatile("cp.async.wait_group 0;" ::: "memory");
}
__device__ __forceinline__ void cpa_wait1() {
    asm volatile("cp.async.wait_group 1;" ::: "memory");
}

// ---------------- conversion kernels ------------------------------------------
// merged q/k/v fp32 -> fp16 (blockIdx.y = slot); also used for attn (src0 only).
__global__ void conv16_kernel(const float* __restrict__ s0,
                              const float* __restrict__ s1,
                              const float* __restrict__ s2, int n4) {
    int i = blockIdx.x * blockDim.x + threadIdx.x;
    if (i >= n4) return;
    int slot = blockIdx.y;
    const float* s = (slot == 0) ? (s0 ? s0 : g_attn) : (slot == 1 ? s1 : s2);
    float4 v = ((const float4*)s)[i];
    *(uint2*)(g_x16 + (size_t)slot * 4096 * 768 + (size_t)i * 4) = cvt4(v);
}

__global__ void transpose_conv_kernel(const float* __restrict__ W, int slot) {
    __shared__ float t[32][33];
    int tx = threadIdx.x, ty = threadIdx.y;
    int k = blockIdx.y * 32 + ty, n = blockIdx.x * 32 + tx;
    t[ty][tx] = W[(size_t)k * 768 + n];
    __syncthreads();
    int n2 = blockIdx.x * 32 + ty, k2 = blockIdx.y * 32 + tx;
    g_wt16[(size_t)slot * 768 * 768 + (size_t)n2 * 768 + k2] = __float2half(t[tx][ty]);
}

__global__ __launch_bounds__(256) void pbconv_kernel(const float* __restrict__ pb, int n4) {
    int i = blockIdx.x * blockDim.x + threadIdx.x;
    if (i >= n4) return;
    float4 v = ((const float4*)pb)[i];
    *(uint2*)(g_pb16 + (size_t)i * 4) = cvt4(v);
}

// ---------------- HMMA dense GEMM (cp.async double-buffered) -------------------
__device__ __forceinline__ void gemm_issue(uint32_t sbase, uint32_t bufoff,
        const __half* xx, const __half* wt, int bm, int bn, int k0, int tid) {
#pragma unroll
    for (int i = 0; i < 8; i++) {
        int idx = tid + i * 256;
        int bsel = idx >> 10, rc = idx & 1023;
        int row = rc >> 3, q = rc & 7;
        uint32_t dst = bufoff + (bsel ? 16384u : 0u) + SWZ(row * 128 + q * 16);
        const __half* src = bsel ? (wt + (size_t)(bn + row) * 768 + k0 + q * 8)
                                 : (xx + (size_t)(bm + row) * 768 + k0 + q * 8);
        cpa16(sbase + dst, src);
    }
    cpa_commit();
}

// mode 0: QKV (z=0/1/2; z==2 writes vw^T). mode 1: output projection.
__global__ __launch_bounds__(256) void gemm_mma_kernel(
    const float* __restrict__ b0, const float* __restrict__ b1,
    const float* __restrict__ b2, float* __restrict__ yout, int mode)
{
    extern __shared__ __align__(128) char smem[];
    const uint32_t sbase = smem_to_u32(smem);
    const int tid = threadIdx.x, wid = tid >> 5, lane = tid & 31;
    const int z = blockIdx.z;
    const int bm = blockIdx.y * 128, bn = blockIdx.x * 128;
    const int xsel = (mode == 0) ? z : 0;
    const int wsel = (mode == 0) ? z : 3;
    const __half* xx = g_x16 + (size_t)xsel * 4096 * 768;
    const __half* wt = g_wt16 + (size_t)wsel * 768 * 768;
    const float* bias = (mode == 1) ? b0 : (z == 0 ? b0 : (z == 1 ? b1 : b2));

    const int wm = (wid >> 1) * 32, wn = (wid & 1) * 64;
    float acc[2][8][4];
#pragma unroll
    for (int a = 0; a < 2; a++)
#pragma unroll
        for (int b = 0; b < 8; b++)
#pragma unroll
            for (int c = 0; c < 4; c++) acc[a][b][c] = 0.f;

    gemm_issue(sbase, 0, xx, wt, bm, bn, 0, tid);
    for (int st = 0; st < 12; st++) {
        const int cur = st & 1;
        if (st + 1 < 12) {
            gemm_issue(sbase, (cur ^ 1) * 32768u, xx, wt, bm, bn, (st + 1) * 64, tid);
            cpa_wait1();
        } else {
            cpa_wait0();
        }
        __syncthreads();
        const uint32_t Ac = cur * 32768u, Bc = Ac + 16384u;
#pragma unroll
        for (int kk = 0; kk < 4; kk++) {
            uint32_t a4[2][4];
            uint32_t aoff = SWZ((wm + (lane & 15)) * 128 + (kk * 2 + (lane >> 4)) * 16);
            ldmx4(a4[0], sbase + Ac + aoff);
            ldmx4(a4[1], sbase + Ac + aoff + 2048);
            uint32_t boff = SWZ((wn + (lane >> 4) * 8 + (lane & 7)) * 128 +
                                (kk * 2 + ((lane >> 3) & 1)) * 16);
#pragma unroll
            for (int ntp = 0; ntp < 4; ntp++) {
                uint32_t b4[4];
                ldmx4(b4, sbase + Bc + boff + ntp * 2048);
#pragma unroll
                for (int mt = 0; mt < 2; mt++) {
                    mmah(acc[mt][ntp * 2 + 0], a4[mt], b4);
                    mmah(acc[mt][ntp * 2 + 1], a4[mt], b4 + 2);
                }
            }
        }
        __syncthreads();
    }

    if (mode == 0 && z == 2) {
        __half* Th = (__half*)smem;               // [128][136]
#pragma unroll
        for (int mt = 0; mt < 2; mt++) {
#pragma unroll
            for (int nt = 0; nt < 8; nt++) {
                int cl = wn + nt * 8 + (lane & 3) * 2;
                float bx = bias[bn + cl], by = bias[bn + cl + 1];
#pragma unroll
                for (int half = 0; half < 2; half++) {
                    int rl = wm + mt * 16 + (lane >> 2) + half * 8;
                    Th[cl * 136 + rl]       = __float2half(acc[mt][nt][half * 2 + 0] + bx);
                    Th[(cl + 1) * 136 + rl] = __float2half(acc[mt][nt][half * 2 + 1] + by);
                }
            }
        }
        __syncthreads();
        int b = bm >> 10, s0 = bm & 1023;
#pragma unroll
        for (int it = 0; it < 8; it++) {
            int g = tid + it * 256;
            int cl = g >> 4, q = g & 15;
            int cg = bn + cl, h = cg >> 6, d = cg & 63;
            size_t o = (((size_t)(b * Hh + h)) * 64 + d) * 1024 + s0 + q * 8;
            *(uint4*)(g_vwt16 + o) = *(uint4*)&Th[cl * 136 + q * 8];
        }
        return;
    }

#pragma unroll
    for (int mt = 0; mt < 2; mt++) {
#pragma unroll
        for (int nt = 0; nt < 8; nt++) {
            int col = bn + wn + nt * 8 + (lane & 3) * 2;
            float bx = bias[col], by = bias[col + 1];
#pragma unroll
            for (int half = 0; half < 2; half++) {
                int row = bm + wm + mt * 16 + (lane >> 2) + half * 8;
                float v0 = acc[mt][nt][half * 2 + 0] + bx;
                float v1 = acc[mt][nt][half * 2 + 1] + by;
                if (mode == 1) {
                    yout[(size_t)row * 768 + col]     = v0;
                    yout[(size_t)row * 768 + col + 1] = v1;
                } else {
                    int b = row >> 10, s = row & 1023;
                    int h = col >> 6, d = col & 63;
                    size_t base = ((size_t)(b * Hh + h) * S + s) * 64 + d;
                    __half* dstp = (z == 0) ? g_q16 : g_k16;
                    dstp[base]     = __float2half(v0);
                    dstp[base + 1] = __float2half(v1);
                }
            }
        }
    }
}

// ---------------- HMMA QK^T (single fp16) --------------------------------------
__global__ __launch_bounds__(256) void qk_mma_kernel() {
    extern __shared__ __align__(128) char smem[];
    const uint32_t Ao = 0, Bo = 16384;
    const uint32_t sbase = smem_to_u32(smem);
    const int tid = threadIdx.x, wid = tid >> 5, lane = tid & 31;
    const int bh = blockIdx.z;
    const int bj = blockIdx.y * 128, bk = blockIdx.x * 128;
    const int wm = (wid >> 1) * 32, wn = (wid & 1) * 64;

    const size_t qb = ((size_t)bh * S + bj) * 64;
    const size_t kb = ((size_t)bh * S + bk) * 64;
#pragma unroll
    for (int i = 0; i < 8; i++) {
        int idx = tid + i * 256;
        int buf = idx >> 10, rc = idx & 1023;
        int row = rc >> 3, q = rc & 7;
        uint32_t dst = SWZ(row * 128 + q * 16);
        const __half* src = buf ? (g_k16 + kb + (size_t)row * 64 + q * 8)
                                : (g_q16 + qb + (size_t)row * 64 + q * 8);
        cpa16(sbase + (buf ? Bo : Ao) + dst, src);
    }
    cpa_commit();
    cpa_wait0();
    __syncthreads();

    float acc[2][8][4];
#pragma unroll
    for (int a = 0; a < 2; a++)
#pragma unroll
        for (int b = 0; b < 8; b++)
#pragma unroll
            for (int c = 0; c < 4; c++) acc[a][b][c] = 0.f;

#pragma unroll
    for (int kk = 0; kk < 4; kk++) {
        uint32_t a4[2][4];
        uint32_t aoff = SWZ((wm + (lane & 15)) * 128 + (kk * 2 + (lane >> 4)) * 16);
        ldmx4(a4[0], sbase + Ao + aoff);
        ldmx4(a4[1], sbase + Ao + aoff + 2048);
        uint32_t boff = SWZ((wn + (lane >> 4) * 8 + (lane & 7)) * 128 +
                            (kk * 2 + ((lane >> 3) & 1)) * 16);
#pragma unroll
        for (int ntp = 0; ntp < 4; ntp++) {
            uint32_t b4[4];
            ldmx4(b4, sbase + Bo + boff + ntp * 2048);
#pragma unroll
            for (int mt = 0; mt < 2; mt++) {
                mmah(acc[mt][ntp * 2 + 0], a4[mt], b4);
                mmah(acc[mt][ntp * 2 + 1], a4[mt], b4 + 2);
            }
        }
    }

#pragma unroll
    for (int mt = 0; mt < 2; mt++) {
#pragma unroll
        for (int nt = 0; nt < 8; nt++) {
            int col = bk + wn + nt * 8 + (lane & 3) * 2;
#pragma unroll
            for (int half = 0; half < 2; half++) {
                int row = bj + wm + mt * 16 + (lane >> 2) + half * 8;
                size_t idx = ((size_t)bh << 20) + ((size_t)row << 10) + col;
                g_scores[idx]     = acc[mt][nt][half * 2 + 0];
                g_scores[idx + 1] = acc[mt][nt][half * 2 + 1];
            }
        }
    }
}

// ---------------------------------------------------------------------------
// Fused: scores += qw·pb (MMA), scale+mask+softmax, A -> fp16 global,
// phase C: attn = A·pb (trans-ldmatrix). pb chunks cp.async double-buffered.
// Grid (3, 1024), 256 threads, smem 113152.
// ---------------------------------------------------------------------------
__device__ __forceinline__ void pb_issue(uint32_t sbase, uint32_t off,
                                         int j, int k0, int tid) {
#pragma unroll
    for (int it = 0; it < 4; it++) {
        int idx = tid + it * 256;
        int kk = idx >> 3, q = idx & 7;
        cpa16(sbase + off + SWZ(kk * 128 + q * 16),
              g_pb16 + ((size_t)j * 1024 + k0 + kk) * 64 + q * 8);
    }
    cpa_commit();
}

__global__ __launch_bounds__(256) void fused_pbq_sm_kernel(
    const float* __restrict__ amask, const int* __restrict__ vmask)
{
    extern __shared__ __align__(128) char smem[];
    float* Sf = (float*)smem;                     // [16][1032] fp32 = 66048
    const uint32_t PB0 = 66048, PB1 = 82432;      // 2 x 16KB pb buffers
    const uint32_t QHo = 98816;                   // [16][64] fp16, 2KB
    float* AM = (float*)(smem + 100864);          // [1024] 4KB
    float* Mf = (float*)(smem + 104960);          // [2][1024] mask 8KB -> 113152
    const uint32_t AHc = 104960;                  // reuse Mf space in phase C (4KB)
    const uint32_t sbase = smem_to_u32(smem);
    const int tid = threadIdx.x, wid = tid >> 5, lane = tid & 31;
    const int t = blockIdx.x, j = blockIdx.y;
    const int bh0 = t * 16, bmin = bh0 / Hh;

    // prefetch pb chunk 0 while doing the setup loads
    pb_issue(sbase, PB0, j, 0, tid);

#pragma unroll
    for (int it = 0; it < 16; it++) {
        int idx = tid + it * 256;
        int row = idx >> 8, k4 = idx & 255;
        *(float4*)&Sf[row * 1032 + k4 * 4] =
            *(const float4*)(g_scores + (((size_t)(bh0 + row)) << 20) +
                             ((size_t)j << 10) + k4 * 4);
    }
    if (tid < 128) {
        int r = tid >> 3, q = tid & 7;
        uint32_t dst = SWZ(r * 128 + q * 16);
        size_t src = ((size_t)(bh0 + r) * 1024 + j) * 64 + q * 8;
        *(uint4*)(smem + QHo + dst) = *(const uint4*)(g_q16 + src);
    }
    *(float4*)&AM[tid * 4] = *(const float4*)(amask + (size_t)j * 1024 + tid * 4);
#pragma unroll
    for (int r2 = 0; r2 < 2; r2++) {
        int4 m = *(const int4*)(vmask + (size_t)(bmin + r2) * 1024 + tid * 4);
        Mf[r2 * 1024 + tid * 4 + 0] = m.x ? 1.f : 0.f;
        Mf[r2 * 1024 + tid * 4 + 1] = m.y ? 1.f : 0.f;
        Mf[r2 * 1024 + tid * 4 + 2] = m.z ? 1.f : 0.f;
        Mf[r2 * 1024 + tid * 4 + 3] = m.w ? 1.f : 0.f;
    }
    __syncthreads();

    uint32_t aq[4][4];
#pragma unroll
    for (int ks = 0; ks < 4; ks++) {
        uint32_t aoff = SWZ((lane & 15) * 128 + (ks * 2 + (lane >> 4)) * 16);
        ldmx4(aq[ks], sbase + QHo + aoff);
    }

    // ---- phase B: scores += qw·pb (double-buffered pb) ----
    for (int c = 0; c < 8; c++) {
        const uint32_t cur = (c & 1) ? PB1 : PB0;
        if (c + 1 < 8) {
            pb_issue(sbase, (c & 1) ? PB0 : PB1, j, (c + 1) * 128, tid);
            cpa_wait1();
        } else {
            cpa_wait0();
        }
        __syncthreads();
        const int k0 = c * 128;
        float frag[2][4] = {{0.f, 0.f, 0.f, 0.f}, {0.f, 0.f, 0.f, 0.f}};
#pragma unroll
        for (int ks = 0; ks < 4; ks++) {
            uint32_t boff = SWZ((wid * 16 + (lane >> 4) * 8 + (lane & 7)) * 128 +
                                (ks * 2 + ((lane >> 3) & 1)) * 16);
            uint32_t b4[4];
            ldmx4(b4, sbase + cur + boff);
            mmah(frag[0], aq[ks], b4);
            mmah(frag[1], aq[ks], b4 + 2);
        }
        int r0 = lane >> 2, c0 = (lane & 3) * 2;
#pragma unroll
        for (int nt = 0; nt < 2; nt++)
#pragma unroll
            for (int e = 0; e < 4; e++) {
                int row = r0 + (e >> 1) * 8;
                int col = k0 + wid * 16 + nt * 8 + c0 + (e & 1);
                Sf[row * 1032 + col] += frag[nt][e];
            }
        __syncthreads();
    }

    // ---- softmax ----
#pragma unroll
    for (int rr = 0; rr < 2; rr++) {
        int row = wid * 2 + rr;
        int bsel = (bh0 + row) / Hh - bmin;
        float x[32];
        float mx = -3.4e38f;
#pragma unroll
        for (int i = 0; i < 32; i++) {
            int k = lane + i * 32;
            float m = Mf[bsel * 1024 + k];
            float val = fmaf(Sf[row * 1032 + k], 0.125f, AM[k]);
            x[i] = (m != 0.f) ? val : NEGV;
            mx = fmaxf(mx, x[i]);
        }
#pragma unroll
        for (int o = 16; o > 0; o >>= 1) mx = fmaxf(mx, __shfl_xor_sync(~0u, mx, o));
        float sum = 0.f;
#pragma unroll
        for (int i = 0; i < 32; i++) { x[i] = __expf(x[i] - mx); sum += x[i]; }
#pragma unroll
        for (int o = 16; o > 0; o >>= 1) sum += __shfl_xor_sync(~0u, sum, o);
        float inv = 1.f / sum;
#pragma unroll
        for (int i = 0; i < 32; i++) Sf[row * 1032 + lane + i * 32] = x[i] * inv;
    }
    __syncthreads();

    // prefetch phase-C pb chunk 0, overlapped with the A16 global write
    pb_issue(sbase, PB0, j, 0, tid);

    // ---- write A fp16 ----
    {
        const int row = tid >> 4, kb = (tid & 15) * 64;
        const size_t obase = (((size_t)(bh0 + row)) << 20) + ((size_t)j << 10);
#pragma unroll
        for (int g = 0; g < 8; g++) {
            int k = kb + g * 8;
            uint2 p0 = cvt4(*(float4*)&Sf[row * 1032 + k]);
            uint2 p1 = cvt4(*(float4*)&Sf[row * 1032 + k + 4]);
            *(uint4*)(g_A16 + obase + k) = make_uint4(p0.x, p0.y, p1.x, p1.y);
        }
    }

    // ---- phase C: attn[bh0..+15][d] = A·pb (double-buffered pb) ----
    float facc[4] = {0.f, 0.f, 0.f, 0.f};
    const int w16 = wid * 16;
    for (int c = 0; c < 8; c++) {
        const uint32_t cur = (c & 1) ? PB1 : PB0;
        const int k0 = c * 128;
        if (c + 1 < 8) pb_issue(sbase, (c & 1) ? PB0 : PB1, j, (c + 1) * 128, tid);
        {
            int row = tid >> 4, col = (tid & 15) * 8;
            uint2 p0 = cvt4(*(float4*)&Sf[row * 1032 + k0 + col]);
            uint2 p1 = cvt4(*(float4*)&Sf[row * 1032 + k0 + col + 4]);
            uint32_t dst = SWZ256(row * 256 + col * 2);
            *(uint4*)(smem + AHc + dst) = make_uint4(p0.x, p0.y, p1.x, p1.y);
        }
        if (c + 1 < 8) cpa_wait1(); else cpa_wait0();
        __syncthreads();
#pragma unroll
        for (int ks = 0; ks < 8; ks++) {
            uint32_t a4[4];
            uint32_t aoff = SWZ256((lane & 15) * 256 + (ks * 2 + (lane >> 4)) * 16);
            ldmx4(a4, sbase + AHc + aoff);
            uint32_t bt[2];
            uint32_t boff = SWZ((ks * 16 + (lane & 15)) * 128 + w16);
            ldmx2t(bt, sbase + cur + boff);
            mmah(facc, a4, bt);
        }
        __syncthreads();
    }
    {
        int d = wid * 8 + (lane & 3) * 2;
#pragma unroll
        for (int half = 0; half < 2; half++) {
            int bh = bh0 + (lane >> 2) + half * 8;
            int b = bh / Hh, h = bh % Hh;
            size_t o = ((size_t)(b * 1024 + j)) * 768 + h * 64 + d;
            g_attn[o]     = facc[half * 2 + 0];
            g_attn[o + 1] = facc[half * 2 + 1];
        }
    }
}

// ---------------------------------------------------------------------------
// av: attn += A·vw. Grid (8, 48). M=128, N=64, K=1024. Single fp16.
// ---------------------------------------------------------------------------
__global__ __launch_bounds__(256) void av_mma_kernel() {
    extern __shared__ __align__(128) char smem[];
    const uint32_t Ao = 0, Vo = 32768;
    const uint32_t sbase = smem_to_u32(smem);
    const int tid = threadIdx.x, wid = tid >> 5, lane = tid & 31;
    const int bh = blockIdx.y, j0 = blockIdx.x * 128;

    float facc[8][4];
#pragma unroll
    for (int a = 0; a < 8; a++)
#pragma unroll
        for (int b = 0; b < 4; b++) facc[a][b] = 0.f;

    for (int c = 0; c < 8; c++) {
        const int k0 = c * 128;
        __syncthreads();
#pragma unroll
        for (int it = 0; it < 12; it++) {
            int idx = tid + it * 256;
            if (idx < 2048) {
                int row = idx >> 4, q = idx & 15;
                uint32_t dst = SWZ256(row * 256 + q * 16);
                cpa16(sbase + Ao + dst,
                      g_A16 + (((size_t)bh) << 20) +
                      ((size_t)(j0 + row) << 10) + k0 + q * 8);
            } else {
                int rc = idx - 2048;
                int d = rc >> 4, q = rc & 15;
                uint32_t dst = SWZ256(d * 256 + q * 16);
                cpa16(sbase + Vo + dst,
                      g_vwt16 + ((size_t)bh * 64 + d) * 1024 + k0 + q * 8);
            }
        }
        cpa_commit();
        cpa_wait0();
        __syncthreads();
#pragma unroll
        for (int ks = 0; ks < 8; ks++) {
            uint32_t a4[4];
            uint32_t aoff = SWZ256((wid * 16 + (lane & 15)) * 256 +
                                   (ks * 2 + (lane >> 4)) * 16);
            ldmx4(a4, sbase + Ao + aoff);
#pragma unroll
            for (int np = 0; np < 4; np++) {
                uint32_t boff = SWZ256((np * 16 + (lane >> 4) * 8 + (lane & 7)) * 256 +
                                       (ks * 2 + ((lane >> 3) & 1)) * 16);
                uint32_t b4[4];
                ldmx4(b4, sbase + Vo + boff);
                mmah(facc[np * 2 + 0], a4, b4);
                mmah(facc[np * 2 + 1], a4, b4 + 2);
            }
        }
    }
    const int b = bh / Hh, h = bh % Hh;
#pragma unroll
    for (int nt = 0; nt < 8; nt++) {
        int d = nt * 8 + (lane & 3) * 2;
#pragma unroll
        for (int half = 0; half < 2; half++) {
            int s = j0 + wid * 16 + (lane >> 2) + half * 8;
            size_t o = ((size_t)(b * 1024 + s)) * 768 + h * 64 + d;
            g_attn[o]     += facc[nt][half * 2 + 0];
            g_attn[o + 1] += facc[nt][half * 2 + 1];
        }
    }
}

// ---------------------------------------------------------------------------
extern "C" void kernel_launch(void* const* d_in, const int* in_sizes, int n_in,
                              void* d_out, int out_size) {
    const float* q     = (const float*)d_in[0];
    const float* k     = (const float*)d_in[1];
    const float* v     = (const float*)d_in[2];
    const float* amask = (const float*)d_in[3];
    const float* pb    = (const float*)d_in[4];
    const int*   vmask = (const int*)  d_in[5];
    const float* Wq    = (const float*)d_in[6];
    const float* bq    = (const float*)d_in[7];
    const float* Wk    = (const float*)d_in[8];
    const float* bk    = (const float*)d_in[9];
    const float* Wv    = (const float*)d_in[10];
    const float* bv    = (const float*)d_in[11];
    const float* Wo    = (const float*)d_in[12];
    const float* bo    = (const float*)d_in[13];
    float* out = (float*)d_out;

    const int SM_GEMM = 65536, SM_QK = 32768, SM_FUSED = 113152, SM_AV = 65536;
    static bool attr_done = false;
    if (!attr_done) {
        cudaFuncSetAttribute(gemm_mma_kernel, cudaFuncAttributeMaxDynamicSharedMemorySize, SM_GEMM);
        cudaFuncSetAttribute(qk_mma_kernel, cudaFuncAttributeMaxDynamicSharedMemorySize, SM_QK);
        cudaFuncSetAttribute(fused_pbq_sm_kernel, cudaFuncAttributeMaxDynamicSharedMemorySize, SM_FUSED);
        cudaFuncSetAttribute(av_mma_kernel, cudaFuncAttributeMaxDynamicSharedMemorySize, SM_AV);
        attr_done = true;
    }

    const int n4 = 4096 * 768 / 4;
    const int pb4 = 1024 * 1024 * 64 / 4;
    pbconv_kernel<<<pb4 / 256, 256>>>(pb, pb4);
    conv16_kernel<<<dim3(n4 / 256, 3), 256>>>(q, k, v, n4);
    dim3 tthr(32, 32), tgrd(24, 24);
    transpose_conv_kernel<<<tgrd, tthr>>>(Wq, 0);
    transpose_conv_kernel<<<tgrd, tthr>>>(Wk, 1);
    transpose_conv_kernel<<<tgrd, tthr>>>(Wv, 2);
    transpose_conv_kernel<<<tgrd, tthr>>>(Wo, 3);

    gemm_mma_kernel<<<dim3(6, 32, 3), 256, SM_GEMM>>>(bq, bk, bv, nullptr, 0);
    qk_mma_kernel<<<dim3(8, 8, 48), 256, SM_QK>>>();
    fused_pbq_sm_kernel<<<dim3(3, 1024), 256, SM_FUSED>>>(amask, vmask);
    av_mma_kernel<<<dim3(8, 48), 256, SM_AV>>>();
    conv16_kernel<<<dim3(n4 / 256, 1), 256>>>(nullptr, nullptr, nullptr, n4);
    gemm_mma_kernel<<<dim3(6, 32, 1), 256, SM_GEMM>>>(bo, nullptr, nullptr, out, 1);
}

// round 11
// speedup vs baseline: 4.0133x; 1.0789x over previous
#include <cuda_runtime.h>
#include <cuda_fp16.h>
#include <cstdint>

// ---------------------------------------------------------------------------
// NEZHA-style MHA, all single-fp16 HMMA (mma.sync m16n8k16 f16, fp32 accum),
// cp.async double-buffered mainloops, fp16 scores tensor.
// B=4, S=1024, H=12, DK=DV=64, DM=768.
// ---------------------------------------------------------------------------

#define S 1024
#define Hh 12
#define BH 48
#define NEGV (-1e12f)

// ---------------- scratch -----------------------------------------------------
__device__ float g_attn[(size_t)4 * S * 768];

__device__ __align__(16) __half g_s16[(size_t)BH * S * S];      // scores, 100 MB
__device__ __align__(16) __half g_x16[(size_t)3 * 4096 * 768];
__device__ __align__(16) __half g_wt16[(size_t)4 * 768 * 768];
__device__ __align__(16) __half g_q16[(size_t)BH * S * 64];
__device__ __align__(16) __half g_k16[(size_t)BH * S * 64];
__device__ __align__(16) __half g_vwt16[(size_t)BH * 64 * S];   // [bh][d][s]
__device__ __align__(16) __half g_A16[(size_t)BH * S * S];      // 100 MB
__device__ __align__(16) __half g_pb16[(size_t)S * S * 64];     // [j][k][d] 128MB

// ---------------- helpers -----------------------------------------------------
__device__ __forceinline__ uint32_t smem_to_u32(const void* p) {
    uint32_t a;
    asm("{ .reg .u64 t; cvta.to.shared.u64 t, %1; cvt.u32.u64 %0, t; }"
        : "=r"(a) : "l"(p));
    return a;
}
#define SWZ(o)    ((uint32_t)(o) ^ ((((uint32_t)(o)) >> 3) & 0x70))
#define SWZ256(o) ((uint32_t)(o) ^ ((((uint32_t)(o)) >> 4) & 0x70))

__device__ __forceinline__ void ldmx4(uint32_t* r, uint32_t a) {
    asm volatile("ldmatrix.sync.aligned.m8n8.x4.shared.b16 {%0,%1,%2,%3}, [%4];"
                 : "=r"(r[0]), "=r"(r[1]), "=r"(r[2]), "=r"(r[3]) : "r"(a));
}
__device__ __forceinline__ void ldmx2t(uint32_t* r, uint32_t a) {
    asm volatile("ldmatrix.sync.aligned.m8n8.x2.trans.shared.b16 {%0,%1}, [%2];"
                 : "=r"(r[0]), "=r"(r[1]) : "r"(a));
}
__device__ __forceinline__ void mmah(float* c, const uint32_t* a,
                                     const uint32_t* b) {
    asm volatile(
        "mma.sync.aligned.m16n8k16.row.col.f32.f16.f16.f32 "
        "{%0,%1,%2,%3},{%4,%5,%6,%7},{%8,%9},{%0,%1,%2,%3};"
        : "+f"(c[0]), "+f"(c[1]), "+f"(c[2]), "+f"(c[3])
        : "r"(a[0]), "r"(a[1]), "r"(a[2]), "r"(a[3]), "r"(b[0]), "r"(b[1]));
}
__device__ __forceinline__ uint32_t hpack(float a, float b) {
    __half2 t = __floats2half2_rn(a, b);
    return *(uint32_t*)&t;
}
__device__ __forceinline__ uint2 cvt4(float4 v) {
    uint2 r;
    r.x = hpack(v.x, v.y);
    r.y = hpack(v.z, v.w);
    return r;
}
__device__ __forceinline__ void cpa16(uint32_t dst, const void* src) {
    asm volatile("cp.async.cg.shared.global [%0], [%1], 16;"
                 :: "r"(dst), "l"(src) : "memory");
}
__device__ __forceinline__ void cpa_commit() {
    asm volatile("cp.async.commit_group;" ::: "memory");
}
__device__ __forceinline__ void cpa_wait0() {
    asm volatile("cp.async.wait_group 0;" ::: "memory");
}
__device__ __forceinline__ void cpa_wait1() {
    asm volatile("cp.async.wait_group 1;" ::: "memory");
}

// ---------------- conversion kernels ------------------------------------------
__global__ void conv16_kernel(const float* __restrict__ s0,
                              const float* __restrict__ s1,
                              const float* __restrict__ s2, int n4) {
    int i = blockIdx.x * blockDim.x + threadIdx.x;
    if (i >= n4) return;
    int slot = blockIdx.y;
    const float* s = (slot == 0) ? (s0 ? s0 : g_attn) : (slot == 1 ? s1 : s2);
    float4 v = ((const float4*)s)[i];
    *(uint2*)(g_x16 + (size_t)slot * 4096 * 768 + (size_t)i * 4) = cvt4(v);
}

__global__ void transpose_conv_kernel(const float* __restrict__ W, int slot) {
    __shared__ float t[32][33];
    int tx = threadIdx.x, ty = threadIdx.y;
    int k = blockIdx.y * 32 + ty, n = blockIdx.x * 32 + tx;
    t[ty][tx] = W[(size_t)k * 768 + n];
    __syncthreads();
    int n2 = blockIdx.x * 32 + ty, k2 = blockIdx.y * 32 + tx;
    g_wt16[(size_t)slot * 768 * 768 + (size_t)n2 * 768 + k2] = __float2half(t[tx][ty]);
}

__global__ __launch_bounds__(256) void pbconv_kernel(const float* __restrict__ pb, int n4) {
    int i = blockIdx.x * blockDim.x + threadIdx.x;
    if (i >= n4) return;
    float4 v = ((const float4*)pb)[i];
    *(uint2*)(g_pb16 + (size_t)i * 4) = cvt4(v);
}

// ---------------- HMMA dense GEMM (cp.async double-buffered) -------------------
__device__ __forceinline__ void gemm_issue(uint32_t sbase, uint32_t bufoff,
        const __half* xx, const __half* wt, int bm, int bn, int k0, int tid) {
#pragma unroll
    for (int i = 0; i < 8; i++) {
        int idx = tid + i * 256;
        int bsel = idx >> 10, rc = idx & 1023;
        int row = rc >> 3, q = rc & 7;
        uint32_t dst = bufoff + (bsel ? 16384u : 0u) + SWZ(row * 128 + q * 16);
        const __half* src = bsel ? (wt + (size_t)(bn + row) * 768 + k0 + q * 8)
                                 : (xx + (size_t)(bm + row) * 768 + k0 + q * 8);
        cpa16(sbase + dst, src);
    }
    cpa_commit();
}

// mode 0: QKV (z=0/1/2; z==2 writes vw^T). mode 1: output projection.
__global__ __launch_bounds__(256) void gemm_mma_kernel(
    const float* __restrict__ b0, const float* __restrict__ b1,
    const float* __restrict__ b2, float* __restrict__ yout, int mode)
{
    extern __shared__ __align__(128) char smem[];
    const uint32_t sbase = smem_to_u32(smem);
    const int tid = threadIdx.x, wid = tid >> 5, lane = tid & 31;
    const int z = blockIdx.z;
    const int bm = blockIdx.y * 128, bn = blockIdx.x * 128;
    const int xsel = (mode == 0) ? z : 0;
    const int wsel = (mode == 0) ? z : 3;
    const __half* xx = g_x16 + (size_t)xsel * 4096 * 768;
    const __half* wt = g_wt16 + (size_t)wsel * 768 * 768;
    const float* bias = (mode == 1) ? b0 : (z == 0 ? b0 : (z == 1 ? b1 : b2));

    const int wm = (wid >> 1) * 32, wn = (wid & 1) * 64;
    float acc[2][8][4];
#pragma unroll
    for (int a = 0; a < 2; a++)
#pragma unroll
        for (int b = 0; b < 8; b++)
#pragma unroll
            for (int c = 0; c < 4; c++) acc[a][b][c] = 0.f;

    gemm_issue(sbase, 0, xx, wt, bm, bn, 0, tid);
    for (int st = 0; st < 12; st++) {
        const int cur = st & 1;
        if (st + 1 < 12) {
            gemm_issue(sbase, (cur ^ 1) * 32768u, xx, wt, bm, bn, (st + 1) * 64, tid);
            cpa_wait1();
        } else {
            cpa_wait0();
        }
        __syncthreads();
        const uint32_t Ac = cur * 32768u, Bc = Ac + 16384u;
#pragma unroll
        for (int kk = 0; kk < 4; kk++) {
            uint32_t a4[2][4];
            uint32_t aoff = SWZ((wm + (lane & 15)) * 128 + (kk * 2 + (lane >> 4)) * 16);
            ldmx4(a4[0], sbase + Ac + aoff);
            ldmx4(a4[1], sbase + Ac + aoff + 2048);
            uint32_t boff = SWZ((wn + (lane >> 4) * 8 + (lane & 7)) * 128 +
                                (kk * 2 + ((lane >> 3) & 1)) * 16);
#pragma unroll
            for (int ntp = 0; ntp < 4; ntp++) {
                uint32_t b4[4];
                ldmx4(b4, sbase + Bc + boff + ntp * 2048);
#pragma unroll
                for (int mt = 0; mt < 2; mt++) {
                    mmah(acc[mt][ntp * 2 + 0], a4[mt], b4);
                    mmah(acc[mt][ntp * 2 + 1], a4[mt], b4 + 2);
                }
            }
        }
        __syncthreads();
    }

    if (mode == 0 && z == 2) {
        __half* Th = (__half*)smem;               // [128][136]
#pragma unroll
        for (int mt = 0; mt < 2; mt++) {
#pragma unroll
            for (int nt = 0; nt < 8; nt++) {
                int cl = wn + nt * 8 + (lane & 3) * 2;
                float bx = bias[bn + cl], by = bias[bn + cl + 1];
#pragma unroll
                for (int half = 0; half < 2; half++) {
                    int rl = wm + mt * 16 + (lane >> 2) + half * 8;
                    Th[cl * 136 + rl]       = __float2half(acc[mt][nt][half * 2 + 0] + bx);
                    Th[(cl + 1) * 136 + rl] = __float2half(acc[mt][nt][half * 2 + 1] + by);
                }
            }
        }
        __syncthreads();
        int b = bm >> 10, s0 = bm & 1023;
#pragma unroll
        for (int it = 0; it < 8; it++) {
            int g = tid + it * 256;
            int cl = g >> 4, q = g & 15;
            int cg = bn + cl, h = cg >> 6, d = cg & 63;
            size_t o = (((size_t)(b * Hh + h)) * 64 + d) * 1024 + s0 + q * 8;
            *(uint4*)(g_vwt16 + o) = *(uint4*)&Th[cl * 136 + q * 8];
        }
        return;
    }

#pragma unroll
    for (int mt = 0; mt < 2; mt++) {
#pragma unroll
        for (int nt = 0; nt < 8; nt++) {
            int col = bn + wn + nt * 8 + (lane & 3) * 2;
            float bx = bias[col], by = bias[col + 1];
#pragma unroll
            for (int half = 0; half < 2; half++) {
                int row = bm + wm + mt * 16 + (lane >> 2) + half * 8;
                float v0 = acc[mt][nt][half * 2 + 0] + bx;
                float v1 = acc[mt][nt][half * 2 + 1] + by;
                if (mode == 1) {
                    yout[(size_t)row * 768 + col]     = v0;
                    yout[(size_t)row * 768 + col + 1] = v1;
                } else {
                    int b = row >> 10, s = row & 1023;
                    int h = col >> 6, d = col & 63;
                    size_t base = ((size_t)(b * Hh + h) * S + s) * 64 + d;
                    __half* dstp = (z == 0) ? g_q16 : g_k16;
                    dstp[base]     = __float2half(v0);
                    dstp[base + 1] = __float2half(v1);
                }
            }
        }
    }
}

// ---------------- HMMA QK^T (writes fp16 scores) -------------------------------
__global__ __launch_bounds__(256) void qk_mma_kernel() {
    extern __shared__ __align__(128) char smem[];
    const uint32_t Ao = 0, Bo = 16384;
    const uint32_t sbase = smem_to_u32(smem);
    const int tid = threadIdx.x, wid = tid >> 5, lane = tid & 31;
    const int bh = blockIdx.z;
    const int bj = blockIdx.y * 128, bk = blockIdx.x * 128;
    const int wm = (wid >> 1) * 32, wn = (wid & 1) * 64;

    const size_t qb = ((size_t)bh * S + bj) * 64;
    const size_t kb = ((size_t)bh * S + bk) * 64;
#pragma unroll
    for (int i = 0; i < 8; i++) {
        int idx = tid + i * 256;
        int buf = idx >> 10, rc = idx & 1023;
        int row = rc >> 3, q = rc & 7;
        uint32_t dst = SWZ(row * 128 + q * 16);
        const __half* src = buf ? (g_k16 + kb + (size_t)row * 64 + q * 8)
                                : (g_q16 + qb + (size_t)row * 64 + q * 8);
        cpa16(sbase + (buf ? Bo : Ao) + dst, src);
    }
    cpa_commit();
    cpa_wait0();
    __syncthreads();

    float acc[2][8][4];
#pragma unroll
    for (int a = 0; a < 2; a++)
#pragma unroll
        for (int b = 0; b < 8; b++)
#pragma unroll
            for (int c = 0; c < 4; c++) acc[a][b][c] = 0.f;

#pragma unroll
    for (int kk = 0; kk < 4; kk++) {
        uint32_t a4[2][4];
        uint32_t aoff = SWZ((wm + (lane & 15)) * 128 + (kk * 2 + (lane >> 4)) * 16);
        ldmx4(a4[0], sbase + Ao + aoff);
        ldmx4(a4[1], sbase + Ao + aoff + 2048);
        uint32_t boff = SWZ((wn + (lane >> 4) * 8 + (lane & 7)) * 128 +
                            (kk * 2 + ((lane >> 3) & 1)) * 16);
#pragma unroll
        for (int ntp = 0; ntp < 4; ntp++) {
            uint32_t b4[4];
            ldmx4(b4, sbase + Bo + boff + ntp * 2048);
#pragma unroll
            for (int mt = 0; mt < 2; mt++) {
                mmah(acc[mt][ntp * 2 + 0], a4[mt], b4);
                mmah(acc[mt][ntp * 2 + 1], a4[mt], b4 + 2);
            }
        }
    }

#pragma unroll
    for (int mt = 0; mt < 2; mt++) {
#pragma unroll
        for (int nt = 0; nt < 8; nt++) {
            int col = bk + wn + nt * 8 + (lane & 3) * 2;
#pragma unroll
            for (int half = 0; half < 2; half++) {
                int row = bj + wm + mt * 16 + (lane >> 2) + half * 8;
                size_t idx = ((size_t)bh << 20) + ((size_t)row << 10) + col;
                *(uint32_t*)(g_s16 + idx) =
                    hpack(acc[mt][nt][half * 2 + 0], acc[mt][nt][half * 2 + 1]);
            }
        }
    }
}

// ---------------------------------------------------------------------------
// Fused: scores += qw·pb (MMA), scale+mask+softmax, A -> fp16 global,
// phase C: attn = A·pb (trans-ldmatrix). pb chunks cp.async double-buffered.
// Grid (3, 1024), 256 threads, smem 113152.
// ---------------------------------------------------------------------------
__device__ __forceinline__ void pb_issue(uint32_t sbase, uint32_t off,
                                         int j, int k0, int tid) {
#pragma unroll
    for (int it = 0; it < 4; it++) {
        int idx = tid + it * 256;
        int kk = idx >> 3, q = idx & 7;
        cpa16(sbase + off + SWZ(kk * 128 + q * 16),
              g_pb16 + ((size_t)j * 1024 + k0 + kk) * 64 + q * 8);
    }
    cpa_commit();
}

__global__ __launch_bounds__(256) void fused_pbq_sm_kernel(
    const float* __restrict__ amask, const int* __restrict__ vmask)
{
    extern __shared__ __align__(128) char smem[];
    float* Sf = (float*)smem;                     // [16][1032] fp32 = 66048
    const uint32_t PB0 = 66048, PB1 = 82432;      // 2 x 16KB pb buffers
    const uint32_t QHo = 98816;                   // [16][64] fp16, 2KB
    float* AM = (float*)(smem + 100864);          // [1024] 4KB
    float* Mf = (float*)(smem + 104960);          // [2][1024] mask 8KB -> 113152
    const uint32_t AHc = 104960;                  // reuse Mf space in phase C (4KB)
    const uint32_t sbase = smem_to_u32(smem);
    const int tid = threadIdx.x, wid = tid >> 5, lane = tid & 31;
    const int t = blockIdx.x, j = blockIdx.y;
    const int bh0 = t * 16, bmin = bh0 / Hh;

    // prefetch pb chunk 0 while doing the setup loads
    pb_issue(sbase, PB0, j, 0, tid);

    // load fp16 scores -> fp32 Sf
#pragma unroll
    for (int it = 0; it < 8; it++) {
        int idx = tid + it * 256;
        int row = idx >> 7, g = idx & 127;
        uint4 v = *(const uint4*)(g_s16 + (((size_t)(bh0 + row)) << 20) +
                                  ((size_t)j << 10) + g * 8);
        const __half2* hp = (const __half2*)&v;
        float2 f0 = __half22float2(hp[0]);
        float2 f1 = __half22float2(hp[1]);
        float2 f2 = __half22float2(hp[2]);
        float2 f3 = __half22float2(hp[3]);
        float* dstp = &Sf[row * 1032 + g * 8];
        dstp[0] = f0.x; dstp[1] = f0.y; dstp[2] = f1.x; dstp[3] = f1.y;
        dstp[4] = f2.x; dstp[5] = f2.y; dstp[6] = f3.x; dstp[7] = f3.y;
    }
    if (tid < 128) {
        int r = tid >> 3, q = tid & 7;
        uint32_t dst = SWZ(r * 128 + q * 16);
        size_t src = ((size_t)(bh0 + r) * 1024 + j) * 64 + q * 8;
        *(uint4*)(smem + QHo + dst) = *(const uint4*)(g_q16 + src);
    }
    *(float4*)&AM[tid * 4] = *(const float4*)(amask + (size_t)j * 1024 + tid * 4);
#pragma unroll
    for (int r2 = 0; r2 < 2; r2++) {
        int4 m = *(const int4*)(vmask + (size_t)(bmin + r2) * 1024 + tid * 4);
        Mf[r2 * 1024 + tid * 4 + 0] = m.x ? 1.f : 0.f;
        Mf[r2 * 1024 + tid * 4 + 1] = m.y ? 1.f : 0.f;
        Mf[r2 * 1024 + tid * 4 + 2] = m.z ? 1.f : 0.f;
        Mf[r2 * 1024 + tid * 4 + 3] = m.w ? 1.f : 0.f;
    }
    __syncthreads();

    uint32_t aq[4][4];
#pragma unroll
    for (int ks = 0; ks < 4; ks++) {
        uint32_t aoff = SWZ((lane & 15) * 128 + (ks * 2 + (lane >> 4)) * 16);
        ldmx4(aq[ks], sbase + QHo + aoff);
    }

    // ---- phase B: scores += qw·pb (double-buffered pb) ----
    for (int c = 0; c < 8; c++) {
        const uint32_t cur = (c & 1) ? PB1 : PB0;
        if (c + 1 < 8) {
            pb_issue(sbase, (c & 1) ? PB0 : PB1, j, (c + 1) * 128, tid);
            cpa_wait1();
        } else {
            cpa_wait0();
        }
        __syncthreads();
        const int k0 = c * 128;
        float frag[2][4] = {{0.f, 0.f, 0.f, 0.f}, {0.f, 0.f, 0.f, 0.f}};
#pragma unroll
        for (int ks = 0; ks < 4; ks++) {
            uint32_t boff = SWZ((wid * 16 + (lane >> 4) * 8 + (lane & 7)) * 128 +
                                (ks * 2 + ((lane >> 3) & 1)) * 16);
            uint32_t b4[4];
            ldmx4(b4, sbase + cur + boff);
            mmah(frag[0], aq[ks], b4);
            mmah(frag[1], aq[ks], b4 + 2);
        }
        int r0 = lane >> 2, c0 = (lane & 3) * 2;
#pragma unroll
        for (int nt = 0; nt < 2; nt++)
#pragma unroll
            for (int e = 0; e < 4; e++) {
                int row = r0 + (e >> 1) * 8;
                int col = k0 + wid * 16 + nt * 8 + c0 + (e & 1);
                Sf[row * 1032 + col] += frag[nt][e];
            }
        __syncthreads();
    }

    // ---- softmax ----
#pragma unroll
    for (int rr = 0; rr < 2; rr++) {
        int row = wid * 2 + rr;
        int bsel = (bh0 + row) / Hh - bmin;
        float x[32];
        float mx = -3.4e38f;
#pragma unroll
        for (int i = 0; i < 32; i++) {
            int k = lane + i * 32;
            float m = Mf[bsel * 1024 + k];
            float val = fmaf(Sf[row * 1032 + k], 0.125f, AM[k]);
            x[i] = (m != 0.f) ? val : NEGV;
            mx = fmaxf(mx, x[i]);
        }
#pragma unroll
        for (int o = 16; o > 0; o >>= 1) mx = fmaxf(mx, __shfl_xor_sync(~0u, mx, o));
        float sum = 0.f;
#pragma unroll
        for (int i = 0; i < 32; i++) { x[i] = __expf(x[i] - mx); sum += x[i]; }
#pragma unroll
        for (int o = 16; o > 0; o >>= 1) sum += __shfl_xor_sync(~0u, sum, o);
        float inv = 1.f / sum;
#pragma unroll
        for (int i = 0; i < 32; i++) Sf[row * 1032 + lane + i * 32] = x[i] * inv;
    }
    __syncthreads();

    // prefetch phase-C pb chunk 0, overlapped with the A16 global write
    pb_issue(sbase, PB0, j, 0, tid);

    // ---- write A fp16 ----
    {
        const int row = tid >> 4, kb = (tid & 15) * 64;
        const size_t obase = (((size_t)(bh0 + row)) << 20) + ((size_t)j << 10);
#pragma unroll
        for (int g = 0; g < 8; g++) {
            int k = kb + g * 8;
            uint2 p0 = cvt4(*(float4*)&Sf[row * 1032 + k]);
            uint2 p1 = cvt4(*(float4*)&Sf[row * 1032 + k + 4]);
            *(uint4*)(g_A16 + obase + k) = make_uint4(p0.x, p0.y, p1.x, p1.y);
        }
    }

    // ---- phase C: attn[bh0..+15][d] = A·pb (double-buffered pb) ----
    float facc[4] = {0.f, 0.f, 0.f, 0.f};
    const int w16 = wid * 16;
    for (int c = 0; c < 8; c++) {
        const uint32_t cur = (c & 1) ? PB1 : PB0;
        const int k0 = c * 128;
        if (c + 1 < 8) pb_issue(sbase, (c & 1) ? PB0 : PB1, j, (c + 1) * 128, tid);
        {
            int row = tid >> 4, col = (tid & 15) * 8;
            uint2 p0 = cvt4(*(float4*)&Sf[row * 1032 + k0 + col]);
            uint2 p1 = cvt4(*(float4*)&Sf[row * 1032 + k0 + col + 4]);
            uint32_t dst = SWZ256(row * 256 + col * 2);
            *(uint4*)(smem + AHc + dst) = make_uint4(p0.x, p0.y, p1.x, p1.y);
        }
        if (c + 1 < 8) cpa_wait1(); else cpa_wait0();
        __syncthreads();
#pragma unroll
        for (int ks = 0; ks < 8; ks++) {
            uint32_t a4[4];
            uint32_t aoff = SWZ256((lane & 15) * 256 + (ks * 2 + (lane >> 4)) * 16);
            ldmx4(a4, sbase + AHc + aoff);
            uint32_t bt[2];
            uint32_t boff = SWZ((ks * 16 + (lane & 15)) * 128 + w16);
            ldmx2t(bt, sbase + cur + boff);
            mmah(facc, a4, bt);
        }
        __syncthreads();
    }
    {
        int d = wid * 8 + (lane & 3) * 2;
#pragma unroll
        for (int half = 0; half < 2; half++) {
            int bh = bh0 + (lane >> 2) + half * 8;
            int b = bh / Hh, h = bh % Hh;
            size_t o = ((size_t)(b * 1024 + j)) * 768 + h * 64 + d;
            g_attn[o]     = facc[half * 2 + 0];
            g_attn[o + 1] = facc[half * 2 + 1];
        }
    }
}

// ---------------------------------------------------------------------------
// av: attn += A·vw. Grid (8, 48). M=128, N=64, K=1024. Double-buffered.
// ---------------------------------------------------------------------------
__device__ __forceinline__ void av_issue(uint32_t sbase, uint32_t bufoff,
                                         int bh, int j0, int k0, int tid) {
#pragma unroll
    for (int it = 0; it < 12; it++) {
        int idx = tid + it * 256;
        if (idx < 2048) {
            int row = idx >> 4, q = idx & 15;
            cpa16(sbase + bufoff + SWZ256(row * 256 + q * 16),
                  g_A16 + (((size_t)bh) << 20) +
                  ((size_t)(j0 + row) << 10) + k0 + q * 8);
        } else {
            int rc = idx - 2048;
            int d = rc >> 4, q = rc & 15;
            cpa16(sbase + bufoff + 32768u + SWZ256(d * 256 + q * 16),
                  g_vwt16 + ((size_t)bh * 64 + d) * 1024 + k0 + q * 8);
        }
    }
    cpa_commit();
}

__global__ __launch_bounds__(256) void av_mma_kernel() {
    extern __shared__ __align__(128) char smem[];
    const uint32_t sbase = smem_to_u32(smem);
    const int tid = threadIdx.x, wid = tid >> 5, lane = tid & 31;
    const int bh = blockIdx.y, j0 = blockIdx.x * 128;

    float facc[8][4];
#pragma unroll
    for (int a = 0; a < 8; a++)
#pragma unroll
        for (int b = 0; b < 4; b++) facc[a][b] = 0.f;

    av_issue(sbase, 0, bh, j0, 0, tid);
    for (int c = 0; c < 8; c++) {
        const uint32_t cur = (c & 1) * 49152u;
        if (c + 1 < 8) {
            av_issue(sbase, ((c & 1) ^ 1) * 49152u, bh, j0, (c + 1) * 128, tid);
            cpa_wait1();
        } else {
            cpa_wait0();
        }
        __syncthreads();
        const uint32_t Ac = cur, Vc = cur + 32768u;
#pragma unroll
        for (int ks = 0; ks < 8; ks++) {
            uint32_t a4[4];
            uint32_t aoff = SWZ256((wid * 16 + (lane & 15)) * 256 +
                                   (ks * 2 + (lane >> 4)) * 16);
            ldmx4(a4, sbase + Ac + aoff);
#pragma unroll
            for (int np = 0; np < 4; np++) {
                uint32_t boff = SWZ256((np * 16 + (lane >> 4) * 8 + (lane & 7)) * 256 +
                                       (ks * 2 + ((lane >> 3) & 1)) * 16);
                uint32_t b4[4];
                ldmx4(b4, sbase + Vc + boff);
                mmah(facc[np * 2 + 0], a4, b4);
                mmah(facc[np * 2 + 1], a4, b4 + 2);
            }
        }
        __syncthreads();
    }
    const int b = bh / Hh, h = bh % Hh;
#pragma unroll
    for (int nt = 0; nt < 8; nt++) {
        int d = nt * 8 + (lane & 3) * 2;
#pragma unroll
        for (int half = 0; half < 2; half++) {
            int s = j0 + wid * 16 + (lane >> 2) + half * 8;
            size_t o = ((size_t)(b * 1024 + s)) * 768 + h * 64 + d;
            g_attn[o]     += facc[nt][half * 2 + 0];
            g_attn[o + 1] += facc[nt][half * 2 + 1];
        }
    }
}

// ---------------------------------------------------------------------------
extern "C" void kernel_launch(void* const* d_in, const int* in_sizes, int n_in,
                              void* d_out, int out_size) {
    const float* q     = (const float*)d_in[0];
    const float* k     = (const float*)d_in[1];
    const float* v     = (const float*)d_in[2];
    const float* amask = (const float*)d_in[3];
    const float* pb    = (const float*)d_in[4];
    const int*   vmask = (const int*)  d_in[5];
    const float* Wq    = (const float*)d_in[6];
    const float* bq    = (const float*)d_in[7];
    const float* Wk    = (const float*)d_in[8];
    const float* bk    = (const float*)d_in[9];
    const float* Wv    = (const float*)d_in[10];
    const float* bv    = (const float*)d_in[11];
    const float* Wo    = (const float*)d_in[12];
    const float* bo    = (const float*)d_in[13];
    float* out = (float*)d_out;

    const int SM_GEMM = 65536, SM_QK = 32768, SM_FUSED = 113152, SM_AV = 98304;
    static bool attr_done = false;
    if (!attr_done) {
        cudaFuncSetAttribute(gemm_mma_kernel, cudaFuncAttributeMaxDynamicSharedMemorySize, SM_GEMM);
        cudaFuncSetAttribute(qk_mma_kernel, cudaFuncAttributeMaxDynamicSharedMemorySize, SM_QK);
        cudaFuncSetAttribute(fused_pbq_sm_kernel, cudaFuncAttributeMaxDynamicSharedMemorySize, SM_FUSED);
        cudaFuncSetAttribute(av_mma_kernel, cudaFuncAttributeMaxDynamicSharedMemorySize, SM_AV);
        attr_done = true;
    }

    const int n4 = 4096 * 768 / 4;
    const int pb4 = 1024 * 1024 * 64 / 4;
    pbconv_kernel<<<pb4 / 256, 256>>>(pb, pb4);
    conv16_kernel<<<dim3(n4 / 256, 3), 256>>>(q, k, v, n4);
    dim3 tthr(32, 32), tgrd(24, 24);
    transpose_conv_kernel<<<tgrd, tthr>>>(Wq, 0);
    transpose_conv_kernel<<<tgrd, tthr>>>(Wk, 1);
    transpose_conv_kernel<<<tgrd, tthr>>>(Wv, 2);
    transpose_conv_kernel<<<tgrd, tthr>>>(Wo, 3);

    gemm_mma_kernel<<<dim3(6, 32, 3), 256, SM_GEMM>>>(bq, bk, bv, nullptr, 0);
    qk_mma_kernel<<<dim3(8, 8, 48), 256, SM_QK>>>();
    fused_pbq_sm_kernel<<<dim3(3, 1024), 256, SM_FUSED>>>(amask, vmask);
    av_mma_kernel<<<dim3(8, 48), 256, SM_AV>>>();
    conv16_kernel<<<dim3(n4 / 256, 1), 256>>>(nullptr, nullptr, nullptr, n4);
    gemm_mma_kernel<<<dim3(6, 32, 1), 256, SM_GEMM>>>(bo, nullptr, nullptr, out, 1);
}